// round 9
// baseline (speedup 1.0000x reference)
#include <cuda_runtime.h>
#include <cuda_bf16.h>
#include <math.h>
#include <stdint.h>

// Problem constants
constexpr int Bsz = 4;
constexpr int L   = 4096;
constexpr int D   = 1024;
constexpr int H   = 16;
constexpr int G   = 8;
constexpr int LG  = L / G;     // 512
constexpr int DH  = D / H;     // 64
constexpr int M_TOK = Bsz * L; // 16384
constexpr int KSPLIT = 3 * D;  // 3072 : [hi | lo | hi] x [hi | hi | lo]

// Scratch (allocation-free: static __device__ globals)
__device__ __nv_bfloat16 g_qh  [(size_t)M_TOK * 3072];   // qkv hi plane
__device__ __nv_bfloat16 g_ql  [(size_t)M_TOK * 3072];   // qkv lo plane
__device__ __nv_bfloat16 g_x2  [(size_t)M_TOK * KSPLIT];
__device__ __nv_bfloat16 g_att2[(size_t)M_TOK * KSPLIT];
__device__ __nv_bfloat16 g_wq2 [(size_t)(3 * D) * KSPLIT];
__device__ __nv_bfloat16 g_wo2 [(size_t)D * KSPLIT];

// ---------------------------------------------------------------------------
// helpers
// ---------------------------------------------------------------------------
__device__ __forceinline__ uint32_t swz(uint32_t off) {
    return off ^ ((off >> 3) & 0x70);
}
__device__ __forceinline__ uint32_t s2u(const void* p) {
    uint32_t a;
    asm("{ .reg .u64 t; cvta.to.shared.u64 t, %1; cvt.u32.u64 %0, t; }"
        : "=r"(a) : "l"(p));
    return a;
}
__device__ __forceinline__ void hilo2(float a, float b, uint32_t& hp, uint32_t& lp) {
    __nv_bfloat16 ha = __float2bfloat16(a);
    __nv_bfloat16 hb = __float2bfloat16(b);
    __nv_bfloat16 la = __float2bfloat16(a - __bfloat162float(ha));
    __nv_bfloat16 lb = __float2bfloat16(b - __bfloat162float(hb));
    hp = (uint32_t)__bfloat16_as_ushort(ha) | ((uint32_t)__bfloat16_as_ushort(hb) << 16);
    lp = (uint32_t)__bfloat16_as_ushort(la) | ((uint32_t)__bfloat16_as_ushort(lb) << 16);
}

#define MMA16816(acc, a, b0, b1)                                             \
    asm volatile(                                                            \
        "mma.sync.aligned.m16n8k16.row.col.f32.bf16.bf16.f32 "               \
        "{%0,%1,%2,%3}, {%4,%5,%6,%7}, {%8,%9}, {%0,%1,%2,%3};"              \
        : "+f"((acc)[0]), "+f"((acc)[1]), "+f"((acc)[2]), "+f"((acc)[3])     \
        : "r"((a)[0]), "r"((a)[1]), "r"((a)[2]), "r"((a)[3]),                \
          "r"(b0), "r"(b1))

#define LDMX4(r, addr)                                                       \
    asm volatile("ldmatrix.sync.aligned.m8n8.x4.shared.b16 {%0,%1,%2,%3}, [%4];" \
        : "=r"((r)[0]), "=r"((r)[1]), "=r"((r)[2]), "=r"((r)[3]) : "r"(addr))

#define LDMX4T(r, addr)                                                      \
    asm volatile("ldmatrix.sync.aligned.m8n8.x4.trans.shared.b16 {%0,%1,%2,%3}, [%4];" \
        : "=r"((r)[0]), "=r"((r)[1]), "=r"((r)[2]), "=r"((r)[3]) : "r"(addr))

#define CPASYNC16(dst, src)                                                  \
    asm volatile("cp.async.cg.shared.global [%0], [%1], 16;"                 \
        :: "r"(dst), "l"(src))

// ---------------------------------------------------------------------------
// Split fp32 [rows,1024] -> bf16 [rows,3072].
// mode 0 (A side): [hi | lo | hi]     mode 1 (B side): [hi | hi | lo]
// ---------------------------------------------------------------------------
__global__ void split_fp32_bf16x2(const float* __restrict__ src,
                                  __nv_bfloat16* __restrict__ dst,
                                  int rows, int mode)
{
    int idx = blockIdx.x * 256 + threadIdx.x;
    if (idx >= rows * 256) return;
    int row = idx >> 8;
    int c4  = (idx & 255) << 2;
    float4 v = *(const float4*)(src + (size_t)row * 1024 + c4);
    uint32_t hp0, lp0, hp1, lp1;
    hilo2(v.x, v.y, hp0, lp0);
    hilo2(v.z, v.w, hp1, lp1);
    __nv_bfloat16* base = dst + (size_t)row * KSPLIT + c4;
    if (mode == 0) {
        *(uint32_t*)(base)          = hp0; *(uint32_t*)(base + 2)        = hp1;
        *(uint32_t*)(base + 1024)   = lp0; *(uint32_t*)(base + 1026)     = lp1;
        *(uint32_t*)(base + 2048)   = hp0; *(uint32_t*)(base + 2050)     = hp1;
    } else {
        *(uint32_t*)(base)          = hp0; *(uint32_t*)(base + 2)        = hp1;
        *(uint32_t*)(base + 1024)   = hp0; *(uint32_t*)(base + 1026)     = hp1;
        *(uint32_t*)(base + 2048)   = lp0; *(uint32_t*)(base + 2050)     = lp1;
    }
}

// ---------------------------------------------------------------------------
// mma.sync bf16 NT GEMM: C = A*B^T. 128x128 CTA tile, 4 warps (64x64 each),
// 128 threads, BK=64, 3-stage cp.async. Output fp32 (+bias) or hi/lo planes.
// ---------------------------------------------------------------------------
constexpr int TILE_BYTES = 128 * 128;
constexpr int STAGE_BYTES = 2 * TILE_BYTES;
constexpr int GEMM_SMEM = 3 * STAGE_BYTES;   // 96KB

__global__ __launch_bounds__(128, 2) void gemm_mma(const __nv_bfloat16* __restrict__ A,
                                                   const __nv_bfloat16* __restrict__ B,
                                                   const float* __restrict__ bias,
                                                   float* __restrict__ C,
                                                   __nv_bfloat16* __restrict__ Ch,
                                                   __nv_bfloat16* __restrict__ Cl,
                                                   int M, int N, int Kt)
{
    extern __shared__ __align__(1024) uint8_t smem[];

    const int tid  = threadIdx.x;
    const int wid  = tid >> 5;
    const int lane = tid & 31;
    const int warp_m = (wid & 1) * 64;
    const int warp_n = (wid >> 1) * 64;
    const size_t bm = (size_t)blockIdx.y * 128;
    const size_t bn = (size_t)blockIdx.x * 128;
    const uint32_t sbase = s2u(smem);

    // loader: thread covers rows (tid>>3) + i*16, seg tid&7, i = 0..7 per tile
    const uint32_t soff0 = swz((uint32_t)(tid >> 3) * 128 + (tid & 7) * 16);
    const __nv_bfloat16* ag0 = A + (bm + (tid >> 3)) * (size_t)Kt + (tid & 7) * 8;
    const __nv_bfloat16* bg0 = B + (bn + (tid >> 3)) * (size_t)Kt + (tid & 7) * 8;
    const size_t rstep = (size_t)16 * Kt;

    const int NC = Kt / 64;

    auto issue_copy = [&](int c, int stage) {
        uint32_t sa = sbase + stage * STAGE_BYTES;
        uint32_t sb = sa + TILE_BYTES;
        const int ko = c * 64;
        #pragma unroll
        for (int i = 0; i < 8; i++) {
            CPASYNC16(sa + soff0 + i * 2048, ag0 + ko + i * rstep);
            CPASYNC16(sb + soff0 + i * 2048, bg0 + ko + i * rstep);
        }
        asm volatile("cp.async.commit_group;");
    };

    const int a_row = warp_m + (lane & 15);
    const int a_sub = lane >> 4;
    const int b_row = warp_n + ((lane >> 4) & 1) * 8 + (lane & 7);
    const int b_sub = (lane >> 3) & 1;

    float acc[4][8][4];
    #pragma unroll
    for (int mt = 0; mt < 4; mt++)
        #pragma unroll
        for (int nt = 0; nt < 8; nt++)
            #pragma unroll
            for (int q = 0; q < 4; q++) acc[mt][nt][q] = 0.f;

    issue_copy(0, 0);
    if (NC > 1) issue_copy(1, 1);

    for (int c = 0; c < NC; c++) {
        if (c + 2 < NC) {
            issue_copy(c + 2, (c + 2) % 3);
            asm volatile("cp.async.wait_group 2;");
        } else if (c + 1 < NC) {
            asm volatile("cp.async.wait_group 1;");
        } else {
            asm volatile("cp.async.wait_group 0;");
        }
        __syncthreads();

        const uint32_t sa = sbase + (c % 3) * STAGE_BYTES;
        const uint32_t sb = sa + TILE_BYTES;

        #pragma unroll
        for (int kk = 0; kk < 4; kk++) {
            uint32_t af[4][4];
            #pragma unroll
            for (int mt = 0; mt < 4; mt++) {
                uint32_t off = (uint32_t)(a_row + mt * 16) * 128 + kk * 32 + a_sub * 16;
                LDMX4(af[mt], sa + swz(off));
            }
            uint32_t bf[8][2];
            #pragma unroll
            for (int j = 0; j < 4; j++) {
                uint32_t off = (uint32_t)(b_row + j * 16) * 128 + kk * 32 + b_sub * 16;
                uint32_t r[4];
                LDMX4(r, sb + swz(off));
                bf[2 * j][0] = r[0]; bf[2 * j][1] = r[1];
                bf[2 * j + 1][0] = r[2]; bf[2 * j + 1][1] = r[3];
            }
            #pragma unroll
            for (int mt = 0; mt < 4; mt++)
                #pragma unroll
                for (int nt = 0; nt < 8; nt++)
                    MMA16816(acc[mt][nt], af[mt], bf[nt][0], bf[nt][1]);
        }
        __syncthreads();
    }

    if (Ch) {
        #pragma unroll
        for (int mt = 0; mt < 4; mt++) {
            const size_t row0 = bm + warp_m + mt * 16 + (lane >> 2);
            #pragma unroll
            for (int nt = 0; nt < 8; nt++) {
                const size_t col = bn + warp_n + nt * 8 + (lane & 3) * 2;
                uint32_t hp, lp;
                hilo2(acc[mt][nt][0], acc[mt][nt][1], hp, lp);
                *(uint32_t*)(Ch + row0 * (size_t)N + col) = hp;
                *(uint32_t*)(Cl + row0 * (size_t)N + col) = lp;
                hilo2(acc[mt][nt][2], acc[mt][nt][3], hp, lp);
                *(uint32_t*)(Ch + (row0 + 8) * (size_t)N + col) = hp;
                *(uint32_t*)(Cl + (row0 + 8) * (size_t)N + col) = lp;
            }
        }
    } else {
        #pragma unroll
        for (int mt = 0; mt < 4; mt++) {
            const size_t row0 = bm + warp_m + mt * 16 + (lane >> 2);
            #pragma unroll
            for (int nt = 0; nt < 8; nt++) {
                const size_t col = bn + warp_n + nt * 8 + (lane & 3) * 2;
                float bx = 0.f, by = 0.f;
                if (bias) { bx = bias[col]; by = bias[col + 1]; }
                float2 v0 = {acc[mt][nt][0] + bx, acc[mt][nt][1] + by};
                float2 v1 = {acc[mt][nt][2] + bx, acc[mt][nt][3] + by};
                *(float2*)(C + row0 * (size_t)N + col)       = v0;
                *(float2*)(C + (row0 + 8) * (size_t)N + col) = v1;
            }
        }
    }
}

// ---------------------------------------------------------------------------
// Tensor-core blocked attention: qkv in bf16 hi/lo planes, cp.async fills,
// double-buffered K/V chunks, 3-pass hi/lo accumulation.
// Phase C: warp-split-K (wk = kk half, wn = n16 strip) + smem reduction.
// ---------------------------------------------------------------------------
constexpr int sQH_OFF  = 0;        // [32][72] bf16  (stride 144B)
constexpr int sQL_OFF  = 4608;
constexpr int sKH0_OFF = 9216;     // [128][72] buf0 hi
constexpr int sKL0_OFF = 27648;    // buf0 lo
constexpr int sKH1_OFF = 46080;    // buf1 hi
constexpr int sKL1_OFF = 64512;    // buf1 lo
constexpr int sPH_OFF  = 82944;    // [32][136] bf16 (stride 272B); reused as redO
constexpr int sPL_OFF  = 91648;
constexpr int sRED_OFF = 100352;   // 2 x [32][8] float
constexpr int ATTN_SMEM = 102400;  // 100KB -> 2 CTA/SM

__global__ __launch_bounds__(256) void attn_tc(const __nv_bfloat16* __restrict__ qh,
                                               const __nv_bfloat16* __restrict__ ql,
                                               __nv_bfloat16* __restrict__ att2)
{
    extern __shared__ __align__(16) char smc[];
    const uint32_t sbs = s2u(smc);
    float* redM = (float*)(smc + sRED_OFF);
    float* redS = redM + 256;

    const int tid  = threadIdx.x;
    const int lane = tid & 31;
    const int wid  = tid >> 5;
    const int q4   = lane >> 2;
    const int kap  = lane & 3;

    const int idx = blockIdx.x;
    const int qt  = idx & 15;
    const int bhg = idx >> 4;
    const int g = bhg & 7;
    const int h = (bhg >> 3) & 15;
    const int b = bhg >> 7;
    const int pos0  = g * LG;
    const int qpos0 = pos0 + qt * 32;

    const uint32_t kbuf[2][2] = {{sbs + sKH0_OFF, sbs + sKL0_OFF},
                                 {sbs + sKH1_OFF, sbs + sKL1_OFF}};

    // ---- Q fill ----
    {
        int row = tid >> 3;
        int seg = tid & 7;
        const size_t go = (size_t)(b * L + qpos0 + row) * 3072 + h * 64 + seg * 8;
        uint32_t so = row * 144 + seg * 16;
        CPASYNC16(sbs + sQH_OFF + so, qh + go);
        CPASYNC16(sbs + sQL_OFF + so, ql + go);
    }

    auto load_kv = [&](int c, int buf, int colbase) {
        const size_t tok0 = (size_t)(b * L + pos0 + c * 128);
        #pragma unroll
        for (int i = 0; i < 4; i++) {
            int f = tid + i * 256;
            int row = f >> 3;
            int seg = f & 7;
            const size_t go = (tok0 + row) * 3072 + colbase + seg * 8;
            uint32_t so = row * 144 + seg * 16;
            CPASYNC16(kbuf[buf][0] + so, qh + go);
            CPASYNC16(kbuf[buf][1] + so, ql + go);
        }
        asm volatile("cp.async.commit_group;");
    };

    const int kcol = 1024 + h * 64;
    const int vcol = 2048 + h * 64;

    // ---- Phase A: S over 4 key chunks, 3 passes each ----
    float sAcc[4][2][2][4];
    #pragma unroll
    for (int c = 0; c < 4; c++)
        #pragma unroll
        for (int mt = 0; mt < 2; mt++)
            #pragma unroll
            for (int j = 0; j < 2; j++)
                #pragma unroll
                for (int r = 0; r < 4; r++) sAcc[c][mt][j][r] = 0.f;

    const int nb = wid * 16;
    const int aRowB = (lane & 15);
    const int aHalf = (lane >> 4) * 8;
    const int bRow  = ((lane >> 4) & 1) * 8 + (lane & 7);
    const int bHalf = ((lane >> 3) & 1) * 8;

    load_kv(0, 0, kcol);

    #pragma unroll
    for (int c = 0; c < 4; c++) {
        __syncthreads();
        if (c + 1 < 4) load_kv(c + 1, (c + 1) & 1, kcol);
        if (c + 1 < 4) { asm volatile("cp.async.wait_group 1;"); }
        else           { asm volatile("cp.async.wait_group 0;"); }
        __syncthreads();

        const uint32_t kh = kbuf[c & 1][0];
        const uint32_t kl = kbuf[c & 1][1];
        const uint32_t qhs = sbs + sQH_OFF;
        const uint32_t qls = sbs + sQL_OFF;

        #pragma unroll
        for (int p = 0; p < 3; p++) {
            const uint32_t qp = (p == 1) ? qls : qhs;
            const uint32_t kp = (p == 2) ? kl  : kh;
            #pragma unroll
            for (int kk = 0; kk < 4; kk++) {
                uint32_t a0[4], a1[4], bq[4];
                LDMX4(a0, qp + (uint32_t)(aRowB)      * 144 + (kk * 16 + aHalf) * 2);
                LDMX4(a1, qp + (uint32_t)(aRowB + 16) * 144 + (kk * 16 + aHalf) * 2);
                LDMX4(bq, kp + (uint32_t)(nb + bRow)  * 144 + (kk * 16 + bHalf) * 2);
                MMA16816(sAcc[c][0][0], a0, bq[0], bq[1]);
                MMA16816(sAcc[c][0][1], a0, bq[2], bq[3]);
                MMA16816(sAcc[c][1][0], a1, bq[0], bq[1]);
                MMA16816(sAcc[c][1][1], a1, bq[2], bq[3]);
            }
        }
    }

    // ---- Phase B: softmax ----
    const float scale = 0.125f;
    float rowinv[2][2];

    #pragma unroll
    for (int mt = 0; mt < 2; mt++)
        #pragma unroll
        for (int hh = 0; hh < 2; hh++) {
            float m = -1e30f;
            #pragma unroll
            for (int c = 0; c < 4; c++)
                #pragma unroll
                for (int j = 0; j < 2; j++)
                    m = fmaxf(m, fmaxf(sAcc[c][mt][j][2 * hh], sAcc[c][mt][j][2 * hh + 1]));
            m = fmaxf(m, __shfl_xor_sync(0xffffffffu, m, 1));
            m = fmaxf(m, __shfl_xor_sync(0xffffffffu, m, 2));
            if (kap == 0) redM[(mt * 16 + hh * 8 + q4) * 8 + wid] = m;
        }
    __syncthreads();
    #pragma unroll
    for (int mt = 0; mt < 2; mt++)
        #pragma unroll
        for (int hh = 0; hh < 2; hh++) {
            const int row = mt * 16 + hh * 8 + q4;
            float m = redM[row * 8];
            #pragma unroll
            for (int w = 1; w < 8; w++) m = fmaxf(m, redM[row * 8 + w]);
            float s = 0.f;
            #pragma unroll
            for (int c = 0; c < 4; c++)
                #pragma unroll
                for (int j = 0; j < 2; j++) {
                    float p0 = __expf((sAcc[c][mt][j][2 * hh]     - m) * scale);
                    float p1 = __expf((sAcc[c][mt][j][2 * hh + 1] - m) * scale);
                    sAcc[c][mt][j][2 * hh]     = p0;
                    sAcc[c][mt][j][2 * hh + 1] = p1;
                    s += p0 + p1;
                }
            s += __shfl_xor_sync(0xffffffffu, s, 1);
            s += __shfl_xor_sync(0xffffffffu, s, 2);
            if (kap == 0) redS[row * 8 + wid] = s;
        }
    __syncthreads();
    #pragma unroll
    for (int mt = 0; mt < 2; mt++)
        #pragma unroll
        for (int hh = 0; hh < 2; hh++) {
            const int row = mt * 16 + hh * 8 + q4;
            float s = redS[row * 8];
            #pragma unroll
            for (int w = 1; w < 8; w++) s += redS[row * 8 + w];
            rowinv[mt][hh] = 1.0f / s;
        }

    // ---- Phase C: O = P*V. Warp-split-K: wk = kk half, wn = n16 strip. ----
    const int wn = wid & 3;
    const int wk = wid >> 2;
    float oAcc[2][2][4];   // [mt][n8][4]
    #pragma unroll
    for (int mt = 0; mt < 2; mt++)
        #pragma unroll
        for (int j = 0; j < 2; j++)
            #pragma unroll
            for (int r = 0; r < 4; r++) oAcc[mt][j][r] = 0.f;

    const int pRowB = (lane & 15);
    const int pHalf = (lane >> 4) * 8;
    const int vRow  = (lane & 7) + ((lane >> 3) & 1) * 8;
    const int vCol  = wn * 16 + (lane >> 4) * 8;

    load_kv(0, 0, vcol);

    #pragma unroll
    for (int c = 0; c < 4; c++) {
        __syncthreads();
        if (c + 1 < 4) load_kv(c + 1, (c + 1) & 1, vcol);

        // write P chunk (hi/lo planes, unnormalized) — all warps own 16-key strips
        #pragma unroll
        for (int mt = 0; mt < 2; mt++)
            #pragma unroll
            for (int j = 0; j < 2; j++)
                #pragma unroll
                for (int hh = 0; hh < 2; hh++) {
                    uint32_t hp, lp;
                    hilo2(sAcc[c][mt][j][2 * hh], sAcc[c][mt][j][2 * hh + 1], hp, lp);
                    const int row = mt * 16 + hh * 8 + q4;
                    const int k = wid * 16 + j * 8 + 2 * kap;
                    *(uint32_t*)(smc + sPH_OFF + row * 272 + k * 2) = hp;
                    *(uint32_t*)(smc + sPL_OFF + row * 272 + k * 2) = lp;
                }

        if (c + 1 < 4) { asm volatile("cp.async.wait_group 1;"); }
        else           { asm volatile("cp.async.wait_group 0;"); }
        __syncthreads();

        const uint32_t vh = kbuf[c & 1][0];
        const uint32_t vl = kbuf[c & 1][1];
        const uint32_t phs = sbs + sPH_OFF;
        const uint32_t pls = sbs + sPL_OFF;

        #pragma unroll
        for (int p = 0; p < 3; p++) {
            const uint32_t pp = (p == 1) ? pls : phs;
            const uint32_t vp = (p == 2) ? vl  : vh;
            #pragma unroll
            for (int kk2 = 0; kk2 < 4; kk2++) {
                const int kk = wk * 4 + kk2;
                uint32_t ap0[4], ap1[4], bv[4];
                LDMX4(ap0, pp + (uint32_t)(pRowB)      * 272 + (kk * 16 + pHalf) * 2);
                LDMX4(ap1, pp + (uint32_t)(pRowB + 16) * 272 + (kk * 16 + pHalf) * 2);
                LDMX4T(bv, vp + (uint32_t)(kk * 16 + vRow) * 144 + vCol * 2);
                MMA16816(oAcc[0][0], ap0, bv[0], bv[1]);
                MMA16816(oAcc[0][1], ap0, bv[2], bv[3]);
                MMA16816(oAcc[1][0], ap1, bv[0], bv[1]);
                MMA16816(oAcc[1][1], ap1, bv[2], bv[3]);
            }
        }
    }

    // ---- cross-warp K reduction (reuse P area), then normalize + store ----
    __syncthreads();
    float* redO = (float*)(smc + sPH_OFF);   // [32][64] fp32 = 8KB
    if (wk == 1) {
        #pragma unroll
        for (int mt = 0; mt < 2; mt++)
            #pragma unroll
            for (int j = 0; j < 2; j++) {
                const int row = mt * 16 + q4;
                const int col = wn * 16 + j * 8 + 2 * kap;
                redO[row * 64 + col]           = oAcc[mt][j][0];
                redO[row * 64 + col + 1]       = oAcc[mt][j][1];
                redO[(row + 8) * 64 + col]     = oAcc[mt][j][2];
                redO[(row + 8) * 64 + col + 1] = oAcc[mt][j][3];
            }
    }
    __syncthreads();
    if (wk == 0) {
        #pragma unroll
        for (int mt = 0; mt < 2; mt++) {
            const float inv0 = rowinv[mt][0];
            const float inv1 = rowinv[mt][1];
            const int r0 = mt * 16 + q4;
            const size_t tr0 = (size_t)(b * L + qpos0 + r0) * 3072 + h * 64;
            const size_t tr1 = tr0 + (size_t)8 * 3072;
            #pragma unroll
            for (int j = 0; j < 2; j++) {
                const int cc = wn * 16 + j * 8 + 2 * kap;
                float o0 = (oAcc[mt][j][0] + redO[r0 * 64 + cc])           * inv0;
                float o1 = (oAcc[mt][j][1] + redO[r0 * 64 + cc + 1])       * inv0;
                float o2 = (oAcc[mt][j][2] + redO[(r0 + 8) * 64 + cc])     * inv1;
                float o3 = (oAcc[mt][j][3] + redO[(r0 + 8) * 64 + cc + 1]) * inv1;
                uint32_t hp, lp;
                hilo2(o0, o1, hp, lp);
                *(uint32_t*)(att2 + tr0 + cc)        = hp;
                *(uint32_t*)(att2 + tr0 + 1024 + cc) = lp;
                *(uint32_t*)(att2 + tr0 + 2048 + cc) = hp;
                hilo2(o2, o3, hp, lp);
                *(uint32_t*)(att2 + tr1 + cc)        = hp;
                *(uint32_t*)(att2 + tr1 + 1024 + cc) = lp;
                *(uint32_t*)(att2 + tr1 + 2048 + cc) = hp;
            }
        }
    }
}

// ---------------------------------------------------------------------------
extern "C" void kernel_launch(void* const* d_in, const int* in_sizes, int n_in,
                              void* d_out, int out_size)
{
    const float* x     = (const float*)d_in[0];
    const float* w_qkv = (const float*)d_in[1];
    const float* w_out = (const float*)d_in[2];
    const float* b_out = (const float*)d_in[3];
    float* out = (float*)d_out;

    __nv_bfloat16 *qhp, *qlp, *x2, *att2, *wq2, *wo2;
    cudaGetSymbolAddress((void**)&qhp,  g_qh);
    cudaGetSymbolAddress((void**)&qlp,  g_ql);
    cudaGetSymbolAddress((void**)&x2,   g_x2);
    cudaGetSymbolAddress((void**)&att2, g_att2);
    cudaGetSymbolAddress((void**)&wq2,  g_wq2);
    cudaGetSymbolAddress((void**)&wo2,  g_wo2);

    cudaFuncSetAttribute(gemm_mma, cudaFuncAttributeMaxDynamicSharedMemorySize,
                         GEMM_SMEM);
    cudaFuncSetAttribute(attn_tc, cudaFuncAttributeMaxDynamicSharedMemorySize,
                         ATTN_SMEM);

    split_fp32_bf16x2<<<M_TOK, 256>>>(x, x2, M_TOK, 0);
    split_fp32_bf16x2<<<3 * D, 256>>>(w_qkv, wq2, 3 * D, 1);
    split_fp32_bf16x2<<<D, 256>>>(w_out, wo2, D, 1);

    // 1) QKV projection -> bf16 hi/lo planes directly
    gemm_mma<<<dim3(3 * D / 128, M_TOK / 128), 128, GEMM_SMEM>>>(
        x2, wq2, nullptr, nullptr, qhp, qlp, M_TOK, 3 * D, KSPLIT);

    // 2) Tensor-core blocked attention -> att2 [hi|lo|hi]
    attn_tc<<<Bsz * H * G * 16, 256, ATTN_SMEM>>>(qhp, qlp, att2);

    // 3) Output projection + bias -> fp32 out
    gemm_mma<<<dim3(D / 128, M_TOK / 128), 128, GEMM_SMEM>>>(
        att2, wo2, b_out, out, nullptr, nullptr, M_TOK, D, KSPLIT);
}

// round 10
// speedup vs baseline: 1.2177x; 1.2177x over previous
#include <cuda_runtime.h>
#include <cuda_bf16.h>
#include <math.h>
#include <stdint.h>

// Problem constants
constexpr int Bsz = 4;
constexpr int L   = 4096;
constexpr int D   = 1024;
constexpr int H   = 16;
constexpr int G   = 8;
constexpr int LG  = L / G;     // 512
constexpr int M_TOK = Bsz * L; // 16384
constexpr int KSPLIT = 3 * D;  // 3072 : [hi | lo | hi] x [hi | hi | lo]

// Scratch (allocation-free: static __device__ globals)
__device__ __nv_bfloat16 g_qh  [(size_t)M_TOK * 3072];   // qkv hi plane
__device__ __nv_bfloat16 g_ql  [(size_t)M_TOK * 3072];   // qkv lo plane
__device__ __nv_bfloat16 g_x2  [(size_t)M_TOK * KSPLIT];
__device__ __nv_bfloat16 g_att2[(size_t)M_TOK * KSPLIT];
__device__ __nv_bfloat16 g_wq2 [(size_t)(3 * D) * KSPLIT];
__device__ __nv_bfloat16 g_wo2 [(size_t)D * KSPLIT];

// ---------------------------------------------------------------------------
// helpers
// ---------------------------------------------------------------------------
__device__ __forceinline__ uint32_t swz(uint32_t off) {
    return off ^ ((off >> 3) & 0x70);
}
__device__ __forceinline__ uint32_t s2u(const void* p) {
    uint32_t a;
    asm("{ .reg .u64 t; cvta.to.shared.u64 t, %1; cvt.u32.u64 %0, t; }"
        : "=r"(a) : "l"(p));
    return a;
}
__device__ __forceinline__ void hilo2(float a, float b, uint32_t& hp, uint32_t& lp) {
    __nv_bfloat16 ha = __float2bfloat16(a);
    __nv_bfloat16 hb = __float2bfloat16(b);
    __nv_bfloat16 la = __float2bfloat16(a - __bfloat162float(ha));
    __nv_bfloat16 lb = __float2bfloat16(b - __bfloat162float(hb));
    hp = (uint32_t)__bfloat16_as_ushort(ha) | ((uint32_t)__bfloat16_as_ushort(hb) << 16);
    lp = (uint32_t)__bfloat16_as_ushort(la) | ((uint32_t)__bfloat16_as_ushort(lb) << 16);
}

#define MMA16816(acc, a, b0, b1)                                             \
    asm volatile(                                                            \
        "mma.sync.aligned.m16n8k16.row.col.f32.bf16.bf16.f32 "               \
        "{%0,%1,%2,%3}, {%4,%5,%6,%7}, {%8,%9}, {%0,%1,%2,%3};"              \
        : "+f"((acc)[0]), "+f"((acc)[1]), "+f"((acc)[2]), "+f"((acc)[3])     \
        : "r"((a)[0]), "r"((a)[1]), "r"((a)[2]), "r"((a)[3]),                \
          "r"(b0), "r"(b1))

#define LDMX4(r, addr)                                                       \
    asm volatile("ldmatrix.sync.aligned.m8n8.x4.shared.b16 {%0,%1,%2,%3}, [%4];" \
        : "=r"((r)[0]), "=r"((r)[1]), "=r"((r)[2]), "=r"((r)[3]) : "r"(addr))

#define LDMX4T(r, addr)                                                      \
    asm volatile("ldmatrix.sync.aligned.m8n8.x4.trans.shared.b16 {%0,%1,%2,%3}, [%4];" \
        : "=r"((r)[0]), "=r"((r)[1]), "=r"((r)[2]), "=r"((r)[3]) : "r"(addr))

#define CPASYNC16(dst, src)                                                  \
    asm volatile("cp.async.cg.shared.global [%0], [%1], 16;"                 \
        :: "r"(dst), "l"(src))

// ---------------------------------------------------------------------------
// Split fp32 [rows,1024] -> bf16 [rows,3072].
// mode 0 (A side): [hi | lo | hi]     mode 1 (B side): [hi | hi | lo]
// ---------------------------------------------------------------------------
__global__ void split_fp32_bf16x2(const float* __restrict__ src,
                                  __nv_bfloat16* __restrict__ dst,
                                  int rows, int mode)
{
    int idx = blockIdx.x * 256 + threadIdx.x;
    if (idx >= rows * 256) return;
    int row = idx >> 8;
    int c4  = (idx & 255) << 2;
    float4 v = *(const float4*)(src + (size_t)row * 1024 + c4);
    uint32_t hp0, lp0, hp1, lp1;
    hilo2(v.x, v.y, hp0, lp0);
    hilo2(v.z, v.w, hp1, lp1);
    __nv_bfloat16* base = dst + (size_t)row * KSPLIT + c4;
    if (mode == 0) {
        *(uint32_t*)(base)          = hp0; *(uint32_t*)(base + 2)        = hp1;
        *(uint32_t*)(base + 1024)   = lp0; *(uint32_t*)(base + 1026)     = lp1;
        *(uint32_t*)(base + 2048)   = hp0; *(uint32_t*)(base + 2050)     = hp1;
    } else {
        *(uint32_t*)(base)          = hp0; *(uint32_t*)(base + 2)        = hp1;
        *(uint32_t*)(base + 1024)   = hp0; *(uint32_t*)(base + 1026)     = hp1;
        *(uint32_t*)(base + 2048)   = lp0; *(uint32_t*)(base + 2050)     = lp1;
    }
}

// ---------------------------------------------------------------------------
// mma.sync bf16 NT GEMM: C = A*B^T. 128x128 CTA tile, 4 warps (64x64 each),
// 128 threads, BK=64, 3-stage cp.async, SINGLE sync per chunk.
// ---------------------------------------------------------------------------
constexpr int TILE_BYTES = 128 * 128;
constexpr int STAGE_BYTES = 2 * TILE_BYTES;
constexpr int GEMM_SMEM = 3 * STAGE_BYTES;   // 96KB

__global__ __launch_bounds__(128, 2) void gemm_mma(const __nv_bfloat16* __restrict__ A,
                                                   const __nv_bfloat16* __restrict__ B,
                                                   const float* __restrict__ bias,
                                                   float* __restrict__ C,
                                                   __nv_bfloat16* __restrict__ Ch,
                                                   __nv_bfloat16* __restrict__ Cl,
                                                   int M, int N, int Kt)
{
    extern __shared__ __align__(1024) uint8_t smem[];

    const int tid  = threadIdx.x;
    const int wid  = tid >> 5;
    const int lane = tid & 31;
    const int warp_m = (wid & 1) * 64;
    const int warp_n = (wid >> 1) * 64;
    const size_t bm = (size_t)blockIdx.y * 128;
    const size_t bn = (size_t)blockIdx.x * 128;
    const uint32_t sbase = s2u(smem);

    const uint32_t soff0 = swz((uint32_t)(tid >> 3) * 128 + (tid & 7) * 16);
    const __nv_bfloat16* ag0 = A + (bm + (tid >> 3)) * (size_t)Kt + (tid & 7) * 8;
    const __nv_bfloat16* bg0 = B + (bn + (tid >> 3)) * (size_t)Kt + (tid & 7) * 8;
    const size_t rstep = (size_t)16 * Kt;

    const int NC = Kt / 64;

    auto issue_copy = [&](int c, int stage) {
        uint32_t sa = sbase + stage * STAGE_BYTES;
        uint32_t sb = sa + TILE_BYTES;
        const int ko = c * 64;
        #pragma unroll
        for (int i = 0; i < 8; i++) {
            CPASYNC16(sa + soff0 + i * 2048, ag0 + ko + i * rstep);
            CPASYNC16(sb + soff0 + i * 2048, bg0 + ko + i * rstep);
        }
        asm volatile("cp.async.commit_group;");
    };

    const int a_row = warp_m + (lane & 15);
    const int a_sub = lane >> 4;
    const int b_row = warp_n + ((lane >> 4) & 1) * 8 + (lane & 7);
    const int b_sub = (lane >> 3) & 1;

    float acc[4][8][4];
    #pragma unroll
    for (int mt = 0; mt < 4; mt++)
        #pragma unroll
        for (int nt = 0; nt < 8; nt++)
            #pragma unroll
            for (int q = 0; q < 4; q++) acc[mt][nt][q] = 0.f;

    issue_copy(0, 0);
    if (NC > 1) issue_copy(1, 1);

    for (int c = 0; c < NC; c++) {
        if (c + 1 < NC) { asm volatile("cp.async.wait_group 1;"); }
        else            { asm volatile("cp.async.wait_group 0;"); }
        __syncthreads();
        if (c + 2 < NC) issue_copy(c + 2, (c + 2) % 3);

        const uint32_t sa = sbase + (c % 3) * STAGE_BYTES;
        const uint32_t sb = sa + TILE_BYTES;

        #pragma unroll
        for (int kk = 0; kk < 4; kk++) {
            uint32_t af[4][4];
            #pragma unroll
            for (int mt = 0; mt < 4; mt++) {
                uint32_t off = (uint32_t)(a_row + mt * 16) * 128 + kk * 32 + a_sub * 16;
                LDMX4(af[mt], sa + swz(off));
            }
            uint32_t bf[8][2];
            #pragma unroll
            for (int j = 0; j < 4; j++) {
                uint32_t off = (uint32_t)(b_row + j * 16) * 128 + kk * 32 + b_sub * 16;
                uint32_t r[4];
                LDMX4(r, sb + swz(off));
                bf[2 * j][0] = r[0]; bf[2 * j][1] = r[1];
                bf[2 * j + 1][0] = r[2]; bf[2 * j + 1][1] = r[3];
            }
            #pragma unroll
            for (int mt = 0; mt < 4; mt++)
                #pragma unroll
                for (int nt = 0; nt < 8; nt++)
                    MMA16816(acc[mt][nt], af[mt], bf[nt][0], bf[nt][1]);
        }
    }

    if (Ch) {
        #pragma unroll
        for (int mt = 0; mt < 4; mt++) {
            const size_t row0 = bm + warp_m + mt * 16 + (lane >> 2);
            #pragma unroll
            for (int nt = 0; nt < 8; nt++) {
                const size_t col = bn + warp_n + nt * 8 + (lane & 3) * 2;
                uint32_t hp, lp;
                hilo2(acc[mt][nt][0], acc[mt][nt][1], hp, lp);
                *(uint32_t*)(Ch + row0 * (size_t)N + col) = hp;
                *(uint32_t*)(Cl + row0 * (size_t)N + col) = lp;
                hilo2(acc[mt][nt][2], acc[mt][nt][3], hp, lp);
                *(uint32_t*)(Ch + (row0 + 8) * (size_t)N + col) = hp;
                *(uint32_t*)(Cl + (row0 + 8) * (size_t)N + col) = lp;
            }
        }
    } else {
        #pragma unroll
        for (int mt = 0; mt < 4; mt++) {
            const size_t row0 = bm + warp_m + mt * 16 + (lane >> 2);
            #pragma unroll
            for (int nt = 0; nt < 8; nt++) {
                const size_t col = bn + warp_n + nt * 8 + (lane & 3) * 2;
                float bx = 0.f, by = 0.f;
                if (bias) { bx = bias[col]; by = bias[col + 1]; }
                float2 v0 = {acc[mt][nt][0] + bx, acc[mt][nt][1] + by};
                float2 v1 = {acc[mt][nt][2] + bx, acc[mt][nt][3] + by};
                *(float2*)(C + row0 * (size_t)N + col)       = v0;
                *(float2*)(C + (row0 + 8) * (size_t)N + col) = v1;
            }
        }
    }
}

// ---------------------------------------------------------------------------
// Flash-style attention: CTA = 64 queries x 512-key block, 4 warps (m16 each),
// per-warp ONLINE softmax (no cross-warp barriers), 8 chunks of 64 keys,
// double-buffered K+V cp.async, single __syncthreads per chunk.
// P stays in registers: QK^T C-fragment layout == PV A-fragment layout.
// 3-pass hi/lo: S = Qh*Kh + Ql*Kh + Qh*Kl ; O = Ph*Vh + Pl*Vh + Ph*Vl.
// ---------------------------------------------------------------------------
constexpr int sAQH = 0;         // Q hi: 64 x 128B (swizzled)
constexpr int sAQL = 8192;      // Q lo
constexpr int sBUF0 = 16384;    // per buffer: KH, KL, VH, VL each 8192
constexpr int sBUFSZ = 32768;
constexpr int ATTN_SMEM = 16384 + 2 * sBUFSZ;   // 81920 -> 2 CTA/SM

__global__ __launch_bounds__(128) void attn_flash(const __nv_bfloat16* __restrict__ qh,
                                                  const __nv_bfloat16* __restrict__ ql,
                                                  __nv_bfloat16* __restrict__ att2)
{
    extern __shared__ __align__(1024) char smc[];
    const uint32_t sbs = s2u(smc);

    const int tid  = threadIdx.x;
    const int lane = tid & 31;
    const int w    = tid >> 5;

    const int idx = blockIdx.x;
    const int qt = idx & 7;
    const int g  = (idx >> 3) & 7;
    const int h  = (idx >> 6) & 15;
    const int b  = idx >> 10;
    const int pos0 = g * LG;
    const int q0   = pos0 + qt * 64;

    // loader mapping: rows lrow + i*16, 16B segment lseg
    const int lrow = tid >> 3;
    const int lseg = tid & 7;
    uint32_t soff[4];
    #pragma unroll
    for (int i = 0; i < 4; i++)
        soff[i] = swz((uint32_t)(lrow + i * 16) * 128 + lseg * 16);

    // ---- issue Q (group 0, together with chunk 0) ----
    #pragma unroll
    for (int i = 0; i < 4; i++) {
        const size_t qo = (size_t)(b * L + q0 + lrow + i * 16) * 3072 + h * 64 + lseg * 8;
        CPASYNC16(sbs + sAQH + soff[i], qh + qo);
        CPASYNC16(sbs + sAQL + soff[i], ql + qo);
    }

    auto issue_chunk = [&](int c, int buf) {
        const uint32_t bb = sbs + sBUF0 + buf * sBUFSZ;
        #pragma unroll
        for (int i = 0; i < 4; i++) {
            const size_t ko = (size_t)(b * L + pos0 + c * 64 + lrow + i * 16) * 3072
                              + 1024 + h * 64 + lseg * 8;
            CPASYNC16(bb         + soff[i], qh + ko);          // K hi
            CPASYNC16(bb + 8192  + soff[i], ql + ko);          // K lo
            CPASYNC16(bb + 16384 + soff[i], qh + ko + 1024);   // V hi
            CPASYNC16(bb + 24576 + soff[i], ql + ko + 1024);   // V lo
        }
        asm volatile("cp.async.commit_group;");
    };
    issue_chunk(0, 0);

    // fragment address components
    const uint32_t qoff0 = swz((uint32_t)(w * 16 + (lane & 15)) * 128 + (lane >> 4) * 16);
    const int kRow  = ((lane >> 4) & 1) * 8 + (lane & 7);   // + n16*16
    const int kSub  = ((lane >> 3) & 1) * 16;               // byte
    const int vRow  = (lane & 7) + ((lane >> 3) & 1) * 8;   // + kk*16
    const int vColB = (lane >> 4) * 16;                     // + n16*32 (bytes)

    uint32_t qf[2][4][4];
    float o[8][4];
    #pragma unroll
    for (int t = 0; t < 8; t++)
        #pragma unroll
        for (int j = 0; j < 4; j++) o[t][j] = 0.f;
    float m0 = -1e30f, m1 = -1e30f, l0 = 0.f, l1 = 0.f;
    const float scale = 0.125f;

    for (int c = 0; c < 8; c++) {
        asm volatile("cp.async.wait_group 0;");
        __syncthreads();
        if (c + 1 < 8) issue_chunk(c + 1, (c + 1) & 1);
        if (c == 0) {
            #pragma unroll
            for (int pl = 0; pl < 2; pl++) {
                const uint32_t qb = sbs + (pl ? sAQL : sAQH);
                #pragma unroll
                for (int kk = 0; kk < 4; kk++)
                    LDMX4(qf[pl][kk], qb + ((qoff0 + (uint32_t)kk * 32) ^
                                            (((qoff0 + (uint32_t)kk * 32) >> 3) & 0x70) ^
                                            (qoff0 ^ ((qoff0 >> 3) & 0x70)) ^ qoff0));
            }
            // NOTE: swizzle distributes over +kk*32 only if kk*32 doesn't touch
            // bits[6:4]^... — recompute cleanly instead:
            #pragma unroll
            for (int pl = 0; pl < 2; pl++) {
                const uint32_t qb = sbs + (pl ? sAQL : sAQH);
                #pragma unroll
                for (int kk = 0; kk < 4; kk++) {
                    uint32_t off = (uint32_t)(w * 16 + (lane & 15)) * 128 + kk * 32 + (lane >> 4) * 16;
                    LDMX4(qf[pl][kk], qb + swz(off));
                }
            }
        }

        const uint32_t bb = sbs + sBUF0 + (c & 1) * sBUFSZ;

        // ---- S = Q*K^T (3 passes) ----
        float s[8][4];
        #pragma unroll
        for (int t = 0; t < 8; t++)
            #pragma unroll
            for (int j = 0; j < 4; j++) s[t][j] = 0.f;

        #pragma unroll
        for (int p = 0; p < 3; p++) {
            const int qpl = (p == 1) ? 1 : 0;
            const uint32_t kb = bb + ((p == 2) ? 8192 : 0);
            #pragma unroll
            for (int kk = 0; kk < 4; kk++) {
                #pragma unroll
                for (int n16 = 0; n16 < 4; n16++) {
                    uint32_t bq[4];
                    uint32_t off = (uint32_t)(n16 * 16 + kRow) * 128 + kk * 32 + kSub;
                    LDMX4(bq, kb + swz(off));
                    MMA16816(s[2 * n16],     qf[qpl][kk], bq[0], bq[1]);
                    MMA16816(s[2 * n16 + 1], qf[qpl][kk], bq[2], bq[3]);
                }
            }
        }

        // ---- online softmax update (per-warp, rows r=lane>>2 and r+8) ----
        float cm0 = -1e30f, cm1 = -1e30f;
        #pragma unroll
        for (int t = 0; t < 8; t++) {
            cm0 = fmaxf(cm0, fmaxf(s[t][0], s[t][1]));
            cm1 = fmaxf(cm1, fmaxf(s[t][2], s[t][3]));
        }
        cm0 *= scale; cm1 *= scale;
        cm0 = fmaxf(cm0, __shfl_xor_sync(0xffffffffu, cm0, 1));
        cm0 = fmaxf(cm0, __shfl_xor_sync(0xffffffffu, cm0, 2));
        cm1 = fmaxf(cm1, __shfl_xor_sync(0xffffffffu, cm1, 1));
        cm1 = fmaxf(cm1, __shfl_xor_sync(0xffffffffu, cm1, 2));
        const float mn0 = fmaxf(m0, cm0);
        const float mn1 = fmaxf(m1, cm1);
        const float al0 = __expf(m0 - mn0);
        const float al1 = __expf(m1 - mn1);
        m0 = mn0; m1 = mn1;

        float ls0 = 0.f, ls1 = 0.f;
        #pragma unroll
        for (int t = 0; t < 8; t++) {
            float p0 = __expf(s[t][0] * scale - mn0);
            float p1 = __expf(s[t][1] * scale - mn0);
            float p2 = __expf(s[t][2] * scale - mn1);
            float p3 = __expf(s[t][3] * scale - mn1);
            s[t][0] = p0; s[t][1] = p1; s[t][2] = p2; s[t][3] = p3;
            ls0 += p0 + p1; ls1 += p2 + p3;
        }
        l0 = l0 * al0 + ls0;
        l1 = l1 * al1 + ls1;
        #pragma unroll
        for (int t = 0; t < 8; t++) {
            o[t][0] *= al0; o[t][1] *= al0;
            o[t][2] *= al1; o[t][3] *= al1;
        }

        // ---- P -> bf16 hi/lo A-fragments (in registers) ----
        uint32_t pfh[4][4], pfl[4][4];
        #pragma unroll
        for (int kk = 0; kk < 4; kk++) {
            hilo2(s[2 * kk][0],     s[2 * kk][1],     pfh[kk][0], pfl[kk][0]);
            hilo2(s[2 * kk][2],     s[2 * kk][3],     pfh[kk][1], pfl[kk][1]);
            hilo2(s[2 * kk + 1][0], s[2 * kk + 1][1], pfh[kk][2], pfl[kk][2]);
            hilo2(s[2 * kk + 1][2], s[2 * kk + 1][3], pfh[kk][3], pfl[kk][3]);
        }

        // ---- O += P*V (3 passes) ----
        #pragma unroll
        for (int p = 0; p < 3; p++) {
            const uint32_t vb = bb + ((p == 2) ? 24576 : 16384);
            #pragma unroll
            for (int kk = 0; kk < 4; kk++) {
                const uint32_t* pf = (p == 1) ? pfl[kk] : pfh[kk];
                #pragma unroll
                for (int n16 = 0; n16 < 4; n16++) {
                    uint32_t bv[4];
                    uint32_t off = (uint32_t)(kk * 16 + vRow) * 128 + n16 * 32 + vColB;
                    LDMX4T(bv, vb + swz(off));
                    MMA16816(o[2 * n16],     pf, bv[0], bv[1]);
                    MMA16816(o[2 * n16 + 1], pf, bv[2], bv[3]);
                }
            }
        }
    }

    // ---- finalize: row sums across quad, normalize, store [hi|lo|hi] ----
    l0 += __shfl_xor_sync(0xffffffffu, l0, 1);
    l0 += __shfl_xor_sync(0xffffffffu, l0, 2);
    l1 += __shfl_xor_sync(0xffffffffu, l1, 1);
    l1 += __shfl_xor_sync(0xffffffffu, l1, 2);
    const float inv0 = 1.0f / l0;
    const float inv1 = 1.0f / l1;

    const size_t gr0 = (size_t)(b * L + q0 + w * 16 + (lane >> 2)) * 3072 + h * 64;
    const size_t gr1 = gr0 + (size_t)8 * 3072;
    #pragma unroll
    for (int t = 0; t < 8; t++) {
        const int cc = t * 8 + (lane & 3) * 2;
        uint32_t hp, lp;
        hilo2(o[t][0] * inv0, o[t][1] * inv0, hp, lp);
        *(uint32_t*)(att2 + gr0 + cc)        = hp;
        *(uint32_t*)(att2 + gr0 + 1024 + cc) = lp;
        *(uint32_t*)(att2 + gr0 + 2048 + cc) = hp;
        hilo2(o[t][2] * inv1, o[t][3] * inv1, hp, lp);
        *(uint32_t*)(att2 + gr1 + cc)        = hp;
        *(uint32_t*)(att2 + gr1 + 1024 + cc) = lp;
        *(uint32_t*)(att2 + gr1 + 2048 + cc) = hp;
    }
}

// ---------------------------------------------------------------------------
extern "C" void kernel_launch(void* const* d_in, const int* in_sizes, int n_in,
                              void* d_out, int out_size)
{
    const float* x     = (const float*)d_in[0];
    const float* w_qkv = (const float*)d_in[1];
    const float* w_out = (const float*)d_in[2];
    const float* b_out = (const float*)d_in[3];
    float* out = (float*)d_out;

    __nv_bfloat16 *qhp, *qlp, *x2, *att2, *wq2, *wo2;
    cudaGetSymbolAddress((void**)&qhp,  g_qh);
    cudaGetSymbolAddress((void**)&qlp,  g_ql);
    cudaGetSymbolAddress((void**)&x2,   g_x2);
    cudaGetSymbolAddress((void**)&att2, g_att2);
    cudaGetSymbolAddress((void**)&wq2,  g_wq2);
    cudaGetSymbolAddress((void**)&wo2,  g_wo2);

    cudaFuncSetAttribute(gemm_mma, cudaFuncAttributeMaxDynamicSharedMemorySize,
                         GEMM_SMEM);
    cudaFuncSetAttribute(attn_flash, cudaFuncAttributeMaxDynamicSharedMemorySize,
                         ATTN_SMEM);

    split_fp32_bf16x2<<<M_TOK, 256>>>(x, x2, M_TOK, 0);
    split_fp32_bf16x2<<<3 * D, 256>>>(w_qkv, wq2, 3 * D, 1);
    split_fp32_bf16x2<<<D, 256>>>(w_out, wo2, D, 1);

    // 1) QKV projection -> bf16 hi/lo planes
    gemm_mma<<<dim3(3 * D / 128, M_TOK / 128), 128, GEMM_SMEM>>>(
        x2, wq2, nullptr, nullptr, qhp, qlp, M_TOK, 3 * D, KSPLIT);

    // 2) Flash attention -> att2 [hi|lo|hi]
    attn_flash<<<Bsz * H * G * (LG / 64), 128, ATTN_SMEM>>>(qhp, qlp, att2);

    // 3) Output projection + bias -> fp32 out
    gemm_mma<<<dim3(D / 128, M_TOK / 128), 128, GEMM_SMEM>>>(
        att2, wo2, b_out, out, nullptr, nullptr, M_TOK, D, KSPLIT);
}

// round 11
// speedup vs baseline: 1.3099x; 1.0757x over previous
#include <cuda_runtime.h>
#include <cuda_bf16.h>
#include <math.h>
#include <stdint.h>

// Problem constants
constexpr int Bsz = 4;
constexpr int L   = 4096;
constexpr int D   = 1024;
constexpr int H   = 16;
constexpr int G   = 8;
constexpr int LG  = L / G;     // 512
constexpr int M_TOK = Bsz * L; // 16384

// Scratch planes (allocation-free: static __device__ globals)
__device__ __nv_bfloat16 g_qh [(size_t)M_TOK * 3072];   // qkv hi plane
__device__ __nv_bfloat16 g_ql [(size_t)M_TOK * 3072];   // qkv lo plane
__device__ __nv_bfloat16 g_xh [(size_t)M_TOK * 1024];
__device__ __nv_bfloat16 g_xl [(size_t)M_TOK * 1024];
__device__ __nv_bfloat16 g_ath[(size_t)M_TOK * 1024];
__device__ __nv_bfloat16 g_atl[(size_t)M_TOK * 1024];
__device__ __nv_bfloat16 g_wqh[(size_t)3072 * 1024];
__device__ __nv_bfloat16 g_wql[(size_t)3072 * 1024];
__device__ __nv_bfloat16 g_woh[(size_t)1024 * 1024];
__device__ __nv_bfloat16 g_wol[(size_t)1024 * 1024];

// ---------------------------------------------------------------------------
// helpers
// ---------------------------------------------------------------------------
__device__ __forceinline__ uint32_t swz64(uint32_t off) {   // 64B-row swizzle
    return off ^ ((off >> 3) & 0x30);
}
__device__ __forceinline__ uint32_t swz(uint32_t off) {     // 128B-row swizzle
    return off ^ ((off >> 3) & 0x70);
}
__device__ __forceinline__ uint32_t s2u(const void* p) {
    uint32_t a;
    asm("{ .reg .u64 t; cvta.to.shared.u64 t, %1; cvt.u32.u64 %0, t; }"
        : "=r"(a) : "l"(p));
    return a;
}
__device__ __forceinline__ void hilo2(float a, float b, uint32_t& hp, uint32_t& lp) {
    __nv_bfloat16 ha = __float2bfloat16(a);
    __nv_bfloat16 hb = __float2bfloat16(b);
    __nv_bfloat16 la = __float2bfloat16(a - __bfloat162float(ha));
    __nv_bfloat16 lb = __float2bfloat16(b - __bfloat162float(hb));
    hp = (uint32_t)__bfloat16_as_ushort(ha) | ((uint32_t)__bfloat16_as_ushort(hb) << 16);
    lp = (uint32_t)__bfloat16_as_ushort(la) | ((uint32_t)__bfloat16_as_ushort(lb) << 16);
}

#define MMA16816(acc, a, b0, b1)                                             \
    asm volatile(                                                            \
        "mma.sync.aligned.m16n8k16.row.col.f32.bf16.bf16.f32 "               \
        "{%0,%1,%2,%3}, {%4,%5,%6,%7}, {%8,%9}, {%0,%1,%2,%3};"              \
        : "+f"((acc)[0]), "+f"((acc)[1]), "+f"((acc)[2]), "+f"((acc)[3])     \
        : "r"((a)[0]), "r"((a)[1]), "r"((a)[2]), "r"((a)[3]),                \
          "r"(b0), "r"(b1))

#define LDMX4(r, addr)                                                       \
    asm volatile("ldmatrix.sync.aligned.m8n8.x4.shared.b16 {%0,%1,%2,%3}, [%4];" \
        : "=r"((r)[0]), "=r"((r)[1]), "=r"((r)[2]), "=r"((r)[3]) : "r"(addr))

#define LDMX4T(r, addr)                                                      \
    asm volatile("ldmatrix.sync.aligned.m8n8.x4.trans.shared.b16 {%0,%1,%2,%3}, [%4];" \
        : "=r"((r)[0]), "=r"((r)[1]), "=r"((r)[2]), "=r"((r)[3]) : "r"(addr))

#define CPASYNC16(dst, src)                                                  \
    asm volatile("cp.async.cg.shared.global [%0], [%1], 16;"                 \
        :: "r"(dst), "l"(src))

// ---------------------------------------------------------------------------
// Split fp32 [rows,1024] -> two bf16 planes [rows,1024].
// ---------------------------------------------------------------------------
__global__ void split_fp32_planes(const float* __restrict__ src,
                                  __nv_bfloat16* __restrict__ dsth,
                                  __nv_bfloat16* __restrict__ dstl,
                                  int rows)
{
    int idx = blockIdx.x * 256 + threadIdx.x;
    if (idx >= rows * 256) return;
    int row = idx >> 8;
    int c4  = (idx & 255) << 2;
    float4 v = *(const float4*)(src + (size_t)row * 1024 + c4);
    uint32_t hp0, lp0, hp1, lp1;
    hilo2(v.x, v.y, hp0, lp0);
    hilo2(v.z, v.w, hp1, lp1);
    size_t o = (size_t)row * 1024 + c4;
    *(uint32_t*)(dsth + o)     = hp0; *(uint32_t*)(dsth + o + 2) = hp1;
    *(uint32_t*)(dstl + o)     = lp0; *(uint32_t*)(dstl + o + 2) = lp1;
}

// ---------------------------------------------------------------------------
// Fused hi/lo plane GEMM: C = Ah*Bh^T + Al*Bh^T + Ah*Bl^T (+bias).
// 128x128 CTA tile, 8 warps (32x64 each), BK=32 (4 planes x 8KB per stage),
// 3-stage cp.async, single sync per chunk. K real = 1024.
// ---------------------------------------------------------------------------
constexpr int PL_BYTES = 128 * 64;           // one plane tile: 128 rows x 64B
constexpr int STAGE_BYTES = 4 * PL_BYTES;    // Ah, Al, Bh, Bl = 32KB
constexpr int GEMM_SMEM = 3 * STAGE_BYTES;   // 96KB

__global__ __launch_bounds__(256, 2) void gemm_mma(
    const __nv_bfloat16* __restrict__ Ah, const __nv_bfloat16* __restrict__ Al,
    const __nv_bfloat16* __restrict__ Bh, const __nv_bfloat16* __restrict__ Bl,
    const float* __restrict__ bias, float* __restrict__ C,
    __nv_bfloat16* __restrict__ Ch, __nv_bfloat16* __restrict__ Cl,
    int M, int N, int Kt)
{
    extern __shared__ __align__(1024) uint8_t smem[];

    const int tid  = threadIdx.x;
    const int wid  = tid >> 5;
    const int lane = tid & 31;
    const int warp_m = (wid & 3) * 32;
    const int warp_n = (wid >> 2) * 64;
    const size_t bm = (size_t)blockIdx.y * 128;
    const size_t bn = (size_t)blockIdx.x * 128;
    const uint32_t sbase = s2u(smem);

    // loader: f = tid + i*256 -> row = f>>2 (0..127), seg = f&3 (16B)
    uint32_t soff[2];
    size_t goff[2];
    #pragma unroll
    for (int i = 0; i < 2; i++) {
        int f = tid + i * 256;
        int row = f >> 2;
        int seg = f & 3;
        soff[i] = swz64((uint32_t)row * 64 + seg * 16);
        goff[i] = (size_t)row * Kt + seg * 8;
    }

    const int NC = Kt / 32;

    auto issue_copy = [&](int c, int stage) {
        const uint32_t ss = sbase + stage * STAGE_BYTES;
        const int ko = c * 32;
        #pragma unroll
        for (int i = 0; i < 2; i++) {
            const size_t ga = bm * Kt + goff[i] + ko;
            const size_t gb = bn * Kt + goff[i] + ko;
            CPASYNC16(ss                + soff[i], Ah + ga);
            CPASYNC16(ss + PL_BYTES     + soff[i], Al + ga);
            CPASYNC16(ss + 2 * PL_BYTES + soff[i], Bh + gb);
            CPASYNC16(ss + 3 * PL_BYTES + soff[i], Bl + gb);
        }
        asm volatile("cp.async.commit_group;");
    };

    const int a_row = warp_m + (lane & 15);
    const int a_sub = (lane >> 4) * 16;                     // byte
    const int b_row = warp_n + ((lane >> 4) & 1) * 8 + (lane & 7);
    const int b_sub = ((lane >> 3) & 1) * 16;               // byte

    float acc[2][8][4];
    #pragma unroll
    for (int mt = 0; mt < 2; mt++)
        #pragma unroll
        for (int nt = 0; nt < 8; nt++)
            #pragma unroll
            for (int q = 0; q < 4; q++) acc[mt][nt][q] = 0.f;

    issue_copy(0, 0);
    if (NC > 1) issue_copy(1, 1);

    for (int c = 0; c < NC; c++) {
        if (c + 1 < NC) { asm volatile("cp.async.wait_group 1;"); }
        else            { asm volatile("cp.async.wait_group 0;"); }
        __syncthreads();
        if (c + 2 < NC) issue_copy(c + 2, (c + 2) % 3);

        const uint32_t ss = sbase + (c % 3) * STAGE_BYTES;

        #pragma unroll
        for (int kk = 0; kk < 2; kk++) {
            uint32_t afh[2][4], afl[2][4];
            #pragma unroll
            for (int mt = 0; mt < 2; mt++) {
                uint32_t off = (uint32_t)(a_row + mt * 16) * 64 + kk * 32 + a_sub;
                LDMX4(afh[mt], ss + swz64(off));
                LDMX4(afl[mt], ss + PL_BYTES + swz64(off));
            }
            #pragma unroll
            for (int j = 0; j < 4; j++) {
                uint32_t off = (uint32_t)(b_row + j * 16) * 64 + kk * 32 + b_sub;
                uint32_t rh[4], rl[4];
                LDMX4(rh, ss + 2 * PL_BYTES + swz64(off));
                LDMX4(rl, ss + 3 * PL_BYTES + swz64(off));
                #pragma unroll
                for (int mt = 0; mt < 2; mt++) {
                    MMA16816(acc[mt][2 * j],     afh[mt], rh[0], rh[1]);
                    MMA16816(acc[mt][2 * j + 1], afh[mt], rh[2], rh[3]);
                    MMA16816(acc[mt][2 * j],     afl[mt], rh[0], rh[1]);
                    MMA16816(acc[mt][2 * j + 1], afl[mt], rh[2], rh[3]);
                    MMA16816(acc[mt][2 * j],     afh[mt], rl[0], rl[1]);
                    MMA16816(acc[mt][2 * j + 1], afh[mt], rl[2], rl[3]);
                }
            }
        }
    }

    if (Ch) {
        #pragma unroll
        for (int mt = 0; mt < 2; mt++) {
            const size_t row0 = bm + warp_m + mt * 16 + (lane >> 2);
            #pragma unroll
            for (int nt = 0; nt < 8; nt++) {
                const size_t col = bn + warp_n + nt * 8 + (lane & 3) * 2;
                uint32_t hp, lp;
                hilo2(acc[mt][nt][0], acc[mt][nt][1], hp, lp);
                *(uint32_t*)(Ch + row0 * (size_t)N + col) = hp;
                *(uint32_t*)(Cl + row0 * (size_t)N + col) = lp;
                hilo2(acc[mt][nt][2], acc[mt][nt][3], hp, lp);
                *(uint32_t*)(Ch + (row0 + 8) * (size_t)N + col) = hp;
                *(uint32_t*)(Cl + (row0 + 8) * (size_t)N + col) = lp;
            }
        }
    } else {
        #pragma unroll
        for (int mt = 0; mt < 2; mt++) {
            const size_t row0 = bm + warp_m + mt * 16 + (lane >> 2);
            #pragma unroll
            for (int nt = 0; nt < 8; nt++) {
                const size_t col = bn + warp_n + nt * 8 + (lane & 3) * 2;
                float bx = bias[col], by = bias[col + 1];
                float2 v0 = {acc[mt][nt][0] + bx, acc[mt][nt][1] + by};
                float2 v1 = {acc[mt][nt][2] + bx, acc[mt][nt][3] + by};
                *(float2*)(C + row0 * (size_t)N + col)       = v0;
                *(float2*)(C + (row0 + 8) * (size_t)N + col) = v1;
            }
        }
    }
}

// ---------------------------------------------------------------------------
// Flash-style attention (R10, passing): CTA = 64 queries x 512-key block,
// 4 warps (m16 each), per-warp online softmax, 8 chunks of 64 keys,
// double-buffered K+V cp.async, P stays in registers.
// Epilogue now writes hi/lo planes (att_h, att_l).
// ---------------------------------------------------------------------------
constexpr int sAQH = 0;
constexpr int sAQL = 8192;
constexpr int sBUF0 = 16384;
constexpr int sBUFSZ = 32768;
constexpr int ATTN_SMEM = 16384 + 2 * sBUFSZ;   // 80KB

__global__ __launch_bounds__(128) void attn_flash(const __nv_bfloat16* __restrict__ qh,
                                                  const __nv_bfloat16* __restrict__ ql,
                                                  __nv_bfloat16* __restrict__ ath,
                                                  __nv_bfloat16* __restrict__ atl)
{
    extern __shared__ __align__(1024) char smc[];
    const uint32_t sbs = s2u(smc);

    const int tid  = threadIdx.x;
    const int lane = tid & 31;
    const int w    = tid >> 5;

    const int idx = blockIdx.x;
    const int qt = idx & 7;
    const int g  = (idx >> 3) & 7;
    const int h  = (idx >> 6) & 15;
    const int b  = idx >> 10;
    const int pos0 = g * LG;
    const int q0   = pos0 + qt * 64;

    const int lrow = tid >> 3;
    const int lseg = tid & 7;
    uint32_t soff[4];
    #pragma unroll
    for (int i = 0; i < 4; i++)
        soff[i] = swz((uint32_t)(lrow + i * 16) * 128 + lseg * 16);

    #pragma unroll
    for (int i = 0; i < 4; i++) {
        const size_t qo = (size_t)(b * L + q0 + lrow + i * 16) * 3072 + h * 64 + lseg * 8;
        CPASYNC16(sbs + sAQH + soff[i], qh + qo);
        CPASYNC16(sbs + sAQL + soff[i], ql + qo);
    }

    auto issue_chunk = [&](int c, int buf) {
        const uint32_t bb = sbs + sBUF0 + buf * sBUFSZ;
        #pragma unroll
        for (int i = 0; i < 4; i++) {
            const size_t ko = (size_t)(b * L + pos0 + c * 64 + lrow + i * 16) * 3072
                              + 1024 + h * 64 + lseg * 8;
            CPASYNC16(bb         + soff[i], qh + ko);          // K hi
            CPASYNC16(bb + 8192  + soff[i], ql + ko);          // K lo
            CPASYNC16(bb + 16384 + soff[i], qh + ko + 1024);   // V hi
            CPASYNC16(bb + 24576 + soff[i], ql + ko + 1024);   // V lo
        }
        asm volatile("cp.async.commit_group;");
    };
    issue_chunk(0, 0);

    const int kRow  = ((lane >> 4) & 1) * 8 + (lane & 7);
    const int kSub  = ((lane >> 3) & 1) * 16;
    const int vRow  = (lane & 7) + ((lane >> 3) & 1) * 8;
    const int vColB = (lane >> 4) * 16;

    uint32_t qf[2][4][4];
    float o[8][4];
    #pragma unroll
    for (int t = 0; t < 8; t++)
        #pragma unroll
        for (int j = 0; j < 4; j++) o[t][j] = 0.f;
    float m0 = -1e30f, m1 = -1e30f, l0 = 0.f, l1 = 0.f;
    const float scale = 0.125f;

    for (int c = 0; c < 8; c++) {
        asm volatile("cp.async.wait_group 0;");
        __syncthreads();
        if (c + 1 < 8) issue_chunk(c + 1, (c + 1) & 1);
        if (c == 0) {
            #pragma unroll
            for (int pl = 0; pl < 2; pl++) {
                const uint32_t qb = sbs + (pl ? sAQL : sAQH);
                #pragma unroll
                for (int kk = 0; kk < 4; kk++) {
                    uint32_t off = (uint32_t)(w * 16 + (lane & 15)) * 128 + kk * 32 + (lane >> 4) * 16;
                    LDMX4(qf[pl][kk], qb + swz(off));
                }
            }
        }

        const uint32_t bb = sbs + sBUF0 + (c & 1) * sBUFSZ;

        // S = Q*K^T (3 passes)
        float s[8][4];
        #pragma unroll
        for (int t = 0; t < 8; t++)
            #pragma unroll
            for (int j = 0; j < 4; j++) s[t][j] = 0.f;

        #pragma unroll
        for (int p = 0; p < 3; p++) {
            const int qpl = (p == 1) ? 1 : 0;
            const uint32_t kb = bb + ((p == 2) ? 8192 : 0);
            #pragma unroll
            for (int kk = 0; kk < 4; kk++) {
                #pragma unroll
                for (int n16 = 0; n16 < 4; n16++) {
                    uint32_t bq[4];
                    uint32_t off = (uint32_t)(n16 * 16 + kRow) * 128 + kk * 32 + kSub;
                    LDMX4(bq, kb + swz(off));
                    MMA16816(s[2 * n16],     qf[qpl][kk], bq[0], bq[1]);
                    MMA16816(s[2 * n16 + 1], qf[qpl][kk], bq[2], bq[3]);
                }
            }
        }

        // online softmax update
        float cm0 = -1e30f, cm1 = -1e30f;
        #pragma unroll
        for (int t = 0; t < 8; t++) {
            cm0 = fmaxf(cm0, fmaxf(s[t][0], s[t][1]));
            cm1 = fmaxf(cm1, fmaxf(s[t][2], s[t][3]));
        }
        cm0 *= scale; cm1 *= scale;
        cm0 = fmaxf(cm0, __shfl_xor_sync(0xffffffffu, cm0, 1));
        cm0 = fmaxf(cm0, __shfl_xor_sync(0xffffffffu, cm0, 2));
        cm1 = fmaxf(cm1, __shfl_xor_sync(0xffffffffu, cm1, 1));
        cm1 = fmaxf(cm1, __shfl_xor_sync(0xffffffffu, cm1, 2));
        const float mn0 = fmaxf(m0, cm0);
        const float mn1 = fmaxf(m1, cm1);
        const float al0 = __expf(m0 - mn0);
        const float al1 = __expf(m1 - mn1);
        m0 = mn0; m1 = mn1;

        float ls0 = 0.f, ls1 = 0.f;
        #pragma unroll
        for (int t = 0; t < 8; t++) {
            float p0 = __expf(s[t][0] * scale - mn0);
            float p1 = __expf(s[t][1] * scale - mn0);
            float p2 = __expf(s[t][2] * scale - mn1);
            float p3 = __expf(s[t][3] * scale - mn1);
            s[t][0] = p0; s[t][1] = p1; s[t][2] = p2; s[t][3] = p3;
            ls0 += p0 + p1; ls1 += p2 + p3;
        }
        l0 = l0 * al0 + ls0;
        l1 = l1 * al1 + ls1;
        #pragma unroll
        for (int t = 0; t < 8; t++) {
            o[t][0] *= al0; o[t][1] *= al0;
            o[t][2] *= al1; o[t][3] *= al1;
        }

        // P -> bf16 hi/lo A-fragments (registers)
        uint32_t pfh[4][4], pfl[4][4];
        #pragma unroll
        for (int kk = 0; kk < 4; kk++) {
            hilo2(s[2 * kk][0],     s[2 * kk][1],     pfh[kk][0], pfl[kk][0]);
            hilo2(s[2 * kk][2],     s[2 * kk][3],     pfh[kk][1], pfl[kk][1]);
            hilo2(s[2 * kk + 1][0], s[2 * kk + 1][1], pfh[kk][2], pfl[kk][2]);
            hilo2(s[2 * kk + 1][2], s[2 * kk + 1][3], pfh[kk][3], pfl[kk][3]);
        }

        // O += P*V (3 passes)
        #pragma unroll
        for (int p = 0; p < 3; p++) {
            const uint32_t vb = bb + ((p == 2) ? 24576 : 16384);
            #pragma unroll
            for (int kk = 0; kk < 4; kk++) {
                const uint32_t* pf = (p == 1) ? pfl[kk] : pfh[kk];
                #pragma unroll
                for (int n16 = 0; n16 < 4; n16++) {
                    uint32_t bv[4];
                    uint32_t off = (uint32_t)(kk * 16 + vRow) * 128 + n16 * 32 + vColB;
                    LDMX4T(bv, vb + swz(off));
                    MMA16816(o[2 * n16],     pf, bv[0], bv[1]);
                    MMA16816(o[2 * n16 + 1], pf, bv[2], bv[3]);
                }
            }
        }
    }

    // finalize + store hi/lo planes
    l0 += __shfl_xor_sync(0xffffffffu, l0, 1);
    l0 += __shfl_xor_sync(0xffffffffu, l0, 2);
    l1 += __shfl_xor_sync(0xffffffffu, l1, 1);
    l1 += __shfl_xor_sync(0xffffffffu, l1, 2);
    const float inv0 = 1.0f / l0;
    const float inv1 = 1.0f / l1;

    const size_t gr0 = (size_t)(b * L + q0 + w * 16 + (lane >> 2)) * 1024 + h * 64;
    const size_t gr1 = gr0 + (size_t)8 * 1024;
    #pragma unroll
    for (int t = 0; t < 8; t++) {
        const int cc = t * 8 + (lane & 3) * 2;
        uint32_t hp, lp;
        hilo2(o[t][0] * inv0, o[t][1] * inv0, hp, lp);
        *(uint32_t*)(ath + gr0 + cc) = hp;
        *(uint32_t*)(atl + gr0 + cc) = lp;
        hilo2(o[t][2] * inv1, o[t][3] * inv1, hp, lp);
        *(uint32_t*)(ath + gr1 + cc) = hp;
        *(uint32_t*)(atl + gr1 + cc) = lp;
    }
}

// ---------------------------------------------------------------------------
extern "C" void kernel_launch(void* const* d_in, const int* in_sizes, int n_in,
                              void* d_out, int out_size)
{
    const float* x     = (const float*)d_in[0];
    const float* w_qkv = (const float*)d_in[1];
    const float* w_out = (const float*)d_in[2];
    const float* b_out = (const float*)d_in[3];
    float* out = (float*)d_out;

    __nv_bfloat16 *qh, *ql, *xh, *xl, *ath, *atl, *wqh, *wql, *woh, *wol;
    cudaGetSymbolAddress((void**)&qh,  g_qh);
    cudaGetSymbolAddress((void**)&ql,  g_ql);
    cudaGetSymbolAddress((void**)&xh,  g_xh);
    cudaGetSymbolAddress((void**)&xl,  g_xl);
    cudaGetSymbolAddress((void**)&ath, g_ath);
    cudaGetSymbolAddress((void**)&atl, g_atl);
    cudaGetSymbolAddress((void**)&wqh, g_wqh);
    cudaGetSymbolAddress((void**)&wql, g_wql);
    cudaGetSymbolAddress((void**)&woh, g_woh);
    cudaGetSymbolAddress((void**)&wol, g_wol);

    cudaFuncSetAttribute(gemm_mma, cudaFuncAttributeMaxDynamicSharedMemorySize,
                         GEMM_SMEM);
    cudaFuncSetAttribute(attn_flash, cudaFuncAttributeMaxDynamicSharedMemorySize,
                         ATTN_SMEM);

    split_fp32_planes<<<M_TOK, 256>>>(x, xh, xl, M_TOK);
    split_fp32_planes<<<3 * D, 256>>>(w_qkv, wqh, wql, 3 * D);
    split_fp32_planes<<<D, 256>>>(w_out, woh, wol, D);

    // 1) QKV projection -> bf16 hi/lo planes (N = 3072, K = 1024)
    gemm_mma<<<dim3(3 * D / 128, M_TOK / 128), 256, GEMM_SMEM>>>(
        xh, xl, wqh, wql, nullptr, nullptr, qh, ql, M_TOK, 3 * D, D);

    // 2) Flash attention -> att hi/lo planes
    attn_flash<<<Bsz * H * G * (LG / 64), 128, ATTN_SMEM>>>(qh, ql, ath, atl);

    // 3) Output projection + bias -> fp32 out (K = 1024)
    gemm_mma<<<dim3(D / 128, M_TOK / 128), 256, GEMM_SMEM>>>(
        ath, atl, woh, wol, b_out, out, nullptr, nullptr, M_TOK, D, D);
}

// round 12
// speedup vs baseline: 1.3602x; 1.0384x over previous
#include <cuda_runtime.h>
#include <cuda_bf16.h>
#include <math.h>
#include <stdint.h>

// Problem constants
constexpr int Bsz = 4;
constexpr int L   = 4096;
constexpr int D   = 1024;
constexpr int H   = 16;
constexpr int G   = 8;
constexpr int LG  = L / G;     // 512
constexpr int M_TOK = Bsz * L; // 16384

// Scratch planes (allocation-free: static __device__ globals)
__device__ __nv_bfloat16 g_qh [(size_t)M_TOK * 3072];   // qkv hi plane
__device__ __nv_bfloat16 g_ql [(size_t)M_TOK * 3072];   // qkv lo plane
__device__ __nv_bfloat16 g_xh [(size_t)M_TOK * 1024];
__device__ __nv_bfloat16 g_xl [(size_t)M_TOK * 1024];
__device__ __nv_bfloat16 g_ath[(size_t)M_TOK * 1024];
__device__ __nv_bfloat16 g_atl[(size_t)M_TOK * 1024];
__device__ __nv_bfloat16 g_wqh[(size_t)3072 * 1024];
__device__ __nv_bfloat16 g_wql[(size_t)3072 * 1024];
__device__ __nv_bfloat16 g_woh[(size_t)1024 * 1024];
__device__ __nv_bfloat16 g_wol[(size_t)1024 * 1024];

// ---------------------------------------------------------------------------
// helpers
// ---------------------------------------------------------------------------
__device__ __forceinline__ uint32_t swz64(uint32_t off) {   // 64B-row swizzle
    return off ^ ((off >> 3) & 0x30);
}
__device__ __forceinline__ uint32_t swz(uint32_t off) {     // 128B-row swizzle
    return off ^ ((off >> 3) & 0x70);
}
__device__ __forceinline__ uint32_t s2u(const void* p) {
    uint32_t a;
    asm("{ .reg .u64 t; cvta.to.shared.u64 t, %1; cvt.u32.u64 %0, t; }"
        : "=r"(a) : "l"(p));
    return a;
}
__device__ __forceinline__ void hilo2(float a, float b, uint32_t& hp, uint32_t& lp) {
    __nv_bfloat16 ha = __float2bfloat16(a);
    __nv_bfloat16 hb = __float2bfloat16(b);
    __nv_bfloat16 la = __float2bfloat16(a - __bfloat162float(ha));
    __nv_bfloat16 lb = __float2bfloat16(b - __bfloat162float(hb));
    hp = (uint32_t)__bfloat16_as_ushort(ha) | ((uint32_t)__bfloat16_as_ushort(hb) << 16);
    lp = (uint32_t)__bfloat16_as_ushort(la) | ((uint32_t)__bfloat16_as_ushort(lb) << 16);
}

#define MMA16816(acc, a, b0, b1)                                             \
    asm volatile(                                                            \
        "mma.sync.aligned.m16n8k16.row.col.f32.bf16.bf16.f32 "               \
        "{%0,%1,%2,%3}, {%4,%5,%6,%7}, {%8,%9}, {%0,%1,%2,%3};"              \
        : "+f"((acc)[0]), "+f"((acc)[1]), "+f"((acc)[2]), "+f"((acc)[3])     \
        : "r"((a)[0]), "r"((a)[1]), "r"((a)[2]), "r"((a)[3]),                \
          "r"(b0), "r"(b1))

#define LDMX4(r, addr)                                                       \
    asm volatile("ldmatrix.sync.aligned.m8n8.x4.shared.b16 {%0,%1,%2,%3}, [%4];" \
        : "=r"((r)[0]), "=r"((r)[1]), "=r"((r)[2]), "=r"((r)[3]) : "r"(addr))

#define LDMX4T(r, addr)                                                      \
    asm volatile("ldmatrix.sync.aligned.m8n8.x4.trans.shared.b16 {%0,%1,%2,%3}, [%4];" \
        : "=r"((r)[0]), "=r"((r)[1]), "=r"((r)[2]), "=r"((r)[3]) : "r"(addr))

#define CPASYNC16(dst, src)                                                  \
    asm volatile("cp.async.cg.shared.global [%0], [%1], 16;"                 \
        :: "r"(dst), "l"(src))

// ---------------------------------------------------------------------------
// Split fp32 [rows,1024] -> two bf16 planes [rows,1024].
// ---------------------------------------------------------------------------
__global__ void split_fp32_planes(const float* __restrict__ src,
                                  __nv_bfloat16* __restrict__ dsth,
                                  __nv_bfloat16* __restrict__ dstl,
                                  int rows)
{
    int idx = blockIdx.x * 256 + threadIdx.x;
    if (idx >= rows * 256) return;
    int row = idx >> 8;
    int c4  = (idx & 255) << 2;
    float4 v = *(const float4*)(src + (size_t)row * 1024 + c4);
    uint32_t hp0, lp0, hp1, lp1;
    hilo2(v.x, v.y, hp0, lp0);
    hilo2(v.z, v.w, hp1, lp1);
    size_t o = (size_t)row * 1024 + c4;
    *(uint32_t*)(dsth + o)     = hp0; *(uint32_t*)(dsth + o + 2) = hp1;
    *(uint32_t*)(dstl + o)     = lp0; *(uint32_t*)(dstl + o + 2) = lp1;
}

// ---------------------------------------------------------------------------
// Fused hi/lo plane GEMM: C = Ah*Bh^T + Al*Bh^T + Ah*Bl^T (+bias).
// 128x128 CTA tile, 4 warps (64x64 each), 128 threads, BK=32,
// 3-stage cp.async, single sync per chunk. 85 B of LDSM per MMA.
// ---------------------------------------------------------------------------
constexpr int PL_BYTES = 128 * 64;           // one plane tile: 128 rows x 64B
constexpr int STAGE_BYTES = 4 * PL_BYTES;    // Ah, Al, Bh, Bl = 32KB
constexpr int GEMM_SMEM = 3 * STAGE_BYTES;   // 96KB

__global__ __launch_bounds__(128, 2) void gemm_mma(
    const __nv_bfloat16* __restrict__ Ah, const __nv_bfloat16* __restrict__ Al,
    const __nv_bfloat16* __restrict__ Bh, const __nv_bfloat16* __restrict__ Bl,
    const float* __restrict__ bias, float* __restrict__ C,
    __nv_bfloat16* __restrict__ Ch, __nv_bfloat16* __restrict__ Cl,
    int M, int N, int Kt)
{
    extern __shared__ __align__(1024) uint8_t smem[];

    const int tid  = threadIdx.x;
    const int wid  = tid >> 5;
    const int lane = tid & 31;
    const int warp_m = (wid & 1) * 64;
    const int warp_n = (wid >> 1) * 64;
    const size_t bm = (size_t)blockIdx.y * 128;
    const size_t bn = (size_t)blockIdx.x * 128;
    const uint32_t sbase = s2u(smem);

    // loader: f = tid + i*128 -> row = f>>2 (0..127), seg = f&3 (16B), i=0..3
    uint32_t soff[4];
    size_t goff[4];
    #pragma unroll
    for (int i = 0; i < 4; i++) {
        int f = tid + i * 128;
        int row = f >> 2;
        int seg = f & 3;
        soff[i] = swz64((uint32_t)row * 64 + seg * 16);
        goff[i] = (size_t)row * Kt + seg * 8;
    }

    const int NC = Kt / 32;

    auto issue_copy = [&](int c, int stage) {
        const uint32_t ss = sbase + stage * STAGE_BYTES;
        const int ko = c * 32;
        #pragma unroll
        for (int i = 0; i < 4; i++) {
            const size_t ga = bm * Kt + goff[i] + ko;
            const size_t gb = bn * Kt + goff[i] + ko;
            CPASYNC16(ss                + soff[i], Ah + ga);
            CPASYNC16(ss + PL_BYTES     + soff[i], Al + ga);
            CPASYNC16(ss + 2 * PL_BYTES + soff[i], Bh + gb);
            CPASYNC16(ss + 3 * PL_BYTES + soff[i], Bl + gb);
        }
        asm volatile("cp.async.commit_group;");
    };

    const int a_row = warp_m + (lane & 15);
    const int a_sub = (lane >> 4) * 16;                     // byte
    const int b_row = warp_n + ((lane >> 4) & 1) * 8 + (lane & 7);
    const int b_sub = ((lane >> 3) & 1) * 16;               // byte

    float acc[4][8][4];
    #pragma unroll
    for (int mt = 0; mt < 4; mt++)
        #pragma unroll
        for (int nt = 0; nt < 8; nt++)
            #pragma unroll
            for (int q = 0; q < 4; q++) acc[mt][nt][q] = 0.f;

    issue_copy(0, 0);
    if (NC > 1) issue_copy(1, 1);

    for (int c = 0; c < NC; c++) {
        if (c + 1 < NC) { asm volatile("cp.async.wait_group 1;"); }
        else            { asm volatile("cp.async.wait_group 0;"); }
        __syncthreads();
        if (c + 2 < NC) issue_copy(c + 2, (c + 2) % 3);

        const uint32_t ss = sbase + (c % 3) * STAGE_BYTES;

        #pragma unroll
        for (int kk = 0; kk < 2; kk++) {
            uint32_t afh[4][4], afl[4][4];
            #pragma unroll
            for (int mt = 0; mt < 4; mt++) {
                uint32_t off = (uint32_t)(a_row + mt * 16) * 64 + kk * 32 + a_sub;
                LDMX4(afh[mt], ss + swz64(off));
                LDMX4(afl[mt], ss + PL_BYTES + swz64(off));
            }
            #pragma unroll
            for (int j = 0; j < 4; j++) {
                uint32_t off = (uint32_t)(b_row + j * 16) * 64 + kk * 32 + b_sub;
                uint32_t rh[4], rl[4];
                LDMX4(rh, ss + 2 * PL_BYTES + swz64(off));
                LDMX4(rl, ss + 3 * PL_BYTES + swz64(off));
                #pragma unroll
                for (int mt = 0; mt < 4; mt++) {
                    MMA16816(acc[mt][2 * j],     afh[mt], rh[0], rh[1]);
                    MMA16816(acc[mt][2 * j + 1], afh[mt], rh[2], rh[3]);
                    MMA16816(acc[mt][2 * j],     afl[mt], rh[0], rh[1]);
                    MMA16816(acc[mt][2 * j + 1], afl[mt], rh[2], rh[3]);
                    MMA16816(acc[mt][2 * j],     afh[mt], rl[0], rl[1]);
                    MMA16816(acc[mt][2 * j + 1], afh[mt], rl[2], rl[3]);
                }
            }
        }
    }

    if (Ch) {
        #pragma unroll
        for (int mt = 0; mt < 4; mt++) {
            const size_t row0 = bm + warp_m + mt * 16 + (lane >> 2);
            #pragma unroll
            for (int nt = 0; nt < 8; nt++) {
                const size_t col = bn + warp_n + nt * 8 + (lane & 3) * 2;
                uint32_t hp, lp;
                hilo2(acc[mt][nt][0], acc[mt][nt][1], hp, lp);
                *(uint32_t*)(Ch + row0 * (size_t)N + col) = hp;
                *(uint32_t*)(Cl + row0 * (size_t)N + col) = lp;
                hilo2(acc[mt][nt][2], acc[mt][nt][3], hp, lp);
                *(uint32_t*)(Ch + (row0 + 8) * (size_t)N + col) = hp;
                *(uint32_t*)(Cl + (row0 + 8) * (size_t)N + col) = lp;
            }
        }
    } else {
        #pragma unroll
        for (int mt = 0; mt < 4; mt++) {
            const size_t row0 = bm + warp_m + mt * 16 + (lane >> 2);
            #pragma unroll
            for (int nt = 0; nt < 8; nt++) {
                const size_t col = bn + warp_n + nt * 8 + (lane & 3) * 2;
                float bx = bias[col], by = bias[col + 1];
                float2 v0 = {acc[mt][nt][0] + bx, acc[mt][nt][1] + by};
                float2 v1 = {acc[mt][nt][2] + bx, acc[mt][nt][3] + by};
                *(float2*)(C + row0 * (size_t)N + col)       = v0;
                *(float2*)(C + (row0 + 8) * (size_t)N + col) = v1;
            }
        }
    }
}

// ---------------------------------------------------------------------------
// Flash-style attention (R11, passing): CTA = 64 queries x 512-key block,
// 4 warps (m16 each), per-warp online softmax, 8 chunks of 64 keys,
// double-buffered K+V cp.async, P stays in registers. Writes hi/lo planes.
// ---------------------------------------------------------------------------
constexpr int sAQH = 0;
constexpr int sAQL = 8192;
constexpr int sBUF0 = 16384;
constexpr int sBUFSZ = 32768;
constexpr int ATTN_SMEM = 16384 + 2 * sBUFSZ;   // 80KB

__global__ __launch_bounds__(128) void attn_flash(const __nv_bfloat16* __restrict__ qh,
                                                  const __nv_bfloat16* __restrict__ ql,
                                                  __nv_bfloat16* __restrict__ ath,
                                                  __nv_bfloat16* __restrict__ atl)
{
    extern __shared__ __align__(1024) char smc[];
    const uint32_t sbs = s2u(smc);

    const int tid  = threadIdx.x;
    const int lane = tid & 31;
    const int w    = tid >> 5;

    const int idx = blockIdx.x;
    const int qt = idx & 7;
    const int g  = (idx >> 3) & 7;
    const int h  = (idx >> 6) & 15;
    const int b  = idx >> 10;
    const int pos0 = g * LG;
    const int q0   = pos0 + qt * 64;

    const int lrow = tid >> 3;
    const int lseg = tid & 7;
    uint32_t soff[4];
    #pragma unroll
    for (int i = 0; i < 4; i++)
        soff[i] = swz((uint32_t)(lrow + i * 16) * 128 + lseg * 16);

    #pragma unroll
    for (int i = 0; i < 4; i++) {
        const size_t qo = (size_t)(b * L + q0 + lrow + i * 16) * 3072 + h * 64 + lseg * 8;
        CPASYNC16(sbs + sAQH + soff[i], qh + qo);
        CPASYNC16(sbs + sAQL + soff[i], ql + qo);
    }

    auto issue_chunk = [&](int c, int buf) {
        const uint32_t bb = sbs + sBUF0 + buf * sBUFSZ;
        #pragma unroll
        for (int i = 0; i < 4; i++) {
            const size_t ko = (size_t)(b * L + pos0 + c * 64 + lrow + i * 16) * 3072
                              + 1024 + h * 64 + lseg * 8;
            CPASYNC16(bb         + soff[i], qh + ko);          // K hi
            CPASYNC16(bb + 8192  + soff[i], ql + ko);          // K lo
            CPASYNC16(bb + 16384 + soff[i], qh + ko + 1024);   // V hi
            CPASYNC16(bb + 24576 + soff[i], ql + ko + 1024);   // V lo
        }
        asm volatile("cp.async.commit_group;");
    };
    issue_chunk(0, 0);

    const int kRow  = ((lane >> 4) & 1) * 8 + (lane & 7);
    const int kSub  = ((lane >> 3) & 1) * 16;
    const int vRow  = (lane & 7) + ((lane >> 3) & 1) * 8;
    const int vColB = (lane >> 4) * 16;

    uint32_t qf[2][4][4];
    float o[8][4];
    #pragma unroll
    for (int t = 0; t < 8; t++)
        #pragma unroll
        for (int j = 0; j < 4; j++) o[t][j] = 0.f;
    float m0 = -1e30f, m1 = -1e30f, l0 = 0.f, l1 = 0.f;
    const float scale = 0.125f;

    for (int c = 0; c < 8; c++) {
        asm volatile("cp.async.wait_group 0;");
        __syncthreads();
        if (c + 1 < 8) issue_chunk(c + 1, (c + 1) & 1);
        if (c == 0) {
            #pragma unroll
            for (int pl = 0; pl < 2; pl++) {
                const uint32_t qb = sbs + (pl ? sAQL : sAQH);
                #pragma unroll
                for (int kk = 0; kk < 4; kk++) {
                    uint32_t off = (uint32_t)(w * 16 + (lane & 15)) * 128 + kk * 32 + (lane >> 4) * 16;
                    LDMX4(qf[pl][kk], qb + swz(off));
                }
            }
        }

        const uint32_t bb = sbs + sBUF0 + (c & 1) * sBUFSZ;

        float s[8][4];
        #pragma unroll
        for (int t = 0; t < 8; t++)
            #pragma unroll
            for (int j = 0; j < 4; j++) s[t][j] = 0.f;

        #pragma unroll
        for (int p = 0; p < 3; p++) {
            const int qpl = (p == 1) ? 1 : 0;
            const uint32_t kb = bb + ((p == 2) ? 8192 : 0);
            #pragma unroll
            for (int kk = 0; kk < 4; kk++) {
                #pragma unroll
                for (int n16 = 0; n16 < 4; n16++) {
                    uint32_t bq[4];
                    uint32_t off = (uint32_t)(n16 * 16 + kRow) * 128 + kk * 32 + kSub;
                    LDMX4(bq, kb + swz(off));
                    MMA16816(s[2 * n16],     qf[qpl][kk], bq[0], bq[1]);
                    MMA16816(s[2 * n16 + 1], qf[qpl][kk], bq[2], bq[3]);
                }
            }
        }

        float cm0 = -1e30f, cm1 = -1e30f;
        #pragma unroll
        for (int t = 0; t < 8; t++) {
            cm0 = fmaxf(cm0, fmaxf(s[t][0], s[t][1]));
            cm1 = fmaxf(cm1, fmaxf(s[t][2], s[t][3]));
        }
        cm0 *= scale; cm1 *= scale;
        cm0 = fmaxf(cm0, __shfl_xor_sync(0xffffffffu, cm0, 1));
        cm0 = fmaxf(cm0, __shfl_xor_sync(0xffffffffu, cm0, 2));
        cm1 = fmaxf(cm1, __shfl_xor_sync(0xffffffffu, cm1, 1));
        cm1 = fmaxf(cm1, __shfl_xor_sync(0xffffffffu, cm1, 2));
        const float mn0 = fmaxf(m0, cm0);
        const float mn1 = fmaxf(m1, cm1);
        const float al0 = __expf(m0 - mn0);
        const float al1 = __expf(m1 - mn1);
        m0 = mn0; m1 = mn1;

        float ls0 = 0.f, ls1 = 0.f;
        #pragma unroll
        for (int t = 0; t < 8; t++) {
            float p0 = __expf(s[t][0] * scale - mn0);
            float p1 = __expf(s[t][1] * scale - mn0);
            float p2 = __expf(s[t][2] * scale - mn1);
            float p3 = __expf(s[t][3] * scale - mn1);
            s[t][0] = p0; s[t][1] = p1; s[t][2] = p2; s[t][3] = p3;
            ls0 += p0 + p1; ls1 += p2 + p3;
        }
        l0 = l0 * al0 + ls0;
        l1 = l1 * al1 + ls1;
        #pragma unroll
        for (int t = 0; t < 8; t++) {
            o[t][0] *= al0; o[t][1] *= al0;
            o[t][2] *= al1; o[t][3] *= al1;
        }

        uint32_t pfh[4][4], pfl[4][4];
        #pragma unroll
        for (int kk = 0; kk < 4; kk++) {
            hilo2(s[2 * kk][0],     s[2 * kk][1],     pfh[kk][0], pfl[kk][0]);
            hilo2(s[2 * kk][2],     s[2 * kk][3],     pfh[kk][1], pfl[kk][1]);
            hilo2(s[2 * kk + 1][0], s[2 * kk + 1][1], pfh[kk][2], pfl[kk][2]);
            hilo2(s[2 * kk + 1][2], s[2 * kk + 1][3], pfh[kk][3], pfl[kk][3]);
        }

        #pragma unroll
        for (int p = 0; p < 3; p++) {
            const uint32_t vb = bb + ((p == 2) ? 24576 : 16384);
            #pragma unroll
            for (int kk = 0; kk < 4; kk++) {
                const uint32_t* pf = (p == 1) ? pfl[kk] : pfh[kk];
                #pragma unroll
                for (int n16 = 0; n16 < 4; n16++) {
                    uint32_t bv[4];
                    uint32_t off = (uint32_t)(kk * 16 + vRow) * 128 + n16 * 32 + vColB;
                    LDMX4T(bv, vb + swz(off));
                    MMA16816(o[2 * n16],     pf, bv[0], bv[1]);
                    MMA16816(o[2 * n16 + 1], pf, bv[2], bv[3]);
                }
            }
        }
    }

    l0 += __shfl_xor_sync(0xffffffffu, l0, 1);
    l0 += __shfl_xor_sync(0xffffffffu, l0, 2);
    l1 += __shfl_xor_sync(0xffffffffu, l1, 1);
    l1 += __shfl_xor_sync(0xffffffffu, l1, 2);
    const float inv0 = 1.0f / l0;
    const float inv1 = 1.0f / l1;

    const size_t gr0 = (size_t)(b * L + q0 + w * 16 + (lane >> 2)) * 1024 + h * 64;
    const size_t gr1 = gr0 + (size_t)8 * 1024;
    #pragma unroll
    for (int t = 0; t < 8; t++) {
        const int cc = t * 8 + (lane & 3) * 2;
        uint32_t hp, lp;
        hilo2(o[t][0] * inv0, o[t][1] * inv0, hp, lp);
        *(uint32_t*)(ath + gr0 + cc) = hp;
        *(uint32_t*)(atl + gr0 + cc) = lp;
        hilo2(o[t][2] * inv1, o[t][3] * inv1, hp, lp);
        *(uint32_t*)(ath + gr1 + cc) = hp;
        *(uint32_t*)(atl + gr1 + cc) = lp;
    }
}

// ---------------------------------------------------------------------------
extern "C" void kernel_launch(void* const* d_in, const int* in_sizes, int n_in,
                              void* d_out, int out_size)
{
    const float* x     = (const float*)d_in[0];
    const float* w_qkv = (const float*)d_in[1];
    const float* w_out = (const float*)d_in[2];
    const float* b_out = (const float*)d_in[3];
    float* out = (float*)d_out;

    __nv_bfloat16 *qh, *ql, *xh, *xl, *ath, *atl, *wqh, *wql, *woh, *wol;
    cudaGetSymbolAddress((void**)&qh,  g_qh);
    cudaGetSymbolAddress((void**)&ql,  g_ql);
    cudaGetSymbolAddress((void**)&xh,  g_xh);
    cudaGetSymbolAddress((void**)&xl,  g_xl);
    cudaGetSymbolAddress((void**)&ath, g_ath);
    cudaGetSymbolAddress((void**)&atl, g_atl);
    cudaGetSymbolAddress((void**)&wqh, g_wqh);
    cudaGetSymbolAddress((void**)&wql, g_wql);
    cudaGetSymbolAddress((void**)&woh, g_woh);
    cudaGetSymbolAddress((void**)&wol, g_wol);

    cudaFuncSetAttribute(gemm_mma, cudaFuncAttributeMaxDynamicSharedMemorySize,
                         GEMM_SMEM);
    cudaFuncSetAttribute(attn_flash, cudaFuncAttributeMaxDynamicSharedMemorySize,
                         ATTN_SMEM);

    split_fp32_planes<<<M_TOK, 256>>>(x, xh, xl, M_TOK);
    split_fp32_planes<<<3 * D, 256>>>(w_qkv, wqh, wql, 3 * D);
    split_fp32_planes<<<D, 256>>>(w_out, wol ? woh : woh, wol, D);

    // 1) QKV projection -> bf16 hi/lo planes (N = 3072, K = 1024)
    gemm_mma<<<dim3(3 * D / 128, M_TOK / 128), 128, GEMM_SMEM>>>(
        xh, xl, wqh, wql, nullptr, nullptr, qh, ql, M_TOK, 3 * D, D);

    // 2) Flash attention -> att hi/lo planes
    attn_flash<<<Bsz * H * G * (LG / 64), 128, ATTN_SMEM>>>(qh, ql, ath, atl);

    // 3) Output projection + bias -> fp32 out (K = 1024)
    gemm_mma<<<dim3(D / 128, M_TOK / 128), 128, GEMM_SMEM>>>(
        ath, atl, woh, wol, b_out, out, nullptr, nullptr, M_TOK, D, D);
}

// round 13
// speedup vs baseline: 1.3605x; 1.0002x over previous
#include <cuda_runtime.h>
#include <cuda_bf16.h>
#include <math.h>
#include <stdint.h>

// Problem constants
constexpr int Bsz = 4;
constexpr int L   = 4096;
constexpr int D   = 1024;
constexpr int H   = 16;
constexpr int G   = 8;
constexpr int LG  = L / G;     // 512
constexpr int M_TOK = Bsz * L; // 16384

// Scratch planes (allocation-free: static __device__ globals)
__device__ __nv_bfloat16 g_qh [(size_t)M_TOK * 3072];   // qkv hi plane
__device__ __nv_bfloat16 g_ql [(size_t)M_TOK * 3072];   // qkv lo plane
__device__ __nv_bfloat16 g_xh [(size_t)M_TOK * 1024];
__device__ __nv_bfloat16 g_xl [(size_t)M_TOK * 1024];
__device__ __nv_bfloat16 g_ath[(size_t)M_TOK * 1024];
__device__ __nv_bfloat16 g_atl[(size_t)M_TOK * 1024];
__device__ __nv_bfloat16 g_wqh[(size_t)3072 * 1024];
__device__ __nv_bfloat16 g_wql[(size_t)3072 * 1024];
__device__ __nv_bfloat16 g_woh[(size_t)1024 * 1024];
__device__ __nv_bfloat16 g_wol[(size_t)1024 * 1024];

// ---------------------------------------------------------------------------
// helpers
// ---------------------------------------------------------------------------
__device__ __forceinline__ uint32_t swz64(uint32_t off) {   // 64B-row swizzle
    return off ^ ((off >> 3) & 0x30);
}
__device__ __forceinline__ uint32_t swz(uint32_t off) {     // 128B-row swizzle
    return off ^ ((off >> 3) & 0x70);
}
__device__ __forceinline__ uint32_t s2u(const void* p) {
    uint32_t a;
    asm("{ .reg .u64 t; cvta.to.shared.u64 t, %1; cvt.u32.u64 %0, t; }"
        : "=r"(a) : "l"(p));
    return a;
}
__device__ __forceinline__ void hilo2(float a, float b, uint32_t& hp, uint32_t& lp) {
    __nv_bfloat16 ha = __float2bfloat16(a);
    __nv_bfloat16 hb = __float2bfloat16(b);
    __nv_bfloat16 la = __float2bfloat16(a - __bfloat162float(ha));
    __nv_bfloat16 lb = __float2bfloat16(b - __bfloat162float(hb));
    hp = (uint32_t)__bfloat16_as_ushort(ha) | ((uint32_t)__bfloat16_as_ushort(hb) << 16);
    lp = (uint32_t)__bfloat16_as_ushort(la) | ((uint32_t)__bfloat16_as_ushort(lb) << 16);
}

// NOTE: no volatile — pure register op; data deps via "+f" keep it correct and
// let ptxas schedule around HMMA latency.
#define MMA16816(acc, a, b0, b1)                                             \
    asm("mma.sync.aligned.m16n8k16.row.col.f32.bf16.bf16.f32 "               \
        "{%0,%1,%2,%3}, {%4,%5,%6,%7}, {%8,%9}, {%0,%1,%2,%3};"              \
        : "+f"((acc)[0]), "+f"((acc)[1]), "+f"((acc)[2]), "+f"((acc)[3])     \
        : "r"((a)[0]), "r"((a)[1]), "r"((a)[2]), "r"((a)[3]),                \
          "r"(b0), "r"(b1))

#define LDMX4(r, addr)                                                       \
    asm volatile("ldmatrix.sync.aligned.m8n8.x4.shared.b16 {%0,%1,%2,%3}, [%4];" \
        : "=r"((r)[0]), "=r"((r)[1]), "=r"((r)[2]), "=r"((r)[3]) : "r"(addr))

#define LDMX4T(r, addr)                                                      \
    asm volatile("ldmatrix.sync.aligned.m8n8.x4.trans.shared.b16 {%0,%1,%2,%3}, [%4];" \
        : "=r"((r)[0]), "=r"((r)[1]), "=r"((r)[2]), "=r"((r)[3]) : "r"(addr))

#define CPASYNC16(dst, src)                                                  \
    asm volatile("cp.async.cg.shared.global [%0], [%1], 16;"                 \
        :: "r"(dst), "l"(src))

// ---------------------------------------------------------------------------
// Split fp32 [rows,1024] -> two bf16 planes [rows,1024].
// ---------------------------------------------------------------------------
__global__ void split_fp32_planes(const float* __restrict__ src,
                                  __nv_bfloat16* __restrict__ dsth,
                                  __nv_bfloat16* __restrict__ dstl,
                                  int rows)
{
    int idx = blockIdx.x * 256 + threadIdx.x;
    if (idx >= rows * 256) return;
    int row = idx >> 8;
    int c4  = (idx & 255) << 2;
    float4 v = *(const float4*)(src + (size_t)row * 1024 + c4);
    uint32_t hp0, lp0, hp1, lp1;
    hilo2(v.x, v.y, hp0, lp0);
    hilo2(v.z, v.w, hp1, lp1);
    size_t o = (size_t)row * 1024 + c4;
    *(uint32_t*)(dsth + o)     = hp0; *(uint32_t*)(dsth + o + 2) = hp1;
    *(uint32_t*)(dstl + o)     = lp0; *(uint32_t*)(dstl + o + 2) = lp1;
}

// ---------------------------------------------------------------------------
// Fused hi/lo plane GEMM: C = Ah*Bh^T + Al*Bh^T + Ah*Bl^T (+bias).
// 128x128 CTA tile, 4 warps (64x64 each), 128 threads, BK=32,
// 3-stage cp.async, single sync per chunk. Pass-major MMA order:
// same-accumulator reuse distance = 8 MMAs (was 2).
// ---------------------------------------------------------------------------
constexpr int PL_BYTES = 128 * 64;           // one plane tile: 128 rows x 64B
constexpr int STAGE_BYTES = 4 * PL_BYTES;    // Ah, Al, Bh, Bl = 32KB
constexpr int GEMM_SMEM = 3 * STAGE_BYTES;   // 96KB

__global__ __launch_bounds__(128, 2) void gemm_mma(
    const __nv_bfloat16* __restrict__ Ah, const __nv_bfloat16* __restrict__ Al,
    const __nv_bfloat16* __restrict__ Bh, const __nv_bfloat16* __restrict__ Bl,
    const float* __restrict__ bias, float* __restrict__ C,
    __nv_bfloat16* __restrict__ Ch, __nv_bfloat16* __restrict__ Cl,
    int M, int N, int Kt)
{
    extern __shared__ __align__(1024) uint8_t smem[];

    const int tid  = threadIdx.x;
    const int wid  = tid >> 5;
    const int lane = tid & 31;
    const int warp_m = (wid & 1) * 64;
    const int warp_n = (wid >> 1) * 64;
    const size_t bm = (size_t)blockIdx.y * 128;
    const size_t bn = (size_t)blockIdx.x * 128;
    const uint32_t sbase = s2u(smem);

    // loader: f = tid + i*128 -> row = f>>2 (0..127), seg = f&3 (16B), i=0..3
    uint32_t soff[4];
    size_t goff[4];
    #pragma unroll
    for (int i = 0; i < 4; i++) {
        int f = tid + i * 128;
        int row = f >> 2;
        int seg = f & 3;
        soff[i] = swz64((uint32_t)row * 64 + seg * 16);
        goff[i] = (size_t)row * Kt + seg * 8;
    }

    const int NC = Kt / 32;

    auto issue_copy = [&](int c, int stage) {
        const uint32_t ss = sbase + stage * STAGE_BYTES;
        const int ko = c * 32;
        #pragma unroll
        for (int i = 0; i < 4; i++) {
            const size_t ga = bm * Kt + goff[i] + ko;
            const size_t gb = bn * Kt + goff[i] + ko;
            CPASYNC16(ss                + soff[i], Ah + ga);
            CPASYNC16(ss + PL_BYTES     + soff[i], Al + ga);
            CPASYNC16(ss + 2 * PL_BYTES + soff[i], Bh + gb);
            CPASYNC16(ss + 3 * PL_BYTES + soff[i], Bl + gb);
        }
        asm volatile("cp.async.commit_group;");
    };

    const int a_row = warp_m + (lane & 15);
    const int a_sub = (lane >> 4) * 16;                     // byte
    const int b_row = warp_n + ((lane >> 4) & 1) * 8 + (lane & 7);
    const int b_sub = ((lane >> 3) & 1) * 16;               // byte

    float acc[4][8][4];
    #pragma unroll
    for (int mt = 0; mt < 4; mt++)
        #pragma unroll
        for (int nt = 0; nt < 8; nt++)
            #pragma unroll
            for (int q = 0; q < 4; q++) acc[mt][nt][q] = 0.f;

    issue_copy(0, 0);
    if (NC > 1) issue_copy(1, 1);

    for (int c = 0; c < NC; c++) {
        if (c + 1 < NC) { asm volatile("cp.async.wait_group 1;"); }
        else            { asm volatile("cp.async.wait_group 0;"); }
        __syncthreads();
        if (c + 2 < NC) issue_copy(c + 2, (c + 2) % 3);

        const uint32_t ss = sbase + (c % 3) * STAGE_BYTES;

        #pragma unroll
        for (int kk = 0; kk < 2; kk++) {
            uint32_t afh[4][4], afl[4][4];
            #pragma unroll
            for (int mt = 0; mt < 4; mt++) {
                uint32_t off = (uint32_t)(a_row + mt * 16) * 64 + kk * 32 + a_sub;
                LDMX4(afh[mt], ss + swz64(off));
                LDMX4(afl[mt], ss + PL_BYTES + swz64(off));
            }
            #pragma unroll
            for (int j = 0; j < 4; j++) {
                uint32_t off = (uint32_t)(b_row + j * 16) * 64 + kk * 32 + b_sub;
                uint32_t rh[4], rl[4];
                LDMX4(rh, ss + 2 * PL_BYTES + swz64(off));
                LDMX4(rl, ss + 3 * PL_BYTES + swz64(off));
                // pass 0: Ah*Bh (8 independent MMAs)
                #pragma unroll
                for (int mt = 0; mt < 4; mt++) {
                    MMA16816(acc[mt][2 * j],     afh[mt], rh[0], rh[1]);
                    MMA16816(acc[mt][2 * j + 1], afh[mt], rh[2], rh[3]);
                }
                // pass 1: Al*Bh
                #pragma unroll
                for (int mt = 0; mt < 4; mt++) {
                    MMA16816(acc[mt][2 * j],     afl[mt], rh[0], rh[1]);
                    MMA16816(acc[mt][2 * j + 1], afl[mt], rh[2], rh[3]);
                }
                // pass 2: Ah*Bl
                #pragma unroll
                for (int mt = 0; mt < 4; mt++) {
                    MMA16816(acc[mt][2 * j],     afh[mt], rl[0], rl[1]);
                    MMA16816(acc[mt][2 * j + 1], afh[mt], rl[2], rl[3]);
                }
            }
        }
    }

    if (Ch) {
        #pragma unroll
        for (int mt = 0; mt < 4; mt++) {
            const size_t row0 = bm + warp_m + mt * 16 + (lane >> 2);
            #pragma unroll
            for (int nt = 0; nt < 8; nt++) {
                const size_t col = bn + warp_n + nt * 8 + (lane & 3) * 2;
                uint32_t hp, lp;
                hilo2(acc[mt][nt][0], acc[mt][nt][1], hp, lp);
                *(uint32_t*)(Ch + row0 * (size_t)N + col) = hp;
                *(uint32_t*)(Cl + row0 * (size_t)N + col) = lp;
                hilo2(acc[mt][nt][2], acc[mt][nt][3], hp, lp);
                *(uint32_t*)(Ch + (row0 + 8) * (size_t)N + col) = hp;
                *(uint32_t*)(Cl + (row0 + 8) * (size_t)N + col) = lp;
            }
        }
    } else {
        #pragma unroll
        for (int mt = 0; mt < 4; mt++) {
            const size_t row0 = bm + warp_m + mt * 16 + (lane >> 2);
            #pragma unroll
            for (int nt = 0; nt < 8; nt++) {
                const size_t col = bn + warp_n + nt * 8 + (lane & 3) * 2;
                float bx = bias[col], by = bias[col + 1];
                float2 v0 = {acc[mt][nt][0] + bx, acc[mt][nt][1] + by};
                float2 v1 = {acc[mt][nt][2] + bx, acc[mt][nt][3] + by};
                *(float2*)(C + row0 * (size_t)N + col)       = v0;
                *(float2*)(C + (row0 + 8) * (size_t)N + col) = v1;
            }
        }
    }
}

// ---------------------------------------------------------------------------
// Flash-style attention: CTA = 64 queries x 512-key block, 4 warps (m16 each),
// per-warp online softmax, 8 chunks of 64 keys, double-buffered K+V cp.async,
// P stays in registers. Writes hi/lo planes.
// ---------------------------------------------------------------------------
constexpr int sAQH = 0;
constexpr int sAQL = 8192;
constexpr int sBUF0 = 16384;
constexpr int sBUFSZ = 32768;
constexpr int ATTN_SMEM = 16384 + 2 * sBUFSZ;   // 80KB

__global__ __launch_bounds__(128) void attn_flash(const __nv_bfloat16* __restrict__ qh,
                                                  const __nv_bfloat16* __restrict__ ql,
                                                  __nv_bfloat16* __restrict__ ath,
                                                  __nv_bfloat16* __restrict__ atl)
{
    extern __shared__ __align__(1024) char smc[];
    const uint32_t sbs = s2u(smc);

    const int tid  = threadIdx.x;
    const int lane = tid & 31;
    const int w    = tid >> 5;

    const int idx = blockIdx.x;
    const int qt = idx & 7;
    const int g  = (idx >> 3) & 7;
    const int h  = (idx >> 6) & 15;
    const int b  = idx >> 10;
    const int pos0 = g * LG;
    const int q0   = pos0 + qt * 64;

    const int lrow = tid >> 3;
    const int lseg = tid & 7;
    uint32_t soff[4];
    #pragma unroll
    for (int i = 0; i < 4; i++)
        soff[i] = swz((uint32_t)(lrow + i * 16) * 128 + lseg * 16);

    #pragma unroll
    for (int i = 0; i < 4; i++) {
        const size_t qo = (size_t)(b * L + q0 + lrow + i * 16) * 3072 + h * 64 + lseg * 8;
        CPASYNC16(sbs + sAQH + soff[i], qh + qo);
        CPASYNC16(sbs + sAQL + soff[i], ql + qo);
    }

    auto issue_chunk = [&](int c, int buf) {
        const uint32_t bb = sbs + sBUF0 + buf * sBUFSZ;
        #pragma unroll
        for (int i = 0; i < 4; i++) {
            const size_t ko = (size_t)(b * L + pos0 + c * 64 + lrow + i * 16) * 3072
                              + 1024 + h * 64 + lseg * 8;
            CPASYNC16(bb         + soff[i], qh + ko);          // K hi
            CPASYNC16(bb + 8192  + soff[i], ql + ko);          // K lo
            CPASYNC16(bb + 16384 + soff[i], qh + ko + 1024);   // V hi
            CPASYNC16(bb + 24576 + soff[i], ql + ko + 1024);   // V lo
        }
        asm volatile("cp.async.commit_group;");
    };
    issue_chunk(0, 0);

    const int kRow  = ((lane >> 4) & 1) * 8 + (lane & 7);
    const int kSub  = ((lane >> 3) & 1) * 16;
    const int vRow  = (lane & 7) + ((lane >> 3) & 1) * 8;
    const int vColB = (lane >> 4) * 16;

    uint32_t qf[2][4][4];
    float o[8][4];
    #pragma unroll
    for (int t = 0; t < 8; t++)
        #pragma unroll
        for (int j = 0; j < 4; j++) o[t][j] = 0.f;
    float m0 = -1e30f, m1 = -1e30f, l0 = 0.f, l1 = 0.f;
    const float scale = 0.125f;

    for (int c = 0; c < 8; c++) {
        asm volatile("cp.async.wait_group 0;");
        __syncthreads();
        if (c + 1 < 8) issue_chunk(c + 1, (c + 1) & 1);
        if (c == 0) {
            #pragma unroll
            for (int pl = 0; pl < 2; pl++) {
                const uint32_t qb = sbs + (pl ? sAQL : sAQH);
                #pragma unroll
                for (int kk = 0; kk < 4; kk++) {
                    uint32_t off = (uint32_t)(w * 16 + (lane & 15)) * 128 + kk * 32 + (lane >> 4) * 16;
                    LDMX4(qf[pl][kk], qb + swz(off));
                }
            }
        }

        const uint32_t bb = sbs + sBUF0 + (c & 1) * sBUFSZ;

        float s[8][4];
        #pragma unroll
        for (int t = 0; t < 8; t++)
            #pragma unroll
            for (int j = 0; j < 4; j++) s[t][j] = 0.f;

        #pragma unroll
        for (int p = 0; p < 3; p++) {
            const int qpl = (p == 1) ? 1 : 0;
            const uint32_t kb = bb + ((p == 2) ? 8192 : 0);
            #pragma unroll
            for (int kk = 0; kk < 4; kk++) {
                #pragma unroll
                for (int n16 = 0; n16 < 4; n16++) {
                    uint32_t bq[4];
                    uint32_t off = (uint32_t)(n16 * 16 + kRow) * 128 + kk * 32 + kSub;
                    LDMX4(bq, kb + swz(off));
                    MMA16816(s[2 * n16],     qf[qpl][kk], bq[0], bq[1]);
                    MMA16816(s[2 * n16 + 1], qf[qpl][kk], bq[2], bq[3]);
                }
            }
        }

        float cm0 = -1e30f, cm1 = -1e30f;
        #pragma unroll
        for (int t = 0; t < 8; t++) {
            cm0 = fmaxf(cm0, fmaxf(s[t][0], s[t][1]));
            cm1 = fmaxf(cm1, fmaxf(s[t][2], s[t][3]));
        }
        cm0 *= scale; cm1 *= scale;
        cm0 = fmaxf(cm0, __shfl_xor_sync(0xffffffffu, cm0, 1));
        cm0 = fmaxf(cm0, __shfl_xor_sync(0xffffffffu, cm0, 2));
        cm1 = fmaxf(cm1, __shfl_xor_sync(0xffffffffu, cm1, 1));
        cm1 = fmaxf(cm1, __shfl_xor_sync(0xffffffffu, cm1, 2));
        const float mn0 = fmaxf(m0, cm0);
        const float mn1 = fmaxf(m1, cm1);
        const float al0 = __expf(m0 - mn0);
        const float al1 = __expf(m1 - mn1);
        m0 = mn0; m1 = mn1;

        float ls0 = 0.f, ls1 = 0.f;
        #pragma unroll
        for (int t = 0; t < 8; t++) {
            float p0 = __expf(s[t][0] * scale - mn0);
            float p1 = __expf(s[t][1] * scale - mn0);
            float p2 = __expf(s[t][2] * scale - mn1);
            float p3 = __expf(s[t][3] * scale - mn1);
            s[t][0] = p0; s[t][1] = p1; s[t][2] = p2; s[t][3] = p3;
            ls0 += p0 + p1; ls1 += p2 + p3;
        }
        l0 = l0 * al0 + ls0;
        l1 = l1 * al1 + ls1;
        #pragma unroll
        for (int t = 0; t < 8; t++) {
            o[t][0] *= al0; o[t][1] *= al0;
            o[t][2] *= al1; o[t][3] *= al1;
        }

        uint32_t pfh[4][4], pfl[4][4];
        #pragma unroll
        for (int kk = 0; kk < 4; kk++) {
            hilo2(s[2 * kk][0],     s[2 * kk][1],     pfh[kk][0], pfl[kk][0]);
            hilo2(s[2 * kk][2],     s[2 * kk][3],     pfh[kk][1], pfl[kk][1]);
            hilo2(s[2 * kk + 1][0], s[2 * kk + 1][1], pfh[kk][2], pfl[kk][2]);
            hilo2(s[2 * kk + 1][2], s[2 * kk + 1][3], pfh[kk][3], pfl[kk][3]);
        }

        #pragma unroll
        for (int p = 0; p < 3; p++) {
            const uint32_t vb = bb + ((p == 2) ? 24576 : 16384);
            #pragma unroll
            for (int kk = 0; kk < 4; kk++) {
                const uint32_t* pf = (p == 1) ? pfl[kk] : pfh[kk];
                #pragma unroll
                for (int n16 = 0; n16 < 4; n16++) {
                    uint32_t bv[4];
                    uint32_t off = (uint32_t)(kk * 16 + vRow) * 128 + n16 * 32 + vColB;
                    LDMX4T(bv, vb + swz(off));
                    MMA16816(o[2 * n16],     pf, bv[0], bv[1]);
                    MMA16816(o[2 * n16 + 1], pf, bv[2], bv[3]);
                }
            }
        }
    }

    l0 += __shfl_xor_sync(0xffffffffu, l0, 1);
    l0 += __shfl_xor_sync(0xffffffffu, l0, 2);
    l1 += __shfl_xor_sync(0xffffffffu, l1, 1);
    l1 += __shfl_xor_sync(0xffffffffu, l1, 2);
    const float inv0 = 1.0f / l0;
    const float inv1 = 1.0f / l1;

    const size_t gr0 = (size_t)(b * L + q0 + w * 16 + (lane >> 2)) * 1024 + h * 64;
    const size_t gr1 = gr0 + (size_t)8 * 1024;
    #pragma unroll
    for (int t = 0; t < 8; t++) {
        const int cc = t * 8 + (lane & 3) * 2;
        uint32_t hp, lp;
        hilo2(o[t][0] * inv0, o[t][1] * inv0, hp, lp);
        *(uint32_t*)(ath + gr0 + cc) = hp;
        *(uint32_t*)(atl + gr0 + cc) = lp;
        hilo2(o[t][2] * inv1, o[t][3] * inv1, hp, lp);
        *(uint32_t*)(ath + gr1 + cc) = hp;
        *(uint32_t*)(atl + gr1 + cc) = lp;
    }
}

// ---------------------------------------------------------------------------
extern "C" void kernel_launch(void* const* d_in, const int* in_sizes, int n_in,
                              void* d_out, int out_size)
{
    const float* x     = (const float*)d_in[0];
    const float* w_qkv = (const float*)d_in[1];
    const float* w_out = (const float*)d_in[2];
    const float* b_out = (const float*)d_in[3];
    float* out = (float*)d_out;

    __nv_bfloat16 *qh, *ql, *xh, *xl, *ath, *atl, *wqh, *wql, *woh, *wol;
    cudaGetSymbolAddress((void**)&qh,  g_qh);
    cudaGetSymbolAddress((void**)&ql,  g_ql);
    cudaGetSymbolAddress((void**)&xh,  g_xh);
    cudaGetSymbolAddress((void**)&xl,  g_xl);
    cudaGetSymbolAddress((void**)&ath, g_ath);
    cudaGetSymbolAddress((void**)&atl, g_atl);
    cudaGetSymbolAddress((void**)&wqh, g_wqh);
    cudaGetSymbolAddress((void**)&wql, g_wql);
    cudaGetSymbolAddress((void**)&woh, g_woh);
    cudaGetSymbolAddress((void**)&wol, g_wol);

    cudaFuncSetAttribute(gemm_mma, cudaFuncAttributeMaxDynamicSharedMemorySize,
                         GEMM_SMEM);
    cudaFuncSetAttribute(attn_flash, cudaFuncAttributeMaxDynamicSharedMemorySize,
                         ATTN_SMEM);

    split_fp32_planes<<<M_TOK, 256>>>(x, xh, xl, M_TOK);
    split_fp32_planes<<<3 * D, 256>>>(w_qkv, wqh, wql, 3 * D);
    split_fp32_planes<<<D, 256>>>(w_out, woh, wol, D);

    // 1) QKV projection -> bf16 hi/lo planes (N = 3072, K = 1024)
    gemm_mma<<<dim3(3 * D / 128, M_TOK / 128), 128, GEMM_SMEM>>>(
        xh, xl, wqh, wql, nullptr, nullptr, qh, ql, M_TOK, 3 * D, D);

    // 2) Flash attention -> att hi/lo planes
    attn_flash<<<Bsz * H * G * (LG / 64), 128, ATTN_SMEM>>>(qh, ql, ath, atl);

    // 3) Output projection + bias -> fp32 out (K = 1024)
    gemm_mma<<<dim3(D / 128, M_TOK / 128), 128, GEMM_SMEM>>>(
        ath, atl, woh, wol, b_out, out, nullptr, nullptr, M_TOK, D, D);
}

// round 14
// speedup vs baseline: 1.8264x; 1.3424x over previous
#include <cuda_runtime.h>
#include <cuda_fp16.h>
#include <math.h>
#include <stdint.h>

// Problem constants
constexpr int Bsz = 4;
constexpr int L   = 4096;
constexpr int D   = 1024;
constexpr int H   = 16;
constexpr int G   = 8;
constexpr int LG  = L / G;     // 512
constexpr int M_TOK = Bsz * L; // 16384

// Scratch planes (allocation-free: static __device__ globals), all fp16
__device__ __half g_qh [(size_t)M_TOK * 3072];   // qkv hi plane (Q,K,V)
__device__ __half g_ql [(size_t)M_TOK * 1024];   // qkv lo plane (Q only)
__device__ __half g_xh [(size_t)M_TOK * 1024];
__device__ __half g_xl [(size_t)M_TOK * 1024];
__device__ __half g_ath[(size_t)M_TOK * 1024];
__device__ __half g_atl[(size_t)M_TOK * 1024];
__device__ __half g_wqh[(size_t)3072 * 1024];
__device__ __half g_woh[(size_t)1024 * 1024];

// ---------------------------------------------------------------------------
// helpers
// ---------------------------------------------------------------------------
__device__ __forceinline__ uint32_t swz64(uint32_t off) {   // 64B-row swizzle
    return off ^ ((off >> 3) & 0x30);
}
__device__ __forceinline__ uint32_t swz(uint32_t off) {     // 128B-row swizzle
    return off ^ ((off >> 3) & 0x70);
}
__device__ __forceinline__ uint32_t s2u(const void* p) {
    uint32_t a;
    asm("{ .reg .u64 t; cvta.to.shared.u64 t, %1; cvt.u32.u64 %0, t; }"
        : "=r"(a) : "l"(p));
    return a;
}
// fp16 hi/lo split of two floats -> packed hi pair, lo pair
__device__ __forceinline__ void hilo2h(float a, float b, uint32_t& hp, uint32_t& lp) {
    __half ha = __float2half_rn(a);
    __half hb = __float2half_rn(b);
    __half la = __float2half_rn(a - __half2float(ha));
    __half lb = __float2half_rn(b - __half2float(hb));
    hp = (uint32_t)__half_as_ushort(ha) | ((uint32_t)__half_as_ushort(hb) << 16);
    lp = (uint32_t)__half_as_ushort(la) | ((uint32_t)__half_as_ushort(lb) << 16);
}
__device__ __forceinline__ uint32_t h2pack(float a, float b) {
    __half ha = __float2half_rn(a);
    __half hb = __float2half_rn(b);
    return (uint32_t)__half_as_ushort(ha) | ((uint32_t)__half_as_ushort(hb) << 16);
}

// fp16 MMA, fp32 accum. No volatile: pure register op, deps via "+f".
#define MMA16816(acc, a, b0, b1)                                             \
    asm("mma.sync.aligned.m16n8k16.row.col.f32.f16.f16.f32 "                 \
        "{%0,%1,%2,%3}, {%4,%5,%6,%7}, {%8,%9}, {%0,%1,%2,%3};"              \
        : "+f"((acc)[0]), "+f"((acc)[1]), "+f"((acc)[2]), "+f"((acc)[3])     \
        : "r"((a)[0]), "r"((a)[1]), "r"((a)[2]), "r"((a)[3]),                \
          "r"(b0), "r"(b1))

#define LDMX4(r, addr)                                                       \
    asm volatile("ldmatrix.sync.aligned.m8n8.x4.shared.b16 {%0,%1,%2,%3}, [%4];" \
        : "=r"((r)[0]), "=r"((r)[1]), "=r"((r)[2]), "=r"((r)[3]) : "r"(addr))

#define LDMX4T(r, addr)                                                      \
    asm volatile("ldmatrix.sync.aligned.m8n8.x4.trans.shared.b16 {%0,%1,%2,%3}, [%4];" \
        : "=r"((r)[0]), "=r"((r)[1]), "=r"((r)[2]), "=r"((r)[3]) : "r"(addr))

#define CPASYNC16(dst, src)                                                  \
    asm volatile("cp.async.cg.shared.global [%0], [%1], 16;"                 \
        :: "r"(dst), "l"(src))

// ---------------------------------------------------------------------------
// Split fp32 [rows,1024] -> fp16 hi + lo planes.
// ---------------------------------------------------------------------------
__global__ void split_f16_planes(const float* __restrict__ src,
                                 __half* __restrict__ dsth,
                                 __half* __restrict__ dstl,
                                 int rows)
{
    int idx = blockIdx.x * 256 + threadIdx.x;
    if (idx >= rows * 256) return;
    int row = idx >> 8;
    int c4  = (idx & 255) << 2;
    float4 v = *(const float4*)(src + (size_t)row * 1024 + c4);
    uint32_t hp0, lp0, hp1, lp1;
    hilo2h(v.x, v.y, hp0, lp0);
    hilo2h(v.z, v.w, hp1, lp1);
    size_t o = (size_t)row * 1024 + c4;
    *(uint32_t*)(dsth + o)     = hp0; *(uint32_t*)(dsth + o + 2) = hp1;
    *(uint32_t*)(dstl + o)     = lp0; *(uint32_t*)(dstl + o + 2) = lp1;
}

// Convert fp32 [rows,1024] -> fp16 single (hi) plane.
__global__ void conv_f16(const float* __restrict__ src,
                         __half* __restrict__ dst, int rows)
{
    int idx = blockIdx.x * 256 + threadIdx.x;
    if (idx >= rows * 256) return;
    int row = idx >> 8;
    int c4  = (idx & 255) << 2;
    float4 v = *(const float4*)(src + (size_t)row * 1024 + c4);
    size_t o = (size_t)row * 1024 + c4;
    *(uint32_t*)(dst + o)     = h2pack(v.x, v.y);
    *(uint32_t*)(dst + o + 2) = h2pack(v.z, v.w);
}

// ---------------------------------------------------------------------------
// fp16 2-product GEMM: C = Ah*Bh^T + Al*Bh^T  (= A*Bh^T, A-side exact).
// 128x128 CTA tile, 4 warps (64x64 each), 128 threads, BK=32,
// 3 planes per stage (Ah, Al, Bh = 24KB), 3-stage cp.async, 1 sync/chunk.
// Epilogue: fp32 (+bias) to C, or fp16 hi/lo planes to Ch/Cl
// (lo written only for col < lo_ncols).
// ---------------------------------------------------------------------------
constexpr int PL_BYTES = 128 * 64;           // one plane tile: 128 rows x 64B
constexpr int STAGE_BYTES = 3 * PL_BYTES;    // Ah, Al, Bh = 24KB
constexpr int GEMM_SMEM = 3 * STAGE_BYTES;   // 72KB

__global__ __launch_bounds__(128, 2) void gemm_mma(
    const __half* __restrict__ Ah, const __half* __restrict__ Al,
    const __half* __restrict__ Bh,
    const float* __restrict__ bias, float* __restrict__ C,
    __half* __restrict__ Ch, __half* __restrict__ Cl,
    int M, int N, int Kt, int lo_ncols)
{
    extern __shared__ __align__(1024) uint8_t smem[];

    const int tid  = threadIdx.x;
    const int wid  = tid >> 5;
    const int lane = tid & 31;
    const int warp_m = (wid & 1) * 64;
    const int warp_n = (wid >> 1) * 64;
    const size_t bm = (size_t)blockIdx.y * 128;
    const size_t bn = (size_t)blockIdx.x * 128;
    const uint32_t sbase = s2u(smem);

    uint32_t soff[4];
    size_t goff[4];
    #pragma unroll
    for (int i = 0; i < 4; i++) {
        int f = tid + i * 128;
        int row = f >> 2;
        int seg = f & 3;
        soff[i] = swz64((uint32_t)row * 64 + seg * 16);
        goff[i] = (size_t)row * Kt + seg * 8;
    }

    const int NC = Kt / 32;

    auto issue_copy = [&](int c, int stage) {
        const uint32_t ss = sbase + stage * STAGE_BYTES;
        const int ko = c * 32;
        #pragma unroll
        for (int i = 0; i < 4; i++) {
            const size_t ga = bm * Kt + goff[i] + ko;
            const size_t gb = bn * Kt + goff[i] + ko;
            CPASYNC16(ss                + soff[i], Ah + ga);
            CPASYNC16(ss + PL_BYTES     + soff[i], Al + ga);
            CPASYNC16(ss + 2 * PL_BYTES + soff[i], Bh + gb);
        }
        asm volatile("cp.async.commit_group;");
    };

    const int a_row = warp_m + (lane & 15);
    const int a_sub = (lane >> 4) * 16;                     // byte
    const int b_row = warp_n + ((lane >> 4) & 1) * 8 + (lane & 7);
    const int b_sub = ((lane >> 3) & 1) * 16;               // byte

    float acc[4][8][4];
    #pragma unroll
    for (int mt = 0; mt < 4; mt++)
        #pragma unroll
        for (int nt = 0; nt < 8; nt++)
            #pragma unroll
            for (int q = 0; q < 4; q++) acc[mt][nt][q] = 0.f;

    issue_copy(0, 0);
    if (NC > 1) issue_copy(1, 1);

    for (int c = 0; c < NC; c++) {
        if (c + 1 < NC) { asm volatile("cp.async.wait_group 1;"); }
        else            { asm volatile("cp.async.wait_group 0;"); }
        __syncthreads();
        if (c + 2 < NC) issue_copy(c + 2, (c + 2) % 3);

        const uint32_t ss = sbase + (c % 3) * STAGE_BYTES;

        #pragma unroll
        for (int kk = 0; kk < 2; kk++) {
            uint32_t afh[4][4], afl[4][4];
            #pragma unroll
            for (int mt = 0; mt < 4; mt++) {
                uint32_t off = (uint32_t)(a_row + mt * 16) * 64 + kk * 32 + a_sub;
                LDMX4(afh[mt], ss + swz64(off));
                LDMX4(afl[mt], ss + PL_BYTES + swz64(off));
            }
            #pragma unroll
            for (int j = 0; j < 4; j++) {
                uint32_t off = (uint32_t)(b_row + j * 16) * 64 + kk * 32 + b_sub;
                uint32_t rh[4];
                LDMX4(rh, ss + 2 * PL_BYTES + swz64(off));
                // pass 0: Ah*Bh
                #pragma unroll
                for (int mt = 0; mt < 4; mt++) {
                    MMA16816(acc[mt][2 * j],     afh[mt], rh[0], rh[1]);
                    MMA16816(acc[mt][2 * j + 1], afh[mt], rh[2], rh[3]);
                }
                // pass 1: Al*Bh
                #pragma unroll
                for (int mt = 0; mt < 4; mt++) {
                    MMA16816(acc[mt][2 * j],     afl[mt], rh[0], rh[1]);
                    MMA16816(acc[mt][2 * j + 1], afl[mt], rh[2], rh[3]);
                }
            }
        }
    }

    if (Ch) {
        #pragma unroll
        for (int mt = 0; mt < 4; mt++) {
            const size_t row0 = bm + warp_m + mt * 16 + (lane >> 2);
            #pragma unroll
            for (int nt = 0; nt < 8; nt++) {
                const size_t col = bn + warp_n + nt * 8 + (lane & 3) * 2;
                uint32_t hp, lp;
                hilo2h(acc[mt][nt][0], acc[mt][nt][1], hp, lp);
                *(uint32_t*)(Ch + row0 * (size_t)N + col) = hp;
                if ((int)col < lo_ncols)
                    *(uint32_t*)(Cl + row0 * (size_t)1024 + col) = lp;
                hilo2h(acc[mt][nt][2], acc[mt][nt][3], hp, lp);
                *(uint32_t*)(Ch + (row0 + 8) * (size_t)N + col) = hp;
                if ((int)col < lo_ncols)
                    *(uint32_t*)(Cl + (row0 + 8) * (size_t)1024 + col) = lp;
            }
        }
    } else {
        #pragma unroll
        for (int mt = 0; mt < 4; mt++) {
            const size_t row0 = bm + warp_m + mt * 16 + (lane >> 2);
            #pragma unroll
            for (int nt = 0; nt < 8; nt++) {
                const size_t col = bn + warp_n + nt * 8 + (lane & 3) * 2;
                float bx = bias[col], by = bias[col + 1];
                float2 v0 = {acc[mt][nt][0] + bx, acc[mt][nt][1] + by};
                float2 v1 = {acc[mt][nt][2] + bx, acc[mt][nt][3] + by};
                *(float2*)(C + row0 * (size_t)N + col)       = v0;
                *(float2*)(C + (row0 + 8) * (size_t)N + col) = v1;
            }
        }
    }
}

// ---------------------------------------------------------------------------
// Flash attention, fp16 2-product: S = Qh*Kh + Ql*Kh ; O = Ph*Vh + Pl*Vh.
// K/V need hi planes only (traffic halved). CTA = 64 q x 512-key block,
// 4 warps (m16 each), per-warp online softmax, 8 chunks of 64 keys,
// double-buffered cp.async, P in registers. Writes fp16 hi/lo planes.
// ---------------------------------------------------------------------------
constexpr int sAQH = 0;         // Q hi: 64 x 128B (swizzled)
constexpr int sAQL = 8192;      // Q lo
constexpr int sBUF0 = 16384;    // per buffer: Kh 8KB + Vh 8KB
constexpr int sBUFSZ = 16384;
constexpr int ATTN_SMEM = 16384 + 2 * sBUFSZ;   // 48KB

__global__ __launch_bounds__(128) void attn_flash(const __half* __restrict__ qh,
                                                  const __half* __restrict__ ql,
                                                  __half* __restrict__ ath,
                                                  __half* __restrict__ atl)
{
    extern __shared__ __align__(1024) char smc[];
    const uint32_t sbs = s2u(smc);

    const int tid  = threadIdx.x;
    const int lane = tid & 31;
    const int w    = tid >> 5;

    const int idx = blockIdx.x;
    const int qt = idx & 7;
    const int g  = (idx >> 3) & 7;
    const int h  = (idx >> 6) & 15;
    const int b  = idx >> 10;
    const int pos0 = g * LG;
    const int q0   = pos0 + qt * 64;

    const int lrow = tid >> 3;
    const int lseg = tid & 7;
    uint32_t soff[4];
    #pragma unroll
    for (int i = 0; i < 4; i++)
        soff[i] = swz((uint32_t)(lrow + i * 16) * 128 + lseg * 16);

    // Q fill (hi from qh plane, lo from ql plane — both stride 1024/3072)
    #pragma unroll
    for (int i = 0; i < 4; i++) {
        const size_t qoh = (size_t)(b * L + q0 + lrow + i * 16) * 3072 + h * 64 + lseg * 8;
        const size_t qol = (size_t)(b * L + q0 + lrow + i * 16) * 1024 + h * 64 + lseg * 8;
        CPASYNC16(sbs + sAQH + soff[i], qh + qoh);
        CPASYNC16(sbs + sAQL + soff[i], ql + qol);
    }

    auto issue_chunk = [&](int c, int buf) {
        const uint32_t bb = sbs + sBUF0 + buf * sBUFSZ;
        #pragma unroll
        for (int i = 0; i < 4; i++) {
            const size_t ko = (size_t)(b * L + pos0 + c * 64 + lrow + i * 16) * 3072
                              + 1024 + h * 64 + lseg * 8;
            CPASYNC16(bb        + soff[i], qh + ko);          // K hi
            CPASYNC16(bb + 8192 + soff[i], qh + ko + 1024);   // V hi
        }
        asm volatile("cp.async.commit_group;");
    };
    issue_chunk(0, 0);

    const int kRow  = ((lane >> 4) & 1) * 8 + (lane & 7);
    const int kSub  = ((lane >> 3) & 1) * 16;
    const int vRow  = (lane & 7) + ((lane >> 3) & 1) * 8;
    const int vColB = (lane >> 4) * 16;

    uint32_t qf[2][4][4];
    float o[8][4];
    #pragma unroll
    for (int t = 0; t < 8; t++)
        #pragma unroll
        for (int j = 0; j < 4; j++) o[t][j] = 0.f;
    float m0 = -1e30f, m1 = -1e30f, l0 = 0.f, l1 = 0.f;
    const float scale = 0.125f;

    for (int c = 0; c < 8; c++) {
        asm volatile("cp.async.wait_group 0;");
        __syncthreads();
        if (c + 1 < 8) issue_chunk(c + 1, (c + 1) & 1);
        if (c == 0) {
            #pragma unroll
            for (int pl = 0; pl < 2; pl++) {
                const uint32_t qb = sbs + (pl ? sAQL : sAQH);
                #pragma unroll
                for (int kk = 0; kk < 4; kk++) {
                    uint32_t off = (uint32_t)(w * 16 + (lane & 15)) * 128 + kk * 32 + (lane >> 4) * 16;
                    LDMX4(qf[pl][kk], qb + swz(off));
                }
            }
        }

        const uint32_t bb = sbs + sBUF0 + (c & 1) * sBUFSZ;

        // S = Q*Kh (2 passes: Qh, Ql)
        float s[8][4];
        #pragma unroll
        for (int t = 0; t < 8; t++)
            #pragma unroll
            for (int j = 0; j < 4; j++) s[t][j] = 0.f;

        #pragma unroll
        for (int p = 0; p < 2; p++) {
            #pragma unroll
            for (int kk = 0; kk < 4; kk++) {
                #pragma unroll
                for (int n16 = 0; n16 < 4; n16++) {
                    uint32_t bq[4];
                    uint32_t off = (uint32_t)(n16 * 16 + kRow) * 128 + kk * 32 + kSub;
                    LDMX4(bq, bb + swz(off));
                    MMA16816(s[2 * n16],     qf[p][kk], bq[0], bq[1]);
                    MMA16816(s[2 * n16 + 1], qf[p][kk], bq[2], bq[3]);
                }
            }
        }

        // online softmax update
        float cm0 = -1e30f, cm1 = -1e30f;
        #pragma unroll
        for (int t = 0; t < 8; t++) {
            cm0 = fmaxf(cm0, fmaxf(s[t][0], s[t][1]));
            cm1 = fmaxf(cm1, fmaxf(s[t][2], s[t][3]));
        }
        cm0 *= scale; cm1 *= scale;
        cm0 = fmaxf(cm0, __shfl_xor_sync(0xffffffffu, cm0, 1));
        cm0 = fmaxf(cm0, __shfl_xor_sync(0xffffffffu, cm0, 2));
        cm1 = fmaxf(cm1, __shfl_xor_sync(0xffffffffu, cm1, 1));
        cm1 = fmaxf(cm1, __shfl_xor_sync(0xffffffffu, cm1, 2));
        const float mn0 = fmaxf(m0, cm0);
        const float mn1 = fmaxf(m1, cm1);
        const float al0 = __expf(m0 - mn0);
        const float al1 = __expf(m1 - mn1);
        m0 = mn0; m1 = mn1;

        float ls0 = 0.f, ls1 = 0.f;
        #pragma unroll
        for (int t = 0; t < 8; t++) {
            float p0 = __expf(s[t][0] * scale - mn0);
            float p1 = __expf(s[t][1] * scale - mn0);
            float p2 = __expf(s[t][2] * scale - mn1);
            float p3 = __expf(s[t][3] * scale - mn1);
            s[t][0] = p0; s[t][1] = p1; s[t][2] = p2; s[t][3] = p3;
            ls0 += p0 + p1; ls1 += p2 + p3;
        }
        l0 = l0 * al0 + ls0;
        l1 = l1 * al1 + ls1;
        #pragma unroll
        for (int t = 0; t < 8; t++) {
            o[t][0] *= al0; o[t][1] *= al0;
            o[t][2] *= al1; o[t][3] *= al1;
        }

        // P -> fp16 hi/lo A-fragments (registers)
        uint32_t pfh[4][4], pfl[4][4];
        #pragma unroll
        for (int kk = 0; kk < 4; kk++) {
            hilo2h(s[2 * kk][0],     s[2 * kk][1],     pfh[kk][0], pfl[kk][0]);
            hilo2h(s[2 * kk][2],     s[2 * kk][3],     pfh[kk][1], pfl[kk][1]);
            hilo2h(s[2 * kk + 1][0], s[2 * kk + 1][1], pfh[kk][2], pfl[kk][2]);
            hilo2h(s[2 * kk + 1][2], s[2 * kk + 1][3], pfh[kk][3], pfl[kk][3]);
        }

        // O += P*Vh (2 passes: Ph, Pl)
        const uint32_t vb = bb + 8192;
        #pragma unroll
        for (int p = 0; p < 2; p++) {
            #pragma unroll
            for (int kk = 0; kk < 4; kk++) {
                const uint32_t* pf = p ? pfl[kk] : pfh[kk];
                #pragma unroll
                for (int n16 = 0; n16 < 4; n16++) {
                    uint32_t bv[4];
                    uint32_t off = (uint32_t)(kk * 16 + vRow) * 128 + n16 * 32 + vColB;
                    LDMX4T(bv, vb + swz(off));
                    MMA16816(o[2 * n16],     pf, bv[0], bv[1]);
                    MMA16816(o[2 * n16 + 1], pf, bv[2], bv[3]);
                }
            }
        }
    }

    l0 += __shfl_xor_sync(0xffffffffu, l0, 1);
    l0 += __shfl_xor_sync(0xffffffffu, l0, 2);
    l1 += __shfl_xor_sync(0xffffffffu, l1, 1);
    l1 += __shfl_xor_sync(0xffffffffu, l1, 2);
    const float inv0 = 1.0f / l0;
    const float inv1 = 1.0f / l1;

    const size_t gr0 = (size_t)(b * L + q0 + w * 16 + (lane >> 2)) * 1024 + h * 64;
    const size_t gr1 = gr0 + (size_t)8 * 1024;
    #pragma unroll
    for (int t = 0; t < 8; t++) {
        const int cc = t * 8 + (lane & 3) * 2;
        uint32_t hp, lp;
        hilo2h(o[t][0] * inv0, o[t][1] * inv0, hp, lp);
        *(uint32_t*)(ath + gr0 + cc) = hp;
        *(uint32_t*)(atl + gr0 + cc) = lp;
        hilo2h(o[t][2] * inv1, o[t][3] * inv1, hp, lp);
        *(uint32_t*)(ath + gr1 + cc) = hp;
        *(uint32_t*)(atl + gr1 + cc) = lp;
    }
}

// ---------------------------------------------------------------------------
extern "C" void kernel_launch(void* const* d_in, const int* in_sizes, int n_in,
                              void* d_out, int out_size)
{
    const float* x     = (const float*)d_in[0];
    const float* w_qkv = (const float*)d_in[1];
    const float* w_out = (const float*)d_in[2];
    const float* b_out = (const float*)d_in[3];
    float* out = (float*)d_out;

    __half *qh, *ql, *xh, *xl, *ath, *atl, *wqh, *woh;
    cudaGetSymbolAddress((void**)&qh,  g_qh);
    cudaGetSymbolAddress((void**)&ql,  g_ql);
    cudaGetSymbolAddress((void**)&xh,  g_xh);
    cudaGetSymbolAddress((void**)&xl,  g_xl);
    cudaGetSymbolAddress((void**)&ath, g_ath);
    cudaGetSymbolAddress((void**)&atl, g_atl);
    cudaGetSymbolAddress((void**)&wqh, g_wqh);
    cudaGetSymbolAddress((void**)&woh, g_woh);

    cudaFuncSetAttribute(gemm_mma, cudaFuncAttributeMaxDynamicSharedMemorySize,
                         GEMM_SMEM);
    cudaFuncSetAttribute(attn_flash, cudaFuncAttributeMaxDynamicSharedMemorySize,
                         ATTN_SMEM);

    // A-side splits (hi+lo) and B-side converts (hi only)
    split_f16_planes<<<M_TOK, 256>>>(x, xh, xl, M_TOK);
    conv_f16<<<3 * D, 256>>>(w_qkv, wqh, 3 * D);
    conv_f16<<<D, 256>>>(w_out, woh, D);

    // 1) QKV projection -> qkv hi plane [M,3072], Q lo plane [M,1024]
    gemm_mma<<<dim3(3 * D / 128, M_TOK / 128), 128, GEMM_SMEM>>>(
        xh, xl, wqh, nullptr, nullptr, qh, ql, M_TOK, 3 * D, D, 1024);

    // 2) Flash attention -> att hi/lo fp16 planes
    attn_flash<<<Bsz * H * G * (LG / 64), 128, ATTN_SMEM>>>(qh, ql, ath, atl);

    // 3) Output projection + bias -> fp32 out
    gemm_mma<<<dim3(D / 128, M_TOK / 128), 128, GEMM_SMEM>>>(
        ath, atl, woh, b_out, out, nullptr, nullptr, M_TOK, D, D, 0);
}

// round 15
// speedup vs baseline: 1.9385x; 1.0614x over previous
#include <cuda_runtime.h>
#include <cuda_fp16.h>
#include <math.h>
#include <stdint.h>

// Problem constants
constexpr int Bsz = 4;
constexpr int L   = 4096;
constexpr int D   = 1024;
constexpr int H   = 16;
constexpr int G   = 8;
constexpr int LG  = L / G;     // 512
constexpr int M_TOK = Bsz * L; // 16384

// Scratch planes (allocation-free: static __device__ globals), all fp16
__device__ __half g_qh [(size_t)M_TOK * 3072];   // qkv hi plane (Q,K,V)
__device__ __half g_ql [(size_t)M_TOK * 1024];   // qkv lo plane (Q only)
__device__ __half g_xh [(size_t)M_TOK * 1024];
__device__ __half g_xl [(size_t)M_TOK * 1024];
__device__ __half g_ath[(size_t)M_TOK * 1024];
__device__ __half g_atl[(size_t)M_TOK * 1024];
__device__ __half g_wqh[(size_t)3072 * 1024];
__device__ __half g_woh[(size_t)1024 * 1024];

// ---------------------------------------------------------------------------
// helpers
// ---------------------------------------------------------------------------
__device__ __forceinline__ uint32_t swz64(uint32_t off) {   // 64B-row swizzle
    return off ^ ((off >> 3) & 0x30);
}
__device__ __forceinline__ uint32_t swz(uint32_t off) {     // 128B-row swizzle
    return off ^ ((off >> 3) & 0x70);
}
__device__ __forceinline__ uint32_t s2u(const void* p) {
    uint32_t a;
    asm("{ .reg .u64 t; cvta.to.shared.u64 t, %1; cvt.u32.u64 %0, t; }"
        : "=r"(a) : "l"(p));
    return a;
}
// fp16 hi/lo split of two floats -> packed hi pair, lo pair
__device__ __forceinline__ void hilo2h(float a, float b, uint32_t& hp, uint32_t& lp) {
    __half ha = __float2half_rn(a);
    __half hb = __float2half_rn(b);
    __half la = __float2half_rn(a - __half2float(ha));
    __half lb = __float2half_rn(b - __half2float(hb));
    hp = (uint32_t)__half_as_ushort(ha) | ((uint32_t)__half_as_ushort(hb) << 16);
    lp = (uint32_t)__half_as_ushort(la) | ((uint32_t)__half_as_ushort(lb) << 16);
}
__device__ __forceinline__ uint32_t h2pack(float a, float b) {
    __half ha = __float2half_rn(a);
    __half hb = __float2half_rn(b);
    return (uint32_t)__half_as_ushort(ha) | ((uint32_t)__half_as_ushort(hb) << 16);
}

// fp16 MMA, fp32 accum. No volatile: pure register op, deps via "+f".
#define MMA16816(acc, a, b0, b1)                                             \
    asm("mma.sync.aligned.m16n8k16.row.col.f32.f16.f16.f32 "                 \
        "{%0,%1,%2,%3}, {%4,%5,%6,%7}, {%8,%9}, {%0,%1,%2,%3};"              \
        : "+f"((acc)[0]), "+f"((acc)[1]), "+f"((acc)[2]), "+f"((acc)[3])     \
        : "r"((a)[0]), "r"((a)[1]), "r"((a)[2]), "r"((a)[3]),                \
          "r"(b0), "r"(b1))

#define LDMX4(r, addr)                                                       \
    asm volatile("ldmatrix.sync.aligned.m8n8.x4.shared.b16 {%0,%1,%2,%3}, [%4];" \
        : "=r"((r)[0]), "=r"((r)[1]), "=r"((r)[2]), "=r"((r)[3]) : "r"(addr))

#define LDMX4T(r, addr)                                                      \
    asm volatile("ldmatrix.sync.aligned.m8n8.x4.trans.shared.b16 {%0,%1,%2,%3}, [%4];" \
        : "=r"((r)[0]), "=r"((r)[1]), "=r"((r)[2]), "=r"((r)[3]) : "r"(addr))

#define CPASYNC16(dst, src)                                                  \
    asm volatile("cp.async.cg.shared.global [%0], [%1], 16;"                 \
        :: "r"(dst), "l"(src))

// ---------------------------------------------------------------------------
// Split fp32 [rows,1024] -> fp16 hi + lo planes.
// ---------------------------------------------------------------------------
__global__ void split_f16_planes(const float* __restrict__ src,
                                 __half* __restrict__ dsth,
                                 __half* __restrict__ dstl,
                                 int rows)
{
    int idx = blockIdx.x * 256 + threadIdx.x;
    if (idx >= rows * 256) return;
    int row = idx >> 8;
    int c4  = (idx & 255) << 2;
    float4 v = *(const float4*)(src + (size_t)row * 1024 + c4);
    uint32_t hp0, lp0, hp1, lp1;
    hilo2h(v.x, v.y, hp0, lp0);
    hilo2h(v.z, v.w, hp1, lp1);
    size_t o = (size_t)row * 1024 + c4;
    *(uint32_t*)(dsth + o)     = hp0; *(uint32_t*)(dsth + o + 2) = hp1;
    *(uint32_t*)(dstl + o)     = lp0; *(uint32_t*)(dstl + o + 2) = lp1;
}

// Convert fp32 [rows,1024] -> fp16 single (hi) plane.
__global__ void conv_f16(const float* __restrict__ src,
                         __half* __restrict__ dst, int rows)
{
    int idx = blockIdx.x * 256 + threadIdx.x;
    if (idx >= rows * 256) return;
    int row = idx >> 8;
    int c4  = (idx & 255) << 2;
    float4 v = *(const float4*)(src + (size_t)row * 1024 + c4);
    size_t o = (size_t)row * 1024 + c4;
    *(uint32_t*)(dst + o)     = h2pack(v.x, v.y);
    *(uint32_t*)(dst + o + 2) = h2pack(v.z, v.w);
}

// ---------------------------------------------------------------------------
// fp16 GEMM: C = (Ah + Al)*Bh^T on N-tiles with bn < q_cols (2 products),
//            C = Ah*Bh^T elsewhere (1 product — output rounded to fp16 anyway).
// 128x128 CTA tile, 4 warps (64x64 each), 128 threads, BK=32,
// 3-stage cp.async, 1 sync/chunk. Epilogue: fp32 (+bias) to C, or fp16
// hi/lo planes to Ch/Cl (lo written only for col < lo_ncols).
// ---------------------------------------------------------------------------
constexpr int PL_BYTES = 128 * 64;           // one plane tile: 128 rows x 64B
constexpr int STAGE_BYTES = 3 * PL_BYTES;    // Ah, Al, Bh = 24KB
constexpr int GEMM_SMEM = 3 * STAGE_BYTES;   // 72KB

__global__ __launch_bounds__(128, 2) void gemm_mma(
    const __half* __restrict__ Ah, const __half* __restrict__ Al,
    const __half* __restrict__ Bh,
    const float* __restrict__ bias, float* __restrict__ C,
    __half* __restrict__ Ch, __half* __restrict__ Cl,
    int M, int N, int Kt, int lo_ncols, int q_cols)
{
    extern __shared__ __align__(1024) uint8_t smem[];

    const int tid  = threadIdx.x;
    const int wid  = tid >> 5;
    const int lane = tid & 31;
    const int warp_m = (wid & 1) * 64;
    const int warp_n = (wid >> 1) * 64;
    const size_t bm = (size_t)blockIdx.y * 128;
    const size_t bn = (size_t)blockIdx.x * 128;
    const uint32_t sbase = s2u(smem);
    const bool aLo = ((int)bn < q_cols);   // tile needs the Al product?

    uint32_t soff[4];
    size_t goff[4];
    #pragma unroll
    for (int i = 0; i < 4; i++) {
        int f = tid + i * 128;
        int row = f >> 2;
        int seg = f & 3;
        soff[i] = swz64((uint32_t)row * 64 + seg * 16);
        goff[i] = (size_t)row * Kt + seg * 8;
    }

    const int NC = Kt / 32;

    auto issue_copy = [&](int c, int stage) {
        const uint32_t ss = sbase + stage * STAGE_BYTES;
        const int ko = c * 32;
        #pragma unroll
        for (int i = 0; i < 4; i++) {
            const size_t ga = bm * Kt + goff[i] + ko;
            const size_t gb = bn * Kt + goff[i] + ko;
            CPASYNC16(ss                + soff[i], Ah + ga);
            if (aLo) CPASYNC16(ss + PL_BYTES + soff[i], Al + ga);
            CPASYNC16(ss + 2 * PL_BYTES + soff[i], Bh + gb);
        }
        asm volatile("cp.async.commit_group;");
    };

    const int a_row = warp_m + (lane & 15);
    const int a_sub = (lane >> 4) * 16;                     // byte
    const int b_row = warp_n + ((lane >> 4) & 1) * 8 + (lane & 7);
    const int b_sub = ((lane >> 3) & 1) * 16;               // byte

    float acc[4][8][4];
    #pragma unroll
    for (int mt = 0; mt < 4; mt++)
        #pragma unroll
        for (int nt = 0; nt < 8; nt++)
            #pragma unroll
            for (int q = 0; q < 4; q++) acc[mt][nt][q] = 0.f;

    issue_copy(0, 0);
    if (NC > 1) issue_copy(1, 1);

    for (int c = 0; c < NC; c++) {
        if (c + 1 < NC) { asm volatile("cp.async.wait_group 1;"); }
        else            { asm volatile("cp.async.wait_group 0;"); }
        __syncthreads();
        if (c + 2 < NC) issue_copy(c + 2, (c + 2) % 3);

        const uint32_t ss = sbase + (c % 3) * STAGE_BYTES;

        #pragma unroll
        for (int kk = 0; kk < 2; kk++) {
            uint32_t afh[4][4], afl[4][4];
            #pragma unroll
            for (int mt = 0; mt < 4; mt++) {
                uint32_t off = (uint32_t)(a_row + mt * 16) * 64 + kk * 32 + a_sub;
                LDMX4(afh[mt], ss + swz64(off));
                if (aLo) LDMX4(afl[mt], ss + PL_BYTES + swz64(off));
            }
            #pragma unroll
            for (int j = 0; j < 4; j++) {
                uint32_t off = (uint32_t)(b_row + j * 16) * 64 + kk * 32 + b_sub;
                uint32_t rh[4];
                LDMX4(rh, ss + 2 * PL_BYTES + swz64(off));
                // pass 0: Ah*Bh
                #pragma unroll
                for (int mt = 0; mt < 4; mt++) {
                    MMA16816(acc[mt][2 * j],     afh[mt], rh[0], rh[1]);
                    MMA16816(acc[mt][2 * j + 1], afh[mt], rh[2], rh[3]);
                }
                // pass 1: Al*Bh (only where the lo term matters)
                if (aLo) {
                    #pragma unroll
                    for (int mt = 0; mt < 4; mt++) {
                        MMA16816(acc[mt][2 * j],     afl[mt], rh[0], rh[1]);
                        MMA16816(acc[mt][2 * j + 1], afl[mt], rh[2], rh[3]);
                    }
                }
            }
        }
    }

    if (Ch) {
        #pragma unroll
        for (int mt = 0; mt < 4; mt++) {
            const size_t row0 = bm + warp_m + mt * 16 + (lane >> 2);
            #pragma unroll
            for (int nt = 0; nt < 8; nt++) {
                const size_t col = bn + warp_n + nt * 8 + (lane & 3) * 2;
                uint32_t hp, lp;
                hilo2h(acc[mt][nt][0], acc[mt][nt][1], hp, lp);
                *(uint32_t*)(Ch + row0 * (size_t)N + col) = hp;
                if ((int)col < lo_ncols)
                    *(uint32_t*)(Cl + row0 * (size_t)1024 + col) = lp;
                hilo2h(acc[mt][nt][2], acc[mt][nt][3], hp, lp);
                *(uint32_t*)(Ch + (row0 + 8) * (size_t)N + col) = hp;
                if ((int)col < lo_ncols)
                    *(uint32_t*)(Cl + (row0 + 8) * (size_t)1024 + col) = lp;
            }
        }
    } else {
        #pragma unroll
        for (int mt = 0; mt < 4; mt++) {
            const size_t row0 = bm + warp_m + mt * 16 + (lane >> 2);
            #pragma unroll
            for (int nt = 0; nt < 8; nt++) {
                const size_t col = bn + warp_n + nt * 8 + (lane & 3) * 2;
                float bx = bias[col], by = bias[col + 1];
                float2 v0 = {acc[mt][nt][0] + bx, acc[mt][nt][1] + by};
                float2 v1 = {acc[mt][nt][2] + bx, acc[mt][nt][3] + by};
                *(float2*)(C + row0 * (size_t)N + col)       = v0;
                *(float2*)(C + (row0 + 8) * (size_t)N + col) = v1;
            }
        }
    }
}

// ---------------------------------------------------------------------------
// Flash attention, fp16 2-product: S = Qh*Kh + Ql*Kh ; O = Ph*Vh + Pl*Vh.
// K/V need hi planes only. CTA = 64 q x 512-key block, 4 warps (m16 each),
// per-warp online softmax, 8 chunks of 64 keys, double-buffered cp.async,
// P in registers. Writes fp16 hi/lo planes.
// ---------------------------------------------------------------------------
constexpr int sAQH = 0;         // Q hi: 64 x 128B (swizzled)
constexpr int sAQL = 8192;      // Q lo
constexpr int sBUF0 = 16384;    // per buffer: Kh 8KB + Vh 8KB
constexpr int sBUFSZ = 16384;
constexpr int ATTN_SMEM = 16384 + 2 * sBUFSZ;   // 48KB

__global__ __launch_bounds__(128) void attn_flash(const __half* __restrict__ qh,
                                                  const __half* __restrict__ ql,
                                                  __half* __restrict__ ath,
                                                  __half* __restrict__ atl)
{
    extern __shared__ __align__(1024) char smc[];
    const uint32_t sbs = s2u(smc);

    const int tid  = threadIdx.x;
    const int lane = tid & 31;
    const int w    = tid >> 5;

    const int idx = blockIdx.x;
    const int qt = idx & 7;
    const int g  = (idx >> 3) & 7;
    const int h  = (idx >> 6) & 15;
    const int b  = idx >> 10;
    const int pos0 = g * LG;
    const int q0   = pos0 + qt * 64;

    const int lrow = tid >> 3;
    const int lseg = tid & 7;
    uint32_t soff[4];
    #pragma unroll
    for (int i = 0; i < 4; i++)
        soff[i] = swz((uint32_t)(lrow + i * 16) * 128 + lseg * 16);

    // Q fill (hi from qh plane stride 3072, lo from ql plane stride 1024)
    #pragma unroll
    for (int i = 0; i < 4; i++) {
        const size_t qoh = (size_t)(b * L + q0 + lrow + i * 16) * 3072 + h * 64 + lseg * 8;
        const size_t qol = (size_t)(b * L + q0 + lrow + i * 16) * 1024 + h * 64 + lseg * 8;
        CPASYNC16(sbs + sAQH + soff[i], qh + qoh);
        CPASYNC16(sbs + sAQL + soff[i], ql + qol);
    }

    auto issue_chunk = [&](int c, int buf) {
        const uint32_t bb = sbs + sBUF0 + buf * sBUFSZ;
        #pragma unroll
        for (int i = 0; i < 4; i++) {
            const size_t ko = (size_t)(b * L + pos0 + c * 64 + lrow + i * 16) * 3072
                              + 1024 + h * 64 + lseg * 8;
            CPASYNC16(bb        + soff[i], qh + ko);          // K hi
            CPASYNC16(bb + 8192 + soff[i], qh + ko + 1024);   // V hi
        }
        asm volatile("cp.async.commit_group;");
    };
    issue_chunk(0, 0);

    const int kRow  = ((lane >> 4) & 1) * 8 + (lane & 7);
    const int kSub  = ((lane >> 3) & 1) * 16;
    const int vRow  = (lane & 7) + ((lane >> 3) & 1) * 8;
    const int vColB = (lane >> 4) * 16;

    uint32_t qf[2][4][4];
    float o[8][4];
    #pragma unroll
    for (int t = 0; t < 8; t++)
        #pragma unroll
        for (int j = 0; j < 4; j++) o[t][j] = 0.f;
    float m0 = -1e30f, m1 = -1e30f, l0 = 0.f, l1 = 0.f;
    const float scale = 0.125f;

    for (int c = 0; c < 8; c++) {
        asm volatile("cp.async.wait_group 0;");
        __syncthreads();
        if (c + 1 < 8) issue_chunk(c + 1, (c + 1) & 1);
        if (c == 0) {
            #pragma unroll
            for (int pl = 0; pl < 2; pl++) {
                const uint32_t qb = sbs + (pl ? sAQL : sAQH);
                #pragma unroll
                for (int kk = 0; kk < 4; kk++) {
                    uint32_t off = (uint32_t)(w * 16 + (lane & 15)) * 128 + kk * 32 + (lane >> 4) * 16;
                    LDMX4(qf[pl][kk], qb + swz(off));
                }
            }
        }

        const uint32_t bb = sbs + sBUF0 + (c & 1) * sBUFSZ;

        // S = Q*Kh (2 passes: Qh, Ql)
        float s[8][4];
        #pragma unroll
        for (int t = 0; t < 8; t++)
            #pragma unroll
            for (int j = 0; j < 4; j++) s[t][j] = 0.f;

        #pragma unroll
        for (int p = 0; p < 2; p++) {
            #pragma unroll
            for (int kk = 0; kk < 4; kk++) {
                #pragma unroll
                for (int n16 = 0; n16 < 4; n16++) {
                    uint32_t bq[4];
                    uint32_t off = (uint32_t)(n16 * 16 + kRow) * 128 + kk * 32 + kSub;
                    LDMX4(bq, bb + swz(off));
                    MMA16816(s[2 * n16],     qf[p][kk], bq[0], bq[1]);
                    MMA16816(s[2 * n16 + 1], qf[p][kk], bq[2], bq[3]);
                }
            }
        }

        // online softmax update
        float cm0 = -1e30f, cm1 = -1e30f;
        #pragma unroll
        for (int t = 0; t < 8; t++) {
            cm0 = fmaxf(cm0, fmaxf(s[t][0], s[t][1]));
            cm1 = fmaxf(cm1, fmaxf(s[t][2], s[t][3]));
        }
        cm0 *= scale; cm1 *= scale;
        cm0 = fmaxf(cm0, __shfl_xor_sync(0xffffffffu, cm0, 1));
        cm0 = fmaxf(cm0, __shfl_xor_sync(0xffffffffu, cm0, 2));
        cm1 = fmaxf(cm1, __shfl_xor_sync(0xffffffffu, cm1, 1));
        cm1 = fmaxf(cm1, __shfl_xor_sync(0xffffffffu, cm1, 2));
        const float mn0 = fmaxf(m0, cm0);
        const float mn1 = fmaxf(m1, cm1);
        const float al0 = __expf(m0 - mn0);
        const float al1 = __expf(m1 - mn1);
        m0 = mn0; m1 = mn1;

        float ls0 = 0.f, ls1 = 0.f;
        #pragma unroll
        for (int t = 0; t < 8; t++) {
            float p0 = __expf(s[t][0] * scale - mn0);
            float p1 = __expf(s[t][1] * scale - mn0);
            float p2 = __expf(s[t][2] * scale - mn1);
            float p3 = __expf(s[t][3] * scale - mn1);
            s[t][0] = p0; s[t][1] = p1; s[t][2] = p2; s[t][3] = p3;
            ls0 += p0 + p1; ls1 += p2 + p3;
        }
        l0 = l0 * al0 + ls0;
        l1 = l1 * al1 + ls1;
        #pragma unroll
        for (int t = 0; t < 8; t++) {
            o[t][0] *= al0; o[t][1] *= al0;
            o[t][2] *= al1; o[t][3] *= al1;
        }

        // P -> fp16 hi/lo A-fragments (registers)
        uint32_t pfh[4][4], pfl[4][4];
        #pragma unroll
        for (int kk = 0; kk < 4; kk++) {
            hilo2h(s[2 * kk][0],     s[2 * kk][1],     pfh[kk][0], pfl[kk][0]);
            hilo2h(s[2 * kk][2],     s[2 * kk][3],     pfh[kk][1], pfl[kk][1]);
            hilo2h(s[2 * kk + 1][0], s[2 * kk + 1][1], pfh[kk][2], pfl[kk][2]);
            hilo2h(s[2 * kk + 1][2], s[2 * kk + 1][3], pfh[kk][3], pfl[kk][3]);
        }

        // O += P*Vh (2 passes: Ph, Pl)
        const uint32_t vb = bb + 8192;
        #pragma unroll
        for (int p = 0; p < 2; p++) {
            #pragma unroll
            for (int kk = 0; kk < 4; kk++) {
                const uint32_t* pf = p ? pfl[kk] : pfh[kk];
                #pragma unroll
                for (int n16 = 0; n16 < 4; n16++) {
                    uint32_t bv[4];
                    uint32_t off = (uint32_t)(kk * 16 + vRow) * 128 + n16 * 32 + vColB;
                    LDMX4T(bv, vb + swz(off));
                    MMA16816(o[2 * n16],     pf, bv[0], bv[1]);
                    MMA16816(o[2 * n16 + 1], pf, bv[2], bv[3]);
                }
            }
        }
    }

    l0 += __shfl_xor_sync(0xffffffffu, l0, 1);
    l0 += __shfl_xor_sync(0xffffffffu, l0, 2);
    l1 += __shfl_xor_sync(0xffffffffu, l1, 1);
    l1 += __shfl_xor_sync(0xffffffffu, l1, 2);
    const float inv0 = 1.0f / l0;
    const float inv1 = 1.0f / l1;

    const size_t gr0 = (size_t)(b * L + q0 + w * 16 + (lane >> 2)) * 1024 + h * 64;
    const size_t gr1 = gr0 + (size_t)8 * 1024;
    #pragma unroll
    for (int t = 0; t < 8; t++) {
        const int cc = t * 8 + (lane & 3) * 2;
        uint32_t hp, lp;
        hilo2h(o[t][0] * inv0, o[t][1] * inv0, hp, lp);
        *(uint32_t*)(ath + gr0 + cc) = hp;
        *(uint32_t*)(atl + gr0 + cc) = lp;
        hilo2h(o[t][2] * inv1, o[t][3] * inv1, hp, lp);
        *(uint32_t*)(ath + gr1 + cc) = hp;
        *(uint32_t*)(atl + gr1 + cc) = lp;
    }
}

// ---------------------------------------------------------------------------
extern "C" void kernel_launch(void* const* d_in, const int* in_sizes, int n_in,
                              void* d_out, int out_size)
{
    const float* x     = (const float*)d_in[0];
    const float* w_qkv = (const float*)d_in[1];
    const float* w_out = (const float*)d_in[2];
    const float* b_out = (const float*)d_in[3];
    float* out = (float*)d_out;

    __half *qh, *ql, *xh, *xl, *ath, *atl, *wqh, *woh;
    cudaGetSymbolAddress((void**)&qh,  g_qh);
    cudaGetSymbolAddress((void**)&ql,  g_ql);
    cudaGetSymbolAddress((void**)&xh,  g_xh);
    cudaGetSymbolAddress((void**)&xl,  g_xl);
    cudaGetSymbolAddress((void**)&ath, g_ath);
    cudaGetSymbolAddress((void**)&atl, g_atl);
    cudaGetSymbolAddress((void**)&wqh, g_wqh);
    cudaGetSymbolAddress((void**)&woh, g_woh);

    cudaFuncSetAttribute(gemm_mma, cudaFuncAttributeMaxDynamicSharedMemorySize,
                         GEMM_SMEM);
    cudaFuncSetAttribute(attn_flash, cudaFuncAttributeMaxDynamicSharedMemorySize,
                         ATTN_SMEM);

    // A-side splits (hi+lo) and B-side converts (hi only)
    split_f16_planes<<<M_TOK, 256>>>(x, xh, xl, M_TOK);
    conv_f16<<<3 * D, 256>>>(w_qkv, wqh, 3 * D);
    conv_f16<<<D, 256>>>(w_out, woh, D);

    // 1) QKV projection -> qkv hi plane [M,3072], Q lo plane [M,1024].
    //    Q tiles (bn<1024): 2 products; K/V tiles: 1 product (hi-only output).
    gemm_mma<<<dim3(3 * D / 128, M_TOK / 128), 128, GEMM_SMEM>>>(
        xh, xl, wqh, nullptr, nullptr, qh, ql, M_TOK, 3 * D, D, 1024, 1024);

    // 2) Flash attention -> att hi/lo fp16 planes
    attn_flash<<<Bsz * H * G * (LG / 64), 128, ATTN_SMEM>>>(qh, ql, ath, atl);

    // 3) Output projection + bias -> fp32 out (full 2-product everywhere)
    gemm_mma<<<dim3(D / 128, M_TOK / 128), 128, GEMM_SMEM>>>(
        ath, atl, woh, b_out, out, nullptr, nullptr, M_TOK, D, D, 0, D);
}

// round 16
// speedup vs baseline: 2.4258x; 1.2514x over previous
#include <cuda_runtime.h>
#include <cuda_fp16.h>
#include <math.h>
#include <stdint.h>

// Problem constants
constexpr int Bsz = 4;
constexpr int L   = 4096;
constexpr int D   = 1024;
constexpr int H   = 16;
constexpr int G   = 8;
constexpr int LG  = L / G;     // 512
constexpr int M_TOK = Bsz * L; // 16384

// Scratch planes (allocation-free: static __device__ globals), all fp16
__device__ __half g_qh [(size_t)M_TOK * 3072];   // qkv hi plane (Q,K,V)
__device__ __half g_ql [(size_t)M_TOK * 1024];   // Q lo plane
__device__ __half g_xh [(size_t)M_TOK * 1024];
__device__ __half g_xl [(size_t)M_TOK * 1024];
__device__ __half g_ath[(size_t)M_TOK * 1024];   // attention output (hi only)
__device__ __half g_wqh[(size_t)3072 * 1024];
__device__ __half g_woh[(size_t)1024 * 1024];

// ---------------------------------------------------------------------------
// helpers
// ---------------------------------------------------------------------------
__device__ __forceinline__ uint32_t swz64(uint32_t off) {   // 64B-row swizzle
    return off ^ ((off >> 3) & 0x30);
}
__device__ __forceinline__ uint32_t swz(uint32_t off) {     // 128B-row swizzle
    return off ^ ((off >> 3) & 0x70);
}
__device__ __forceinline__ uint32_t s2u(const void* p) {
    uint32_t a;
    asm("{ .reg .u64 t; cvta.to.shared.u64 t, %1; cvt.u32.u64 %0, t; }"
        : "=r"(a) : "l"(p));
    return a;
}
__device__ __forceinline__ void hilo2h(float a, float b, uint32_t& hp, uint32_t& lp) {
    __half ha = __float2half_rn(a);
    __half hb = __float2half_rn(b);
    __half la = __float2half_rn(a - __half2float(ha));
    __half lb = __float2half_rn(b - __half2float(hb));
    hp = (uint32_t)__half_as_ushort(ha) | ((uint32_t)__half_as_ushort(hb) << 16);
    lp = (uint32_t)__half_as_ushort(la) | ((uint32_t)__half_as_ushort(lb) << 16);
}
__device__ __forceinline__ uint32_t h2pack(float a, float b) {
    __half ha = __float2half_rn(a);
    __half hb = __float2half_rn(b);
    return (uint32_t)__half_as_ushort(ha) | ((uint32_t)__half_as_ushort(hb) << 16);
}

// fp16 MMA, fp32 accum. No volatile: deps via "+f".
#define MMA16816(acc, a, b0, b1)                                             \
    asm("mma.sync.aligned.m16n8k16.row.col.f32.f16.f16.f32 "                 \
        "{%0,%1,%2,%3}, {%4,%5,%6,%7}, {%8,%9}, {%0,%1,%2,%3};"              \
        : "+f"((acc)[0]), "+f"((acc)[1]), "+f"((acc)[2]), "+f"((acc)[3])     \
        : "r"((a)[0]), "r"((a)[1]), "r"((a)[2]), "r"((a)[3]),                \
          "r"(b0), "r"(b1))

#define LDMX4(r, addr)                                                       \
    asm volatile("ldmatrix.sync.aligned.m8n8.x4.shared.b16 {%0,%1,%2,%3}, [%4];" \
        : "=r"((r)[0]), "=r"((r)[1]), "=r"((r)[2]), "=r"((r)[3]) : "r"(addr))

#define LDMX4T(r, addr)                                                      \
    asm volatile("ldmatrix.sync.aligned.m8n8.x4.trans.shared.b16 {%0,%1,%2,%3}, [%4];" \
        : "=r"((r)[0]), "=r"((r)[1]), "=r"((r)[2]), "=r"((r)[3]) : "r"(addr))

#define CPASYNC16(dst, src)                                                  \
    asm volatile("cp.async.cg.shared.global [%0], [%1], 16;"                 \
        :: "r"(dst), "l"(src))

// ---------------------------------------------------------------------------
// Split fp32 [rows,1024] -> fp16 hi + lo planes.
// ---------------------------------------------------------------------------
__global__ void split_f16_planes(const float* __restrict__ src,
                                 __half* __restrict__ dsth,
                                 __half* __restrict__ dstl,
                                 int rows)
{
    int idx = blockIdx.x * 256 + threadIdx.x;
    if (idx >= rows * 256) return;
    int row = idx >> 8;
    int c4  = (idx & 255) << 2;
    float4 v = *(const float4*)(src + (size_t)row * 1024 + c4);
    uint32_t hp0, lp0, hp1, lp1;
    hilo2h(v.x, v.y, hp0, lp0);
    hilo2h(v.z, v.w, hp1, lp1);
    size_t o = (size_t)row * 1024 + c4;
    *(uint32_t*)(dsth + o)     = hp0; *(uint32_t*)(dsth + o + 2) = hp1;
    *(uint32_t*)(dstl + o)     = lp0; *(uint32_t*)(dstl + o + 2) = lp1;
}

// Convert fp32 [rows,1024] -> fp16 single plane.
__global__ void conv_f16(const float* __restrict__ src,
                         __half* __restrict__ dst, int rows)
{
    int idx = blockIdx.x * 256 + threadIdx.x;
    if (idx >= rows * 256) return;
    int row = idx >> 8;
    int c4  = (idx & 255) << 2;
    float4 v = *(const float4*)(src + (size_t)row * 1024 + c4);
    size_t o = (size_t)row * 1024 + c4;
    *(uint32_t*)(dst + o)     = h2pack(v.x, v.y);
    *(uint32_t*)(dst + o + 2) = h2pack(v.z, v.w);
}

// ---------------------------------------------------------------------------
// 2-product GEMM (Q projection): C = (Ah+Al)*Bh^T -> fp16 hi/lo planes.
// 128x128 CTA, 4 warps (64x64), BK=32, 64B rows, 3 stages (72KB).
// ---------------------------------------------------------------------------
constexpr int PL32 = 128 * 64;               // plane tile, BK=32: 8KB
constexpr int ST2P = 3 * PL32;               // Ah, Al, Bh = 24KB
constexpr int SMEM_2P = 3 * ST2P;            // 72KB

__global__ __launch_bounds__(128, 2) void gemm_2p(
    const __half* __restrict__ Ah, const __half* __restrict__ Al,
    const __half* __restrict__ Bh,
    __half* __restrict__ Ch, __half* __restrict__ Cl,
    int M, int N, int Kt, int ldCh, int ldCl)
{
    extern __shared__ __align__(1024) uint8_t smem[];

    const int tid  = threadIdx.x;
    const int wid  = tid >> 5;
    const int lane = tid & 31;
    const int warp_m = (wid & 1) * 64;
    const int warp_n = (wid >> 1) * 64;
    const size_t bm = (size_t)blockIdx.y * 128;
    const size_t bn = (size_t)blockIdx.x * 128;
    const uint32_t sbase = s2u(smem);

    uint32_t soff[4];
    size_t goff[4];
    #pragma unroll
    for (int i = 0; i < 4; i++) {
        int f = tid + i * 128;
        int row = f >> 2;
        int seg = f & 3;
        soff[i] = swz64((uint32_t)row * 64 + seg * 16);
        goff[i] = (size_t)row * Kt + seg * 8;
    }

    const int NC = Kt / 32;

    auto issue_copy = [&](int c, int stage) {
        const uint32_t ss = sbase + stage * ST2P;
        const int ko = c * 32;
        #pragma unroll
        for (int i = 0; i < 4; i++) {
            const size_t ga = bm * Kt + goff[i] + ko;
            const size_t gb = bn * Kt + goff[i] + ko;
            CPASYNC16(ss            + soff[i], Ah + ga);
            CPASYNC16(ss + PL32     + soff[i], Al + ga);
            CPASYNC16(ss + 2 * PL32 + soff[i], Bh + gb);
        }
        asm volatile("cp.async.commit_group;");
    };

    const int a_row = warp_m + (lane & 15);
    const int a_sub = (lane >> 4) * 16;
    const int b_row = warp_n + ((lane >> 4) & 1) * 8 + (lane & 7);
    const int b_sub = ((lane >> 3) & 1) * 16;

    float acc[4][8][4];
    #pragma unroll
    for (int mt = 0; mt < 4; mt++)
        #pragma unroll
        for (int nt = 0; nt < 8; nt++)
            #pragma unroll
            for (int q = 0; q < 4; q++) acc[mt][nt][q] = 0.f;

    issue_copy(0, 0);
    if (NC > 1) issue_copy(1, 1);

    for (int c = 0; c < NC; c++) {
        if (c + 1 < NC) { asm volatile("cp.async.wait_group 1;"); }
        else            { asm volatile("cp.async.wait_group 0;"); }
        __syncthreads();
        if (c + 2 < NC) issue_copy(c + 2, (c + 2) % 3);

        const uint32_t ss = sbase + (c % 3) * ST2P;

        #pragma unroll
        for (int kk = 0; kk < 2; kk++) {
            uint32_t afh[4][4], afl[4][4];
            #pragma unroll
            for (int mt = 0; mt < 4; mt++) {
                uint32_t off = (uint32_t)(a_row + mt * 16) * 64 + kk * 32 + a_sub;
                LDMX4(afh[mt], ss + swz64(off));
                LDMX4(afl[mt], ss + PL32 + swz64(off));
            }
            #pragma unroll
            for (int j = 0; j < 4; j++) {
                uint32_t off = (uint32_t)(b_row + j * 16) * 64 + kk * 32 + b_sub;
                uint32_t rh[4];
                LDMX4(rh, ss + 2 * PL32 + swz64(off));
                #pragma unroll
                for (int mt = 0; mt < 4; mt++) {
                    MMA16816(acc[mt][2 * j],     afh[mt], rh[0], rh[1]);
                    MMA16816(acc[mt][2 * j + 1], afh[mt], rh[2], rh[3]);
                }
                #pragma unroll
                for (int mt = 0; mt < 4; mt++) {
                    MMA16816(acc[mt][2 * j],     afl[mt], rh[0], rh[1]);
                    MMA16816(acc[mt][2 * j + 1], afl[mt], rh[2], rh[3]);
                }
            }
        }
    }

    #pragma unroll
    for (int mt = 0; mt < 4; mt++) {
        const size_t row0 = bm + warp_m + mt * 16 + (lane >> 2);
        #pragma unroll
        for (int nt = 0; nt < 8; nt++) {
            const size_t col = bn + warp_n + nt * 8 + (lane & 3) * 2;
            uint32_t hp, lp;
            hilo2h(acc[mt][nt][0], acc[mt][nt][1], hp, lp);
            *(uint32_t*)(Ch + row0 * (size_t)ldCh + col) = hp;
            *(uint32_t*)(Cl + row0 * (size_t)ldCl + col) = lp;
            hilo2h(acc[mt][nt][2], acc[mt][nt][3], hp, lp);
            *(uint32_t*)(Ch + (row0 + 8) * (size_t)ldCh + col) = hp;
            *(uint32_t*)(Cl + (row0 + 8) * (size_t)ldCl + col) = lp;
        }
    }
}

// ---------------------------------------------------------------------------
// 1-product GEMM (KV projection / output projection): C = Ah*Bh^T.
// 128x128 CTA, 4 warps (64x64), BK=64, 128B rows, 3 stages (96KB).
// Output: fp16 hi plane (Ch) or fp32 (+bias) to C.
// ---------------------------------------------------------------------------
constexpr int PL64 = 128 * 128;              // plane tile, BK=64: 16KB
constexpr int ST1P = 2 * PL64;               // Ah, Bh = 32KB
constexpr int SMEM_1P = 3 * ST1P;            // 96KB

__global__ __launch_bounds__(128, 2) void gemm_1p(
    const __half* __restrict__ Ah, const __half* __restrict__ Bh,
    const float* __restrict__ bias, float* __restrict__ C,
    __half* __restrict__ Ch,
    int M, int N, int Kt, int ldCh)
{
    extern __shared__ __align__(1024) uint8_t smem[];

    const int tid  = threadIdx.x;
    const int wid  = tid >> 5;
    const int lane = tid & 31;
    const int warp_m = (wid & 1) * 64;
    const int warp_n = (wid >> 1) * 64;
    const size_t bm = (size_t)blockIdx.y * 128;
    const size_t bn = (size_t)blockIdx.x * 128;
    const uint32_t sbase = s2u(smem);

    uint32_t soff[8];
    size_t goff[8];
    #pragma unroll
    for (int i = 0; i < 8; i++) {
        int f = tid + i * 128;
        int row = f >> 3;
        int seg = f & 7;
        soff[i] = swz((uint32_t)row * 128 + seg * 16);
        goff[i] = (size_t)row * Kt + seg * 8;
    }

    const int NC = Kt / 64;

    auto issue_copy = [&](int c, int stage) {
        const uint32_t ss = sbase + stage * ST1P;
        const int ko = c * 64;
        #pragma unroll
        for (int i = 0; i < 8; i++) {
            CPASYNC16(ss        + soff[i], Ah + bm * Kt + goff[i] + ko);
            CPASYNC16(ss + PL64 + soff[i], Bh + bn * Kt + goff[i] + ko);
        }
        asm volatile("cp.async.commit_group;");
    };

    const int a_row = warp_m + (lane & 15);
    const int a_sub = (lane >> 4) * 16;
    const int b_row = warp_n + ((lane >> 4) & 1) * 8 + (lane & 7);
    const int b_sub = ((lane >> 3) & 1) * 16;

    float acc[4][8][4];
    #pragma unroll
    for (int mt = 0; mt < 4; mt++)
        #pragma unroll
        for (int nt = 0; nt < 8; nt++)
            #pragma unroll
            for (int q = 0; q < 4; q++) acc[mt][nt][q] = 0.f;

    issue_copy(0, 0);
    if (NC > 1) issue_copy(1, 1);

    for (int c = 0; c < NC; c++) {
        if (c + 1 < NC) { asm volatile("cp.async.wait_group 1;"); }
        else            { asm volatile("cp.async.wait_group 0;"); }
        __syncthreads();
        if (c + 2 < NC) issue_copy(c + 2, (c + 2) % 3);

        const uint32_t sa = sbase + (c % 3) * ST1P;
        const uint32_t sb = sa + PL64;

        #pragma unroll
        for (int kk = 0; kk < 4; kk++) {
            uint32_t af[4][4];
            #pragma unroll
            for (int mt = 0; mt < 4; mt++) {
                uint32_t off = (uint32_t)(a_row + mt * 16) * 128 + kk * 32 + a_sub;
                LDMX4(af[mt], sa + swz(off));
            }
            #pragma unroll
            for (int j = 0; j < 4; j++) {
                uint32_t off = (uint32_t)(b_row + j * 16) * 128 + kk * 32 + b_sub;
                uint32_t rh[4];
                LDMX4(rh, sb + swz(off));
                #pragma unroll
                for (int mt = 0; mt < 4; mt++) {
                    MMA16816(acc[mt][2 * j],     af[mt], rh[0], rh[1]);
                    MMA16816(acc[mt][2 * j + 1], af[mt], rh[2], rh[3]);
                }
            }
        }
    }

    if (Ch) {
        #pragma unroll
        for (int mt = 0; mt < 4; mt++) {
            const size_t row0 = bm + warp_m + mt * 16 + (lane >> 2);
            #pragma unroll
            for (int nt = 0; nt < 8; nt++) {
                const size_t col = bn + warp_n + nt * 8 + (lane & 3) * 2;
                *(uint32_t*)(Ch + row0 * (size_t)ldCh + col) =
                    h2pack(acc[mt][nt][0], acc[mt][nt][1]);
                *(uint32_t*)(Ch + (row0 + 8) * (size_t)ldCh + col) =
                    h2pack(acc[mt][nt][2], acc[mt][nt][3]);
            }
        }
    } else {
        #pragma unroll
        for (int mt = 0; mt < 4; mt++) {
            const size_t row0 = bm + warp_m + mt * 16 + (lane >> 2);
            #pragma unroll
            for (int nt = 0; nt < 8; nt++) {
                const size_t col = bn + warp_n + nt * 8 + (lane & 3) * 2;
                float bx = bias[col], by = bias[col + 1];
                float2 v0 = {acc[mt][nt][0] + bx, acc[mt][nt][1] + by};
                float2 v1 = {acc[mt][nt][2] + bx, acc[mt][nt][3] + by};
                *(float2*)(C + row0 * (size_t)N + col)       = v0;
                *(float2*)(C + (row0 + 8) * (size_t)N + col) = v1;
            }
        }
    }
}

// ---------------------------------------------------------------------------
// Flash attention, fp16: S = (Qh+Ql)*Kh ; O = (Ph+Pl)*Vh. K/V hi-only.
// CTA = 64 q x 512-key block, 4 warps (m16), per-warp online softmax,
// 8 chunks of 64 keys, double-buffered cp.async, P in registers.
// Writes fp16 hi plane only (GEMM3 is 1-product).
// ---------------------------------------------------------------------------
constexpr int sAQH = 0;
constexpr int sAQL = 8192;
constexpr int sBUF0 = 16384;
constexpr int sBUFSZ = 16384;
constexpr int ATTN_SMEM = 16384 + 2 * sBUFSZ;   // 48KB

__global__ __launch_bounds__(128) void attn_flash(const __half* __restrict__ qh,
                                                  const __half* __restrict__ ql,
                                                  __half* __restrict__ ath)
{
    extern __shared__ __align__(1024) char smc[];
    const uint32_t sbs = s2u(smc);

    const int tid  = threadIdx.x;
    const int lane = tid & 31;
    const int w    = tid >> 5;

    const int idx = blockIdx.x;
    const int qt = idx & 7;
    const int g  = (idx >> 3) & 7;
    const int h  = (idx >> 6) & 15;
    const int b  = idx >> 10;
    const int pos0 = g * LG;
    const int q0   = pos0 + qt * 64;

    const int lrow = tid >> 3;
    const int lseg = tid & 7;
    uint32_t soff[4];
    #pragma unroll
    for (int i = 0; i < 4; i++)
        soff[i] = swz((uint32_t)(lrow + i * 16) * 128 + lseg * 16);

    #pragma unroll
    for (int i = 0; i < 4; i++) {
        const size_t qoh = (size_t)(b * L + q0 + lrow + i * 16) * 3072 + h * 64 + lseg * 8;
        const size_t qol = (size_t)(b * L + q0 + lrow + i * 16) * 1024 + h * 64 + lseg * 8;
        CPASYNC16(sbs + sAQH + soff[i], qh + qoh);
        CPASYNC16(sbs + sAQL + soff[i], ql + qol);
    }

    auto issue_chunk = [&](int c, int buf) {
        const uint32_t bb = sbs + sBUF0 + buf * sBUFSZ;
        #pragma unroll
        for (int i = 0; i < 4; i++) {
            const size_t ko = (size_t)(b * L + pos0 + c * 64 + lrow + i * 16) * 3072
                              + 1024 + h * 64 + lseg * 8;
            CPASYNC16(bb        + soff[i], qh + ko);          // K hi
            CPASYNC16(bb + 8192 + soff[i], qh + ko + 1024);   // V hi
        }
        asm volatile("cp.async.commit_group;");
    };
    issue_chunk(0, 0);

    const int kRow  = ((lane >> 4) & 1) * 8 + (lane & 7);
    const int kSub  = ((lane >> 3) & 1) * 16;
    const int vRow  = (lane & 7) + ((lane >> 3) & 1) * 8;
    const int vColB = (lane >> 4) * 16;

    uint32_t qf[2][4][4];
    float o[8][4];
    #pragma unroll
    for (int t = 0; t < 8; t++)
        #pragma unroll
        for (int j = 0; j < 4; j++) o[t][j] = 0.f;
    float m0 = -1e30f, m1 = -1e30f, l0 = 0.f, l1 = 0.f;
    const float scale = 0.125f;

    for (int c = 0; c < 8; c++) {
        asm volatile("cp.async.wait_group 0;");
        __syncthreads();
        if (c + 1 < 8) issue_chunk(c + 1, (c + 1) & 1);
        if (c == 0) {
            #pragma unroll
            for (int pl = 0; pl < 2; pl++) {
                const uint32_t qb = sbs + (pl ? sAQL : sAQH);
                #pragma unroll
                for (int kk = 0; kk < 4; kk++) {
                    uint32_t off = (uint32_t)(w * 16 + (lane & 15)) * 128 + kk * 32 + (lane >> 4) * 16;
                    LDMX4(qf[pl][kk], qb + swz(off));
                }
            }
        }

        const uint32_t bb = sbs + sBUF0 + (c & 1) * sBUFSZ;

        float s[8][4];
        #pragma unroll
        for (int t = 0; t < 8; t++)
            #pragma unroll
            for (int j = 0; j < 4; j++) s[t][j] = 0.f;

        #pragma unroll
        for (int p = 0; p < 2; p++) {
            #pragma unroll
            for (int kk = 0; kk < 4; kk++) {
                #pragma unroll
                for (int n16 = 0; n16 < 4; n16++) {
                    uint32_t bq[4];
                    uint32_t off = (uint32_t)(n16 * 16 + kRow) * 128 + kk * 32 + kSub;
                    LDMX4(bq, bb + swz(off));
                    MMA16816(s[2 * n16],     qf[p][kk], bq[0], bq[1]);
                    MMA16816(s[2 * n16 + 1], qf[p][kk], bq[2], bq[3]);
                }
            }
        }

        float cm0 = -1e30f, cm1 = -1e30f;
        #pragma unroll
        for (int t = 0; t < 8; t++) {
            cm0 = fmaxf(cm0, fmaxf(s[t][0], s[t][1]));
            cm1 = fmaxf(cm1, fmaxf(s[t][2], s[t][3]));
        }
        cm0 *= scale; cm1 *= scale;
        cm0 = fmaxf(cm0, __shfl_xor_sync(0xffffffffu, cm0, 1));
        cm0 = fmaxf(cm0, __shfl_xor_sync(0xffffffffu, cm0, 2));
        cm1 = fmaxf(cm1, __shfl_xor_sync(0xffffffffu, cm1, 1));
        cm1 = fmaxf(cm1, __shfl_xor_sync(0xffffffffu, cm1, 2));
        const float mn0 = fmaxf(m0, cm0);
        const float mn1 = fmaxf(m1, cm1);
        const float al0 = __expf(m0 - mn0);
        const float al1 = __expf(m1 - mn1);
        m0 = mn0; m1 = mn1;

        float ls0 = 0.f, ls1 = 0.f;
        #pragma unroll
        for (int t = 0; t < 8; t++) {
            float p0 = __expf(s[t][0] * scale - mn0);
            float p1 = __expf(s[t][1] * scale - mn0);
            float p2 = __expf(s[t][2] * scale - mn1);
            float p3 = __expf(s[t][3] * scale - mn1);
            s[t][0] = p0; s[t][1] = p1; s[t][2] = p2; s[t][3] = p3;
            ls0 += p0 + p1; ls1 += p2 + p3;
        }
        l0 = l0 * al0 + ls0;
        l1 = l1 * al1 + ls1;
        #pragma unroll
        for (int t = 0; t < 8; t++) {
            o[t][0] *= al0; o[t][1] *= al0;
            o[t][2] *= al1; o[t][3] *= al1;
        }

        uint32_t pfh[4][4], pfl[4][4];
        #pragma unroll
        for (int kk = 0; kk < 4; kk++) {
            hilo2h(s[2 * kk][0],     s[2 * kk][1],     pfh[kk][0], pfl[kk][0]);
            hilo2h(s[2 * kk][2],     s[2 * kk][3],     pfh[kk][1], pfl[kk][1]);
            hilo2h(s[2 * kk + 1][0], s[2 * kk + 1][1], pfh[kk][2], pfl[kk][2]);
            hilo2h(s[2 * kk + 1][2], s[2 * kk + 1][3], pfh[kk][3], pfl[kk][3]);
        }

        const uint32_t vb = bb + 8192;
        #pragma unroll
        for (int p = 0; p < 2; p++) {
            #pragma unroll
            for (int kk = 0; kk < 4; kk++) {
                const uint32_t* pf = p ? pfl[kk] : pfh[kk];
                #pragma unroll
                for (int n16 = 0; n16 < 4; n16++) {
                    uint32_t bv[4];
                    uint32_t off = (uint32_t)(kk * 16 + vRow) * 128 + n16 * 32 + vColB;
                    LDMX4T(bv, vb + swz(off));
                    MMA16816(o[2 * n16],     pf, bv[0], bv[1]);
                    MMA16816(o[2 * n16 + 1], pf, bv[2], bv[3]);
                }
            }
        }
    }

    l0 += __shfl_xor_sync(0xffffffffu, l0, 1);
    l0 += __shfl_xor_sync(0xffffffffu, l0, 2);
    l1 += __shfl_xor_sync(0xffffffffu, l1, 1);
    l1 += __shfl_xor_sync(0xffffffffu, l1, 2);
    const float inv0 = 1.0f / l0;
    const float inv1 = 1.0f / l1;

    const size_t gr0 = (size_t)(b * L + q0 + w * 16 + (lane >> 2)) * 1024 + h * 64;
    const size_t gr1 = gr0 + (size_t)8 * 1024;
    #pragma unroll
    for (int t = 0; t < 8; t++) {
        const int cc = t * 8 + (lane & 3) * 2;
        *(uint32_t*)(ath + gr0 + cc) = h2pack(o[t][0] * inv0, o[t][1] * inv0);
        *(uint32_t*)(ath + gr1 + cc) = h2pack(o[t][2] * inv1, o[t][3] * inv1);
    }
}

// ---------------------------------------------------------------------------
extern "C" void kernel_launch(void* const* d_in, const int* in_sizes, int n_in,
                              void* d_out, int out_size)
{
    const float* x     = (const float*)d_in[0];
    const float* w_qkv = (const float*)d_in[1];
    const float* w_out = (const float*)d_in[2];
    const float* b_out = (const float*)d_in[3];
    float* out = (float*)d_out;

    __half *qh, *ql, *xh, *xl, *ath, *wqh, *woh;
    cudaGetSymbolAddress((void**)&qh,  g_qh);
    cudaGetSymbolAddress((void**)&ql,  g_ql);
    cudaGetSymbolAddress((void**)&xh,  g_xh);
    cudaGetSymbolAddress((void**)&xl,  g_xl);
    cudaGetSymbolAddress((void**)&ath, g_ath);
    cudaGetSymbolAddress((void**)&wqh, g_wqh);
    cudaGetSymbolAddress((void**)&woh, g_woh);

    cudaFuncSetAttribute(gemm_2p, cudaFuncAttributeMaxDynamicSharedMemorySize,
                         SMEM_2P);
    cudaFuncSetAttribute(gemm_1p, cudaFuncAttributeMaxDynamicSharedMemorySize,
                         SMEM_1P);
    cudaFuncSetAttribute(attn_flash, cudaFuncAttributeMaxDynamicSharedMemorySize,
                         ATTN_SMEM);

    // Splits / converts
    split_f16_planes<<<M_TOK, 256>>>(x, xh, xl, M_TOK);
    conv_f16<<<3 * D, 256>>>(w_qkv, wqh, 3 * D);
    conv_f16<<<D, 256>>>(w_out, woh, D);

    // 1a) Q projection (2-product, BK=32): cols 0..1023 of qkv hi + Q lo
    gemm_2p<<<dim3(8, M_TOK / 128), 128, SMEM_2P>>>(
        xh, xl, wqh, qh, ql, M_TOK, 1024, D, 3072, 1024);

    // 1b) KV projection (1-product, BK=64): cols 1024..3071 of qkv hi
    gemm_1p<<<dim3(16, M_TOK / 128), 128, SMEM_1P>>>(
        xh, wqh + (size_t)1024 * 1024, nullptr, nullptr, qh + 1024,
        M_TOK, 2048, D, 3072);

    // 2) Flash attention -> att hi plane
    attn_flash<<<Bsz * H * G * (LG / 64), 128, ATTN_SMEM>>>(qh, ql, ath);

    // 3) Output projection + bias (1-product, BK=64) -> fp32 out
    gemm_1p<<<dim3(8, M_TOK / 128), 128, SMEM_1P>>>(
        ath, woh, b_out, out, nullptr, M_TOK, 1024, D, 0);
}

// round 17
// speedup vs baseline: 3.1658x; 1.3051x over previous
#include <cuda_runtime.h>
#include <cuda_fp16.h>
#include <math.h>
#include <stdint.h>

// Problem constants
constexpr int Bsz = 4;
constexpr int L   = 4096;
constexpr int D   = 1024;
constexpr int H   = 16;
constexpr int G   = 8;
constexpr int LG  = L / G;     // 512
constexpr int M_TOK = Bsz * L; // 16384

// Scratch planes (allocation-free: static __device__ globals), all fp16
__device__ __half g_qh [(size_t)M_TOK * 3072];   // qkv fp16 (Q,K,V)
__device__ __half g_xh [(size_t)M_TOK * 1024];   // x fp16
__device__ __half g_ath[(size_t)M_TOK * 1024];   // attention output fp16
__device__ __half g_wqh[(size_t)3072 * 1024];    // w_qkv fp16
__device__ __half g_woh[(size_t)1024 * 1024];    // w_out fp16

// ---------------------------------------------------------------------------
// helpers
// ---------------------------------------------------------------------------
__device__ __forceinline__ uint32_t swz(uint32_t off) {     // 128B-row swizzle
    return off ^ ((off >> 3) & 0x70);
}
__device__ __forceinline__ uint32_t s2u(const void* p) {
    uint32_t a;
    asm("{ .reg .u64 t; cvta.to.shared.u64 t, %1; cvt.u32.u64 %0, t; }"
        : "=r"(a) : "l"(p));
    return a;
}
__device__ __forceinline__ uint32_t h2pack(float a, float b) {
    __half ha = __float2half_rn(a);
    __half hb = __float2half_rn(b);
    return (uint32_t)__half_as_ushort(ha) | ((uint32_t)__half_as_ushort(hb) << 16);
}

// fp16 MMA, fp32 accum. No volatile: deps via "+f".
#define MMA16816(acc, a, b0, b1)                                             \
    asm("mma.sync.aligned.m16n8k16.row.col.f32.f16.f16.f32 "                 \
        "{%0,%1,%2,%3}, {%4,%5,%6,%7}, {%8,%9}, {%0,%1,%2,%3};"              \
        : "+f"((acc)[0]), "+f"((acc)[1]), "+f"((acc)[2]), "+f"((acc)[3])     \
        : "r"((a)[0]), "r"((a)[1]), "r"((a)[2]), "r"((a)[3]),                \
          "r"(b0), "r"(b1))

#define LDMX4(r, addr)                                                       \
    asm volatile("ldmatrix.sync.aligned.m8n8.x4.shared.b16 {%0,%1,%2,%3}, [%4];" \
        : "=r"((r)[0]), "=r"((r)[1]), "=r"((r)[2]), "=r"((r)[3]) : "r"(addr))

#define LDMX4T(r, addr)                                                      \
    asm volatile("ldmatrix.sync.aligned.m8n8.x4.trans.shared.b16 {%0,%1,%2,%3}, [%4];" \
        : "=r"((r)[0]), "=r"((r)[1]), "=r"((r)[2]), "=r"((r)[3]) : "r"(addr))

#define CPASYNC16(dst, src)                                                  \
    asm volatile("cp.async.cg.shared.global [%0], [%1], 16;"                 \
        :: "r"(dst), "l"(src))

// ---------------------------------------------------------------------------
// Convert fp32 [rows,1024] -> fp16 plane.
// ---------------------------------------------------------------------------
__global__ void conv_f16(const float* __restrict__ src,
                         __half* __restrict__ dst, int rows)
{
    int idx = blockIdx.x * 256 + threadIdx.x;
    if (idx >= rows * 256) return;
    int row = idx >> 8;
    int c4  = (idx & 255) << 2;
    float4 v = *(const float4*)(src + (size_t)row * 1024 + c4);
    size_t o = (size_t)row * 1024 + c4;
    *(uint32_t*)(dst + o)     = h2pack(v.x, v.y);
    *(uint32_t*)(dst + o + 2) = h2pack(v.z, v.w);
}

// ---------------------------------------------------------------------------
// fp16 GEMM: C = A*B^T. 128x128 CTA, 4 warps (64x64), BK=64, 128B rows,
// 3 stages (96KB), single sync per chunk.
// Output: fp16 plane (Ch, ld=ldCh) or fp32 (+bias) to C.
// ---------------------------------------------------------------------------
constexpr int PL64 = 128 * 128;              // plane tile, BK=64: 16KB
constexpr int ST1P = 2 * PL64;               // A, B = 32KB
constexpr int SMEM_1P = 3 * ST1P;            // 96KB

__global__ __launch_bounds__(128, 2) void gemm_1p(
    const __half* __restrict__ Ah, const __half* __restrict__ Bh,
    const float* __restrict__ bias, float* __restrict__ C,
    __half* __restrict__ Ch,
    int M, int N, int Kt, int ldCh)
{
    extern __shared__ __align__(1024) uint8_t smem[];

    const int tid  = threadIdx.x;
    const int wid  = tid >> 5;
    const int lane = tid & 31;
    const int warp_m = (wid & 1) * 64;
    const int warp_n = (wid >> 1) * 64;
    const size_t bm = (size_t)blockIdx.y * 128;
    const size_t bn = (size_t)blockIdx.x * 128;
    const uint32_t sbase = s2u(smem);

    uint32_t soff[8];
    size_t goff[8];
    #pragma unroll
    for (int i = 0; i < 8; i++) {
        int f = tid + i * 128;
        int row = f >> 3;
        int seg = f & 7;
        soff[i] = swz((uint32_t)row * 128 + seg * 16);
        goff[i] = (size_t)row * Kt + seg * 8;
    }

    const int NC = Kt / 64;

    auto issue_copy = [&](int c, int stage) {
        const uint32_t ss = sbase + stage * ST1P;
        const int ko = c * 64;
        #pragma unroll
        for (int i = 0; i < 8; i++) {
            CPASYNC16(ss        + soff[i], Ah + bm * Kt + goff[i] + ko);
            CPASYNC16(ss + PL64 + soff[i], Bh + bn * Kt + goff[i] + ko);
        }
        asm volatile("cp.async.commit_group;");
    };

    const int a_row = warp_m + (lane & 15);
    const int a_sub = (lane >> 4) * 16;
    const int b_row = warp_n + ((lane >> 4) & 1) * 8 + (lane & 7);
    const int b_sub = ((lane >> 3) & 1) * 16;

    float acc[4][8][4];
    #pragma unroll
    for (int mt = 0; mt < 4; mt++)
        #pragma unroll
        for (int nt = 0; nt < 8; nt++)
            #pragma unroll
            for (int q = 0; q < 4; q++) acc[mt][nt][q] = 0.f;

    issue_copy(0, 0);
    if (NC > 1) issue_copy(1, 1);

    for (int c = 0; c < NC; c++) {
        if (c + 1 < NC) { asm volatile("cp.async.wait_group 1;"); }
        else            { asm volatile("cp.async.wait_group 0;"); }
        __syncthreads();
        if (c + 2 < NC) issue_copy(c + 2, (c + 2) % 3);

        const uint32_t sa = sbase + (c % 3) * ST1P;
        const uint32_t sb = sa + PL64;

        #pragma unroll
        for (int kk = 0; kk < 4; kk++) {
            uint32_t af[4][4];
            #pragma unroll
            for (int mt = 0; mt < 4; mt++) {
                uint32_t off = (uint32_t)(a_row + mt * 16) * 128 + kk * 32 + a_sub;
                LDMX4(af[mt], sa + swz(off));
            }
            #pragma unroll
            for (int j = 0; j < 4; j++) {
                uint32_t off = (uint32_t)(b_row + j * 16) * 128 + kk * 32 + b_sub;
                uint32_t rh[4];
                LDMX4(rh, sb + swz(off));
                #pragma unroll
                for (int mt = 0; mt < 4; mt++) {
                    MMA16816(acc[mt][2 * j],     af[mt], rh[0], rh[1]);
                    MMA16816(acc[mt][2 * j + 1], af[mt], rh[2], rh[3]);
                }
            }
        }
    }

    if (Ch) {
        #pragma unroll
        for (int mt = 0; mt < 4; mt++) {
            const size_t row0 = bm + warp_m + mt * 16 + (lane >> 2);
            #pragma unroll
            for (int nt = 0; nt < 8; nt++) {
                const size_t col = bn + warp_n + nt * 8 + (lane & 3) * 2;
                *(uint32_t*)(Ch + row0 * (size_t)ldCh + col) =
                    h2pack(acc[mt][nt][0], acc[mt][nt][1]);
                *(uint32_t*)(Ch + (row0 + 8) * (size_t)ldCh + col) =
                    h2pack(acc[mt][nt][2], acc[mt][nt][3]);
            }
        }
    } else {
        #pragma unroll
        for (int mt = 0; mt < 4; mt++) {
            const size_t row0 = bm + warp_m + mt * 16 + (lane >> 2);
            #pragma unroll
            for (int nt = 0; nt < 8; nt++) {
                const size_t col = bn + warp_n + nt * 8 + (lane & 3) * 2;
                float bx = bias[col], by = bias[col + 1];
                float2 v0 = {acc[mt][nt][0] + bx, acc[mt][nt][1] + by};
                float2 v1 = {acc[mt][nt][2] + bx, acc[mt][nt][3] + by};
                *(float2*)(C + row0 * (size_t)N + col)       = v0;
                *(float2*)(C + (row0 + 8) * (size_t)N + col) = v1;
            }
        }
    }
}

// ---------------------------------------------------------------------------
// Flash attention, plain fp16: S = Qh*Kh ; O = Ph*Vh (single pass each).
// CTA = 64 q x 512-key block, 4 warps (m16), per-warp online softmax,
// 8 chunks of 64 keys, double-buffered cp.async, P in registers.
// ---------------------------------------------------------------------------
constexpr int sAQH = 0;         // Q: 64 x 128B (swizzled) = 8KB
constexpr int sBUF0 = 8192;     // per buffer: K 8KB + V 8KB
constexpr int sBUFSZ = 16384;
constexpr int ATTN_SMEM = 8192 + 2 * sBUFSZ;   // 40KB

__global__ __launch_bounds__(128) void attn_flash(const __half* __restrict__ qh,
                                                  __half* __restrict__ ath)
{
    extern __shared__ __align__(1024) char smc[];
    const uint32_t sbs = s2u(smc);

    const int tid  = threadIdx.x;
    const int lane = tid & 31;
    const int w    = tid >> 5;

    const int idx = blockIdx.x;
    const int qt = idx & 7;
    const int g  = (idx >> 3) & 7;
    const int h  = (idx >> 6) & 15;
    const int b  = idx >> 10;
    const int pos0 = g * LG;
    const int q0   = pos0 + qt * 64;

    const int lrow = tid >> 3;
    const int lseg = tid & 7;
    uint32_t soff[4];
    #pragma unroll
    for (int i = 0; i < 4; i++)
        soff[i] = swz((uint32_t)(lrow + i * 16) * 128 + lseg * 16);

    // Q fill (single fp16 plane, stride 3072)
    #pragma unroll
    for (int i = 0; i < 4; i++) {
        const size_t qo = (size_t)(b * L + q0 + lrow + i * 16) * 3072 + h * 64 + lseg * 8;
        CPASYNC16(sbs + sAQH + soff[i], qh + qo);
    }

    auto issue_chunk = [&](int c, int buf) {
        const uint32_t bb = sbs + sBUF0 + buf * sBUFSZ;
        #pragma unroll
        for (int i = 0; i < 4; i++) {
            const size_t ko = (size_t)(b * L + pos0 + c * 64 + lrow + i * 16) * 3072
                              + 1024 + h * 64 + lseg * 8;
            CPASYNC16(bb        + soff[i], qh + ko);          // K
            CPASYNC16(bb + 8192 + soff[i], qh + ko + 1024);   // V
        }
        asm volatile("cp.async.commit_group;");
    };
    issue_chunk(0, 0);

    const int kRow  = ((lane >> 4) & 1) * 8 + (lane & 7);
    const int kSub  = ((lane >> 3) & 1) * 16;
    const int vRow  = (lane & 7) + ((lane >> 3) & 1) * 8;
    const int vColB = (lane >> 4) * 16;

    uint32_t qf[4][4];
    float o[8][4];
    #pragma unroll
    for (int t = 0; t < 8; t++)
        #pragma unroll
        for (int j = 0; j < 4; j++) o[t][j] = 0.f;
    float m0 = -1e30f, m1 = -1e30f, l0 = 0.f, l1 = 0.f;
    const float scale = 0.125f;

    for (int c = 0; c < 8; c++) {
        asm volatile("cp.async.wait_group 0;");
        __syncthreads();
        if (c + 1 < 8) issue_chunk(c + 1, (c + 1) & 1);
        if (c == 0) {
            #pragma unroll
            for (int kk = 0; kk < 4; kk++) {
                uint32_t off = (uint32_t)(w * 16 + (lane & 15)) * 128 + kk * 32 + (lane >> 4) * 16;
                LDMX4(qf[kk], sbs + sAQH + swz(off));
            }
        }

        const uint32_t bb = sbs + sBUF0 + (c & 1) * sBUFSZ;

        // S = Q*K^T (single pass)
        float s[8][4];
        #pragma unroll
        for (int t = 0; t < 8; t++)
            #pragma unroll
            for (int j = 0; j < 4; j++) s[t][j] = 0.f;

        #pragma unroll
        for (int kk = 0; kk < 4; kk++) {
            #pragma unroll
            for (int n16 = 0; n16 < 4; n16++) {
                uint32_t bq[4];
                uint32_t off = (uint32_t)(n16 * 16 + kRow) * 128 + kk * 32 + kSub;
                LDMX4(bq, bb + swz(off));
                MMA16816(s[2 * n16],     qf[kk], bq[0], bq[1]);
                MMA16816(s[2 * n16 + 1], qf[kk], bq[2], bq[3]);
            }
        }

        // online softmax update
        float cm0 = -1e30f, cm1 = -1e30f;
        #pragma unroll
        for (int t = 0; t < 8; t++) {
            cm0 = fmaxf(cm0, fmaxf(s[t][0], s[t][1]));
            cm1 = fmaxf(cm1, fmaxf(s[t][2], s[t][3]));
        }
        cm0 *= scale; cm1 *= scale;
        cm0 = fmaxf(cm0, __shfl_xor_sync(0xffffffffu, cm0, 1));
        cm0 = fmaxf(cm0, __shfl_xor_sync(0xffffffffu, cm0, 2));
        cm1 = fmaxf(cm1, __shfl_xor_sync(0xffffffffu, cm1, 1));
        cm1 = fmaxf(cm1, __shfl_xor_sync(0xffffffffu, cm1, 2));
        const float mn0 = fmaxf(m0, cm0);
        const float mn1 = fmaxf(m1, cm1);
        const float al0 = __expf(m0 - mn0);
        const float al1 = __expf(m1 - mn1);
        m0 = mn0; m1 = mn1;

        float ls0 = 0.f, ls1 = 0.f;
        #pragma unroll
        for (int t = 0; t < 8; t++) {
            float p0 = __expf(s[t][0] * scale - mn0);
            float p1 = __expf(s[t][1] * scale - mn0);
            float p2 = __expf(s[t][2] * scale - mn1);
            float p3 = __expf(s[t][3] * scale - mn1);
            s[t][0] = p0; s[t][1] = p1; s[t][2] = p2; s[t][3] = p3;
            ls0 += p0 + p1; ls1 += p2 + p3;
        }
        l0 = l0 * al0 + ls0;
        l1 = l1 * al1 + ls1;
        #pragma unroll
        for (int t = 0; t < 8; t++) {
            o[t][0] *= al0; o[t][1] *= al0;
            o[t][2] *= al1; o[t][3] *= al1;
        }

        // P -> fp16 A-fragments (registers, hi only)
        uint32_t pf[4][4];
        #pragma unroll
        for (int kk = 0; kk < 4; kk++) {
            pf[kk][0] = h2pack(s[2 * kk][0],     s[2 * kk][1]);
            pf[kk][1] = h2pack(s[2 * kk][2],     s[2 * kk][3]);
            pf[kk][2] = h2pack(s[2 * kk + 1][0], s[2 * kk + 1][1]);
            pf[kk][3] = h2pack(s[2 * kk + 1][2], s[2 * kk + 1][3]);
        }

        // O += P*V (single pass)
        const uint32_t vb = bb + 8192;
        #pragma unroll
        for (int kk = 0; kk < 4; kk++) {
            #pragma unroll
            for (int n16 = 0; n16 < 4; n16++) {
                uint32_t bv[4];
                uint32_t off = (uint32_t)(kk * 16 + vRow) * 128 + n16 * 32 + vColB;
                LDMX4T(bv, vb + swz(off));
                MMA16816(o[2 * n16],     pf[kk], bv[0], bv[1]);
                MMA16816(o[2 * n16 + 1], pf[kk], bv[2], bv[3]);
            }
        }
    }

    l0 += __shfl_xor_sync(0xffffffffu, l0, 1);
    l0 += __shfl_xor_sync(0xffffffffu, l0, 2);
    l1 += __shfl_xor_sync(0xffffffffu, l1, 1);
    l1 += __shfl_xor_sync(0xffffffffu, l1, 2);
    const float inv0 = 1.0f / l0;
    const float inv1 = 1.0f / l1;

    const size_t gr0 = (size_t)(b * L + q0 + w * 16 + (lane >> 2)) * 1024 + h * 64;
    const size_t gr1 = gr0 + (size_t)8 * 1024;
    #pragma unroll
    for (int t = 0; t < 8; t++) {
        const int cc = t * 8 + (lane & 3) * 2;
        *(uint32_t*)(ath + gr0 + cc) = h2pack(o[t][0] * inv0, o[t][1] * inv0);
        *(uint32_t*)(ath + gr1 + cc) = h2pack(o[t][2] * inv1, o[t][3] * inv1);
    }
}

// ---------------------------------------------------------------------------
extern "C" void kernel_launch(void* const* d_in, const int* in_sizes, int n_in,
                              void* d_out, int out_size)
{
    const float* x     = (const float*)d_in[0];
    const float* w_qkv = (const float*)d_in[1];
    const float* w_out = (const float*)d_in[2];
    const float* b_out = (const float*)d_in[3];
    float* out = (float*)d_out;

    __half *qh, *xh, *ath, *wqh, *woh;
    cudaGetSymbolAddress((void**)&qh,  g_qh);
    cudaGetSymbolAddress((void**)&xh,  g_xh);
    cudaGetSymbolAddress((void**)&ath, g_ath);
    cudaGetSymbolAddress((void**)&wqh, g_wqh);
    cudaGetSymbolAddress((void**)&woh, g_woh);

    cudaFuncSetAttribute(gemm_1p, cudaFuncAttributeMaxDynamicSharedMemorySize,
                         SMEM_1P);
    cudaFuncSetAttribute(attn_flash, cudaFuncAttributeMaxDynamicSharedMemorySize,
                         ATTN_SMEM);

    // fp16 converts
    conv_f16<<<M_TOK, 256>>>(x, xh, M_TOK);
    conv_f16<<<3 * D, 256>>>(w_qkv, wqh, 3 * D);
    conv_f16<<<D, 256>>>(w_out, woh, D);

    // 1) Fused QKV projection (1-product, BK=64): all 3072 cols -> qh
    gemm_1p<<<dim3(24, M_TOK / 128), 128, SMEM_1P>>>(
        xh, wqh, nullptr, nullptr, qh, M_TOK, 3072, D, 3072);

    // 2) Flash attention -> ath (fp16)
    attn_flash<<<Bsz * H * G * (LG / 64), 128, ATTN_SMEM>>>(qh, ath);

    // 3) Output projection + bias -> fp32 out
    gemm_1p<<<dim3(8, M_TOK / 128), 128, SMEM_1P>>>(
        ath, woh, b_out, out, nullptr, M_TOK, 1024, D, 0);
}